// round 1
// baseline (speedup 1.0000x reference)
#include <cuda_runtime.h>
#include <math.h>

#define BB 2
#define SS 2048
#define EE 128
#define HH 16
#define DD 128
#define DHH 512
#define MM (BB*SS)     // 4096 rows
#define HD (HH*DD)     // 2048

// ---------------- scratch (static __device__, no allocation) ----------------
__device__ float g_h1[MM*EE];
__device__ float g_q [MM*HD];
__device__ float g_k [MM*HD];
__device__ float g_v [MM*HD];
__device__ float g_ao[MM*HD];
__device__ float g_x2[MM*EE];
__device__ float g_h2[MM*EE];
__device__ float g_t [MM*DHH];

// ---------------- LayerNorm: one warp per row (E=128, 4 elems/lane) ---------
__global__ void ln_kernel(const float* __restrict__ x, const float* __restrict__ g,
                          const float* __restrict__ b, float* __restrict__ out) {
    int warp = threadIdx.x >> 5, lane = threadIdx.x & 31;
    int row = blockIdx.x * 8 + warp;
    float4 v = ((const float4*)(x + (size_t)row * EE))[lane];
    float s = v.x + v.y + v.z + v.w;
    #pragma unroll
    for (int o = 16; o; o >>= 1) s += __shfl_xor_sync(0xffffffffu, s, o);
    float mu = s * (1.0f / EE);
    float d0 = v.x - mu, d1 = v.y - mu, d2 = v.z - mu, d3 = v.w - mu;
    float q = d0*d0 + d1*d1 + d2*d2 + d3*d3;
    #pragma unroll
    for (int o = 16; o; o >>= 1) q += __shfl_xor_sync(0xffffffffu, q, o);
    float inv = rsqrtf(q * (1.0f / EE) + 1e-5f);
    float4 gg = ((const float4*)g)[lane];
    float4 bb = ((const float4*)b)[lane];
    float4 r;
    r.x = d0 * inv * gg.x + bb.x;
    r.y = d1 * inv * gg.y + bb.y;
    r.z = d2 * inv * gg.z + bb.z;
    r.w = d3 * inv * gg.w + bb.w;
    ((float4*)(out + (size_t)row * EE))[lane] = r;
}

// ---------------- Generic 64x64 SGEMM with fused epilogues ------------------
// MODE 1: RoPE + qscale, store transposed to (B,H,S,D)   (Q and K)
// MODE 2: qscale only,   store transposed to (B,H,S,D)   (V)
// MODE 3: out = resid + acc                               (O-proj + residual)
// MODE 4: out = gelu(acc + bias)                          (fc1)
// MODE 5: out = resid + acc + bias                        (fc2)
// AG: gather A from attention-output layout (B,H,S,D) viewed as (B*S, H*D)
template<int MODE, bool AG>
__global__ void gemm_k(const float* __restrict__ A, const float* __restrict__ Bw,
                       const float* __restrict__ bias, const float* __restrict__ resid,
                       float* __restrict__ out, int M, int N, int K, float qscale)
{
    __shared__ float As[16][65];
    __shared__ float Bs[16][64];
    int tid = threadIdx.x;
    int tx = tid & 15, ty = tid >> 4;
    int m0 = blockIdx.y * 64, n0 = blockIdx.x * 64;
    float acc[4][4] = {};
    int arow = tid >> 2;
    int acol = (tid & 3) << 2;
    int brow = tid >> 4;
    int bcol = (tid & 15) << 2;

    for (int k0 = 0; k0 < K; k0 += 16) {
        float4 av;
        if (!AG) {
            av = *(const float4*)(A + (size_t)(m0 + arow) * K + k0 + acol);
        } else {
            int r  = m0 + arow;
            int b_ = r >> 11, s_ = r & 2047;
            int kk = k0 + acol;
            av = *(const float4*)(A + (((size_t)(b_*HH + (kk >> 7)) * SS + s_) * DD + (kk & 127)));
        }
        As[acol+0][arow] = av.x;
        As[acol+1][arow] = av.y;
        As[acol+2][arow] = av.z;
        As[acol+3][arow] = av.w;
        *(float4*)&Bs[brow][bcol] = *(const float4*)(Bw + (size_t)(k0 + brow) * N + n0 + bcol);
        __syncthreads();
        #pragma unroll
        for (int kk = 0; kk < 16; kk++) {
            float a[4], b[4];
            #pragma unroll
            for (int i = 0; i < 4; i++) a[i] = As[kk][ty*4 + i];
            #pragma unroll
            for (int j = 0; j < 4; j++) b[j] = Bs[kk][tx*4 + j];
            #pragma unroll
            for (int i = 0; i < 4; i++)
                #pragma unroll
                for (int j = 0; j < 4; j++)
                    acc[i][j] += a[i] * b[j];
        }
        __syncthreads();
    }

    int gr0 = m0 + ty * 4;
    int gc0 = n0 + tx * 4;
    if (MODE == 1 || MODE == 2) {
        #pragma unroll
        for (int i = 0; i < 4; i++) {
            int r  = gr0 + i;
            int b_ = r >> 11, s_ = r & 2047;
            #pragma unroll
            for (int j = 0; j < 4; j += 2) {
                int c = gc0 + j;
                int h = c >> 7, d = c & 127;
                float o1 = acc[i][j]   * qscale;
                float o2 = acc[i][j+1] * qscale;
                if (MODE == 1) {
                    int t2 = d >> 1;
                    // inv_freq = 10000^(-t2/64) = exp(-t2 * ln(10000)/64)
                    float ang = (float)s_ * expf((float)t2 * -0.14391157f);
                    float si, co;
                    sincosf(ang, &si, &co);
                    float r1 = o1 * co - o2 * si;
                    float r2 = o1 * si + o2 * co;
                    o1 = r1; o2 = r2;
                }
                float* op = out + (((size_t)(b_*HH + h) * SS + s_) * DD + d);
                op[0] = o1; op[1] = o2;
            }
        }
    } else {
        #pragma unroll
        for (int i = 0; i < 4; i++) {
            int r = gr0 + i;
            #pragma unroll
            for (int j = 0; j < 4; j++) {
                int c = gc0 + j;
                float v = acc[i][j];
                size_t idx = (size_t)r * N + c;
                if (MODE == 3) {
                    out[idx] = resid[idx] + v;
                } else if (MODE == 4) {
                    v += bias[c];
                    out[idx] = 0.5f * v * (1.0f + erff(v * 0.70710678f));
                } else if (MODE == 5) {
                    out[idx] = resid[idx] + v + bias[c];
                } else {
                    out[idx] = v;
                }
            }
        }
    }
}

// ---------------- Flash attention (fp32, causal), BM=BN=64, D=128 -----------
#define FA_PAD 129
#define FA_SMEM_BYTES ((3*64*FA_PAD + 64*65) * 4)

__global__ void fa_kernel(const float* __restrict__ Q, const float* __restrict__ Kg,
                          const float* __restrict__ V, float* __restrict__ O)
{
    extern __shared__ float sm[];
    float (*Qs)[FA_PAD] = (float (*)[FA_PAD])sm;
    float (*Ks)[FA_PAD] = (float (*)[FA_PAD])(sm + 64*FA_PAD);
    float (*Vs)[FA_PAD] = (float (*)[FA_PAD])(sm + 2*64*FA_PAD);
    float (*Ps)[65]     = (float (*)[65])(sm + 3*64*FA_PAD);
    int tid = threadIdx.x;
    int tx = tid & 15, ty = tid >> 4;
    int m0 = blockIdx.x * 64;
    int bh = blockIdx.y;
    const float* Qb = Q + (size_t)bh * SS * DD;
    const float* Kb = Kg + (size_t)bh * SS * DD;
    const float* Vb = V + (size_t)bh * SS * DD;

    // load Q tile (scale already folded in at projection)
    for (int f = tid; f < 64*32; f += 256) {
        int r = f >> 5, c = (f & 31) << 2;
        float4 qv = *(const float4*)(Qb + (size_t)(m0 + r) * DD + c);
        Qs[r][c] = qv.x; Qs[r][c+1] = qv.y; Qs[r][c+2] = qv.z; Qs[r][c+3] = qv.w;
    }

    float m_i[4], l_i[4], o_acc[4][8];
    #pragma unroll
    for (int i = 0; i < 4; i++) {
        m_i[i] = -1e30f; l_i[i] = 0.f;
        #pragma unroll
        for (int k2 = 0; k2 < 8; k2++) o_acc[i][k2] = 0.f;
    }

    for (int n0 = 0; n0 <= m0; n0 += 64) {
        __syncthreads();
        for (int f = tid; f < 64*32; f += 256) {
            int r = f >> 5, c = (f & 31) << 2;
            float4 kv = *(const float4*)(Kb + (size_t)(n0 + r) * DD + c);
            Ks[r][c] = kv.x; Ks[r][c+1] = kv.y; Ks[r][c+2] = kv.z; Ks[r][c+3] = kv.w;
            float4 vv = *(const float4*)(Vb + (size_t)(n0 + r) * DD + c);
            Vs[r][c] = vv.x; Vs[r][c+1] = vv.y; Vs[r][c+2] = vv.z; Vs[r][c+3] = vv.w;
        }
        __syncthreads();

        // scores: rows ty*4+i, cols tx+16*j (strided -> conflict-free K reads)
        float sacc[4][4] = {};
        #pragma unroll 8
        for (int kd = 0; kd < 128; kd++) {
            float a[4], bq[4];
            #pragma unroll
            for (int i = 0; i < 4; i++) a[i] = Qs[ty*4 + i][kd];
            #pragma unroll
            for (int j = 0; j < 4; j++) bq[j] = Ks[tx + 16*j][kd];
            #pragma unroll
            for (int i = 0; i < 4; i++)
                #pragma unroll
                for (int j = 0; j < 4; j++)
                    sacc[i][j] += a[i] * bq[j];
        }
        if (n0 == m0) {
            #pragma unroll
            for (int i = 0; i < 4; i++) {
                int gr = m0 + ty*4 + i;
                #pragma unroll
                for (int j = 0; j < 4; j++) {
                    int gc = n0 + tx + 16*j;
                    if (gc > gr) sacc[i][j] = -1e30f;
                }
            }
        }

        // online softmax; reductions across the 16 tx lanes (xor 8,4,2,1)
        #pragma unroll
        for (int i = 0; i < 4; i++) {
            float mx = fmaxf(fmaxf(sacc[i][0], sacc[i][1]), fmaxf(sacc[i][2], sacc[i][3]));
            #pragma unroll
            for (int o = 8; o; o >>= 1) mx = fmaxf(mx, __shfl_xor_sync(0xffffffffu, mx, o));
            float mnew  = fmaxf(m_i[i], mx);
            float alpha = expf(m_i[i] - mnew);
            float sum = 0.f;
            #pragma unroll
            for (int j = 0; j < 4; j++) {
                float p = expf(sacc[i][j] - mnew);
                sacc[i][j] = p;
                sum += p;
            }
            #pragma unroll
            for (int o = 8; o; o >>= 1) sum += __shfl_xor_sync(0xffffffffu, sum, o);
            l_i[i] = l_i[i] * alpha + sum;
            m_i[i] = mnew;
            #pragma unroll
            for (int k2 = 0; k2 < 8; k2++) o_acc[i][k2] *= alpha;
            #pragma unroll
            for (int j = 0; j < 4; j++) Ps[ty*4 + i][tx + 16*j] = sacc[i][j];
        }
        __syncwarp();  // P written/read within the same warp (rows keyed by ty)

        // O += P @ V : thread owns rows ty*4+i, d-cols tx+16*k2
        #pragma unroll 4
        for (int j = 0; j < 64; j++) {
            float p[4];
            #pragma unroll
            for (int i = 0; i < 4; i++) p[i] = Ps[ty*4 + i][j];
            float vv[8];
            #pragma unroll
            for (int k2 = 0; k2 < 8; k2++) vv[k2] = Vs[j][tx + 16*k2];
            #pragma unroll
            for (int i = 0; i < 4; i++)
                #pragma unroll
                for (int k2 = 0; k2 < 8; k2++)
                    o_acc[i][k2] += p[i] * vv[k2];
        }
    }

    #pragma unroll
    for (int i = 0; i < 4; i++) {
        float invl = 1.0f / l_i[i];
        int gr = m0 + ty*4 + i;
        float* Ob = O + (size_t)bh * SS * DD + (size_t)gr * DD;
        #pragma unroll
        for (int k2 = 0; k2 < 8; k2++) Ob[tx + 16*k2] = o_acc[i][k2] * invl;
    }
}

// ---------------- launch -----------------------------------------------------
extern "C" void kernel_launch(void* const* d_in, const int* in_sizes, int n_in,
                              void* d_out, int out_size) {
    const float* x        = (const float*)d_in[0];
    const float* W_q      = (const float*)d_in[1];
    const float* W_k      = (const float*)d_in[2];
    const float* W_v      = (const float*)d_in[3];
    const float* W_o      = (const float*)d_in[4];
    const float* ln_attn_g= (const float*)d_in[5];
    const float* ln_attn_b= (const float*)d_in[6];
    const float* fc1_w    = (const float*)d_in[7];
    const float* fc1_b    = (const float*)d_in[8];
    const float* fc2_w    = (const float*)d_in[9];
    const float* fc2_b    = (const float*)d_in[10];
    const float* ln_mlp_g = (const float*)d_in[11];
    const float* ln_mlp_b = (const float*)d_in[12];
    float* out = (float*)d_out;

    float *h1, *q, *k, *v, *ao, *x2, *h2, *t;
    cudaGetSymbolAddress((void**)&h1, g_h1);
    cudaGetSymbolAddress((void**)&q,  g_q);
    cudaGetSymbolAddress((void**)&k,  g_k);
    cudaGetSymbolAddress((void**)&v,  g_v);
    cudaGetSymbolAddress((void**)&ao, g_ao);
    cudaGetSymbolAddress((void**)&x2, g_x2);
    cudaGetSymbolAddress((void**)&h2, g_h2);
    cudaGetSymbolAddress((void**)&t,  g_t);

    // 1) LN
    ln_kernel<<<MM/8, 256>>>(x, ln_attn_g, ln_attn_b, h1);

    // 2) QKV projections with fused RoPE / scale / transpose
    dim3 gq(HD/64, MM/64);
    const float qscale = 0.08838834764831845f;  // 1/sqrt(128)
    gemm_k<1,false><<<gq, 256>>>(h1, W_q, nullptr, nullptr, q, MM, HD, EE, qscale);
    gemm_k<1,false><<<gq, 256>>>(h1, W_k, nullptr, nullptr, k, MM, HD, EE, 1.0f);
    gemm_k<2,false><<<gq, 256>>>(h1, W_v, nullptr, nullptr, v, MM, HD, EE, 1.0f);

    // 3) causal flash attention
    cudaFuncSetAttribute(fa_kernel, cudaFuncAttributeMaxDynamicSharedMemorySize, FA_SMEM_BYTES);
    fa_kernel<<<dim3(SS/64, BB*HH), 256, FA_SMEM_BYTES>>>(q, k, v, ao);

    // 4) O-projection + residual (A gathered from (B,H,S,D) layout)
    gemm_k<3,true><<<dim3(EE/64, MM/64), 256>>>(ao, W_o, nullptr, x, x2, MM, EE, HD, 1.0f);

    // 5) LN
    ln_kernel<<<MM/8, 256>>>(x2, ln_mlp_g, ln_mlp_b, h2);

    // 6) MLP
    gemm_k<4,false><<<dim3(DHH/64, MM/64), 256>>>(h2, fc1_w, fc1_b, nullptr, t, MM, DHH, EE, 1.0f);
    gemm_k<5,false><<<dim3(EE/64,  MM/64), 256>>>(t,  fc2_w, fc2_b, x2, out, MM, EE, DHH, 1.0f);
}

// round 4
// speedup vs baseline: 1.8033x; 1.8033x over previous
#include <cuda_runtime.h>
#include <cuda_bf16.h>
#include <math.h>
#include <stdint.h>

#define BB 2
#define SS 2048
#define EE 128
#define HH 16
#define DD 128
#define DHH 512
#define MM (BB*SS)     // 4096 rows
#define HD (HH*DD)     // 2048

// ---------------- scratch (static __device__, no allocation) ----------------
__device__ float g_h1[MM*EE];
__device__ float g_ao[MM*HD];
__device__ float g_x2[MM*EE];
__device__ float g_h2[MM*EE];
__device__ float g_t [MM*DHH];
__device__ __nv_bfloat16 g_qhi[MM*HD];
__device__ __nv_bfloat16 g_qlo[MM*HD];
__device__ __nv_bfloat16 g_khi[MM*HD];
__device__ __nv_bfloat16 g_klo[MM*HD];
__device__ __nv_bfloat16 g_vhi[MM*HD];
__device__ __nv_bfloat16 g_vlo[MM*HD];

// ======================= warp MMA helpers (baseline PTX) =====================
__device__ __forceinline__ uint32_t smem_u32(const void* p) {
    uint32_t a;
    asm("{ .reg .u64 t; cvta.to.shared.u64 t, %1; cvt.u32.u64 %0, t; }"
        : "=r"(a) : "l"(p));
    return a;
}

__device__ __forceinline__ void mma16816(float* c, const uint32_t* a, const uint32_t* b) {
    asm volatile(
        "mma.sync.aligned.m16n8k16.row.col.f32.bf16.bf16.f32 "
        "{%0,%1,%2,%3}, {%4,%5,%6,%7}, {%8,%9}, {%0,%1,%2,%3};"
        : "+f"(c[0]), "+f"(c[1]), "+f"(c[2]), "+f"(c[3])
        : "r"(a[0]), "r"(a[1]), "r"(a[2]), "r"(a[3]), "r"(b[0]), "r"(b[1]));
}
__device__ __forceinline__ void ldsm_x4(uint32_t* r, uint32_t addr) {
    asm volatile("ldmatrix.sync.aligned.m8n8.x4.shared.b16 {%0,%1,%2,%3}, [%4];"
        : "=r"(r[0]), "=r"(r[1]), "=r"(r[2]), "=r"(r[3]) : "r"(addr));
}
__device__ __forceinline__ void ldsm_x4_t(uint32_t* r, uint32_t addr) {
    asm volatile("ldmatrix.sync.aligned.m8n8.x4.trans.shared.b16 {%0,%1,%2,%3}, [%4];"
        : "=r"(r[0]), "=r"(r[1]), "=r"(r[2]), "=r"(r[3]) : "r"(addr));
}
__device__ __forceinline__ uint32_t pack_bf2(float a, float b) {
    __nv_bfloat162 h = __halves2bfloat162(__float2bfloat16(a), __float2bfloat16(b));
    return *(uint32_t*)&h;
}

// ---------------- LayerNorm: one warp per row (E=128, 4 elems/lane) ---------
__global__ void ln_kernel(const float* __restrict__ x, const float* __restrict__ g,
                          const float* __restrict__ b, float* __restrict__ out) {
    int warp = threadIdx.x >> 5, lane = threadIdx.x & 31;
    int row = blockIdx.x * 8 + warp;
    float4 v = ((const float4*)(x + (size_t)row * EE))[lane];
    float s = v.x + v.y + v.z + v.w;
    #pragma unroll
    for (int o = 16; o; o >>= 1) s += __shfl_xor_sync(0xffffffffu, s, o);
    float mu = s * (1.0f / EE);
    float d0 = v.x - mu, d1 = v.y - mu, d2 = v.z - mu, d3 = v.w - mu;
    float q = d0*d0 + d1*d1 + d2*d2 + d3*d3;
    #pragma unroll
    for (int o = 16; o; o >>= 1) q += __shfl_xor_sync(0xffffffffu, q, o);
    float inv = rsqrtf(q * (1.0f / EE) + 1e-5f);
    float4 gg = ((const float4*)g)[lane];
    float4 bb = ((const float4*)b)[lane];
    float4 r;
    r.x = d0 * inv * gg.x + bb.x;
    r.y = d1 * inv * gg.y + bb.y;
    r.z = d2 * inv * gg.z + bb.z;
    r.w = d3 * inv * gg.w + bb.w;
    ((float4*)(out + (size_t)row * EE))[lane] = r;
}

// ---------------- Generic 64x64 SGEMM with fused epilogues ------------------
// MODE 1: RoPE + qscale, bf16 hi/lo split stored to (B,H,S,D)    (Q and K)
// MODE 2: qscale only,   bf16 hi/lo split stored to (B,H,S,D)    (V)
// MODE 3: out = resid + acc                                      (O-proj + residual)
// MODE 4: out = gelu(acc + bias)                                 (fc1)
// MODE 5: out = resid + acc + bias                               (fc2)
template<int MODE, bool AG>
__global__ void gemm_k(const float* __restrict__ A, const float* __restrict__ Bw,
                       const float* __restrict__ bias, const float* __restrict__ resid,
                       float* __restrict__ out,
                       __nv_bfloat16* __restrict__ ohi, __nv_bfloat16* __restrict__ olo,
                       int M, int N, int K, float qscale)
{
    __shared__ float As[16][65];
    __shared__ float Bs[16][64];
    int tid = threadIdx.x;
    int tx = tid & 15, ty = tid >> 4;
    int m0 = blockIdx.y * 64, n0 = blockIdx.x * 64;
    float acc[4][4] = {};
    int arow = tid >> 2;
    int acol = (tid & 3) << 2;
    int brow = tid >> 4;
    int bcol = (tid & 15) << 2;

    for (int k0 = 0; k0 < K; k0 += 16) {
        float4 av;
        if (!AG) {
            av = *(const float4*)(A + (size_t)(m0 + arow) * K + k0 + acol);
        } else {
            int r  = m0 + arow;
            int b_ = r >> 11, s_ = r & 2047;
            int kk = k0 + acol;
            av = *(const float4*)(A + (((size_t)(b_*HH + (kk >> 7)) * SS + s_) * DD + (kk & 127)));
        }
        As[acol+0][arow] = av.x;
        As[acol+1][arow] = av.y;
        As[acol+2][arow] = av.z;
        As[acol+3][arow] = av.w;
        *(float4*)&Bs[brow][bcol] = *(const float4*)(Bw + (size_t)(k0 + brow) * N + n0 + bcol);
        __syncthreads();
        #pragma unroll
        for (int kk = 0; kk < 16; kk++) {
            float a[4], b[4];
            #pragma unroll
            for (int i = 0; i < 4; i++) a[i] = As[kk][ty*4 + i];
            #pragma unroll
            for (int j = 0; j < 4; j++) b[j] = Bs[kk][tx*4 + j];
            #pragma unroll
            for (int i = 0; i < 4; i++)
                #pragma unroll
                for (int j = 0; j < 4; j++)
                    acc[i][j] += a[i] * b[j];
        }
        __syncthreads();
    }

    int gr0 = m0 + ty * 4;
    int gc0 = n0 + tx * 4;
    if (MODE == 1 || MODE == 2) {
        #pragma unroll
        for (int i = 0; i < 4; i++) {
            int r  = gr0 + i;
            int b_ = r >> 11, s_ = r & 2047;
            #pragma unroll
            for (int j = 0; j < 4; j += 2) {
                int c = gc0 + j;
                int h = c >> 7, d = c & 127;
                float o1 = acc[i][j]   * qscale;
                float o2 = acc[i][j+1] * qscale;
                if (MODE == 1) {
                    int t2 = d >> 1;
                    float ang = (float)s_ * expf((float)t2 * -0.14391157f);
                    float si, co;
                    sincosf(ang, &si, &co);
                    float r1 = o1 * co - o2 * si;
                    float r2 = o1 * si + o2 * co;
                    o1 = r1; o2 = r2;
                }
                size_t oi = (((size_t)(b_*HH + h) * SS + s_) * DD + d);
                __nv_bfloat16 hb1 = __float2bfloat16(o1);
                __nv_bfloat16 hb2 = __float2bfloat16(o2);
                ohi[oi]   = hb1;
                ohi[oi+1] = hb2;
                olo[oi]   = __float2bfloat16(o1 - __bfloat162float(hb1));
                olo[oi+1] = __float2bfloat16(o2 - __bfloat162float(hb2));
            }
        }
    } else {
        #pragma unroll
        for (int i = 0; i < 4; i++) {
            int r = gr0 + i;
            #pragma unroll
            for (int j = 0; j < 4; j++) {
                int c = gc0 + j;
                float v = acc[i][j];
                size_t idx = (size_t)r * N + c;
                if (MODE == 3) {
                    out[idx] = resid[idx] + v;
                } else if (MODE == 4) {
                    v += bias[c];
                    out[idx] = 0.5f * v * (1.0f + erff(v * 0.70710678f));
                } else if (MODE == 5) {
                    out[idx] = resid[idx] + v + bias[c];
                } else {
                    out[idx] = v;
                }
            }
        }
    }
}

// ============== mma.sync flash attention (bf16x3, FA2 single pass) ==========
// CTA: 128 query rows of one (b,h), 8 warps (16 rows each), K-tiles of 64.
// Smem: Khi[16K] Klo[16K] Vhi[16K] Vlo[16K], rows = 256B, XOR-swizzled.
#define KHI_OFF 0u
#define KLO_OFF 16384u
#define VHI_OFF 32768u
#define VLO_OFF 49152u
#define FA_SMEM 65536

__device__ __forceinline__ uint32_t fa_off(int r, int cbyte) {
    return (uint32_t)(r * 256 + (cbyte ^ ((r & 7) << 4)));
}

__global__ __launch_bounds__(256, 1)
void fa_mma(const __nv_bfloat16* __restrict__ qhi, const __nv_bfloat16* __restrict__ qlo,
            const __nv_bfloat16* __restrict__ khi, const __nv_bfloat16* __restrict__ klo,
            const __nv_bfloat16* __restrict__ vhi, const __nv_bfloat16* __restrict__ vlo,
            float* __restrict__ O)
{
    extern __shared__ char sm[];
    uint32_t sb = smem_u32(sm);
    const int tid = threadIdx.x;
    const int w = tid >> 5, ln = tid & 31;
    const int tig = ln & 3, gid = ln >> 2;
    const int m0 = (gridDim.x - 1 - blockIdx.x) * 128;   // big tiles first
    const int bh = blockIdx.y;
    const size_t base = (size_t)bh * SS * DD;

    // ---- stage Q tile (128 x 128 bf16, hi then lo) through smem ----
    for (int f = tid; f < 2048; f += 256) {
        int r = f >> 4, c16 = f & 15;
        size_t g = base + (size_t)(m0 + r) * DD + c16 * 8;
        uint32_t so = fa_off(r, c16 * 16);
        *(uint4*)(sm + so)          = *(const uint4*)(qhi + g);
        *(uint4*)(sm + 32768 + so)  = *(const uint4*)(qlo + g);
    }
    __syncthreads();
    uint32_t Qh[8][4], Ql[8][4];
    {
        int row = 16 * w + ((ln >> 3) & 1) * 8 + (ln & 7);
        int kb0 = (ln >> 4) * 16;
        #pragma unroll
        for (int kk = 0; kk < 8; kk++) {
            uint32_t off = fa_off(row, kk * 32 + kb0);
            ldsm_x4(Qh[kk], sb + off);
            ldsm_x4(Ql[kk], sb + 32768 + off);
        }
    }
    __syncthreads();

    float Oa[16][4];
    #pragma unroll
    for (int j = 0; j < 16; j++)
        #pragma unroll
        for (int e = 0; e < 4; e++) Oa[j][e] = 0.f;
    float m0r = -1e30f, m1r = -1e30f, l0r = 0.f, l1r = 0.f;

    const int grow0 = m0 + 16 * w + gid;
    const int grow1 = grow0 + 8;
    const int nk = m0 / 64 + 2;

    for (int t = 0; t < nk; t++) {
        int n0 = t * 64;
        __syncthreads();
        for (int f = tid; f < 1024; f += 256) {
            int r = f >> 4, c16 = f & 15;
            size_t g = base + (size_t)(n0 + r) * DD + c16 * 8;
            uint32_t so = fa_off(r, c16 * 16);
            *(uint4*)(sm + KHI_OFF + so) = *(const uint4*)(khi + g);
            *(uint4*)(sm + KLO_OFF + so) = *(const uint4*)(klo + g);
            *(uint4*)(sm + VHI_OFF + so) = *(const uint4*)(vhi + g);
            *(uint4*)(sm + VLO_OFF + so) = *(const uint4*)(vlo + g);
        }
        __syncthreads();

        // ---- S = Q K^T (3-term) ----
        float S[8][4];
        #pragma unroll
        for (int j = 0; j < 8; j++)
            #pragma unroll
            for (int e = 0; e < 4; e++) S[j][e] = 0.f;
        {
            int brow = ((ln >> 4) << 3) + (ln & 7);
            int bkb  = ((ln >> 3) & 1) << 4;
            #pragma unroll
            for (int jp = 0; jp < 4; jp++) {
                #pragma unroll
                for (int kk = 0; kk < 8; kk++) {
                    int r_ = 16 * jp + brow;
                    uint32_t off = fa_off(r_, kk * 32 + bkb);
                    uint32_t Bh[4], Bl[4];
                    ldsm_x4(Bh, sb + KHI_OFF + off);
                    mma16816(S[2*jp],   Qh[kk], Bh);
                    mma16816(S[2*jp+1], Qh[kk], Bh + 2);
                    mma16816(S[2*jp],   Ql[kk], Bh);
                    mma16816(S[2*jp+1], Ql[kk], Bh + 2);
                    ldsm_x4(Bl, sb + KLO_OFF + off);
                    mma16816(S[2*jp],   Qh[kk], Bl);
                    mma16816(S[2*jp+1], Qh[kk], Bl + 2);
                }
            }
        }

        // ---- causal mask (only near-diagonal tiles) ----
        if (n0 + 63 > m0 + 16 * w) {
            #pragma unroll
            for (int j = 0; j < 8; j++) {
                int c = n0 + 8 * j + 2 * tig;
                if (c     > grow0) S[j][0] = -1e30f;
                if (c + 1 > grow0) S[j][1] = -1e30f;
                if (c     > grow1) S[j][2] = -1e30f;
                if (c + 1 > grow1) S[j][3] = -1e30f;
            }
        }

        // ---- online softmax (rows r0=gid, r1=gid+8 per thread; quad reduce) ----
        float mx0 = -1e30f, mx1 = -1e30f;
        #pragma unroll
        for (int j = 0; j < 8; j++) {
            mx0 = fmaxf(mx0, fmaxf(S[j][0], S[j][1]));
            mx1 = fmaxf(mx1, fmaxf(S[j][2], S[j][3]));
        }
        mx0 = fmaxf(mx0, __shfl_xor_sync(0xffffffffu, mx0, 1));
        mx0 = fmaxf(mx0, __shfl_xor_sync(0xffffffffu, mx0, 2));
        mx1 = fmaxf(mx1, __shfl_xor_sync(0xffffffffu, mx1, 1));
        mx1 = fmaxf(mx1, __shfl_xor_sync(0xffffffffu, mx1, 2));
        float mn0 = fmaxf(m0r, mx0), mn1 = fmaxf(m1r, mx1);
        float a0 = __expf(m0r - mn0), a1 = __expf(m1r - mn1);
        m0r = mn0; m1r = mn1;
        l0r *= a0; l1r *= a1;

        uint32_t Phi[4][4], Plo[4][4];
        float ls0 = 0.f, ls1 = 0.f;
        #pragma unroll
        for (int j = 0; j < 8; j++) {
            float p0 = __expf(S[j][0] - mn0);
            float p1 = __expf(S[j][1] - mn0);
            float p2 = __expf(S[j][2] - mn1);
            float p3 = __expf(S[j][3] - mn1);
            ls0 += p0 + p1; ls1 += p2 + p3;
            __nv_bfloat16 h0 = __float2bfloat16(p0);
            __nv_bfloat16 h1 = __float2bfloat16(p1);
            __nv_bfloat16 h2 = __float2bfloat16(p2);
            __nv_bfloat16 h3 = __float2bfloat16(p3);
            int kk = j >> 1, q = (j & 1) * 2;
            __nv_bfloat162 hh01 = __halves2bfloat162(h0, h1);
            __nv_bfloat162 hh23 = __halves2bfloat162(h2, h3);
            Phi[kk][q]     = *(uint32_t*)&hh01;
            Phi[kk][q + 1] = *(uint32_t*)&hh23;
            Plo[kk][q]     = pack_bf2(p0 - __bfloat162float(h0), p1 - __bfloat162float(h1));
            Plo[kk][q + 1] = pack_bf2(p2 - __bfloat162float(h2), p3 - __bfloat162float(h3));
        }
        l0r += ls0; l1r += ls1;

        #pragma unroll
        for (int j = 0; j < 16; j++) {
            Oa[j][0] *= a0; Oa[j][1] *= a0;
            Oa[j][2] *= a1; Oa[j][3] *= a1;
        }

        // ---- O += P V (3-term) ----
        {
            int vrow = ((ln >> 3) & 1) * 8 + (ln & 7);
            int vcb  = (ln >> 4) << 4;
            #pragma unroll
            for (int jp = 0; jp < 8; jp++) {
                #pragma unroll
                for (int kk = 0; kk < 4; kk++) {
                    int r_ = 16 * kk + vrow;
                    uint32_t off = fa_off(r_, 32 * jp + vcb);
                    uint32_t Bh[4], Bl[4];
                    ldsm_x4_t(Bh, sb + VHI_OFF + off);
                    mma16816(Oa[2*jp],   Phi[kk], Bh);
                    mma16816(Oa[2*jp+1], Phi[kk], Bh + 2);
                    mma16816(Oa[2*jp],   Plo[kk], Bh);
                    mma16816(Oa[2*jp+1], Plo[kk], Bh + 2);
                    ldsm_x4_t(Bl, sb + VLO_OFF + off);
                    mma16816(Oa[2*jp],   Phi[kk], Bl);
                    mma16816(Oa[2*jp+1], Phi[kk], Bl + 2);
                }
            }
        }
    }

    // ---- finalize: reduce l across quad, normalize, store ----
    l0r += __shfl_xor_sync(0xffffffffu, l0r, 1);
    l0r += __shfl_xor_sync(0xffffffffu, l0r, 2);
    l1r += __shfl_xor_sync(0xffffffffu, l1r, 1);
    l1r += __shfl_xor_sync(0xffffffffu, l1r, 2);
    float inv0 = 1.0f / l0r, inv1 = 1.0f / l1r;
    float* op0 = O + base + (size_t)grow0 * DD;
    float* op1 = O + base + (size_t)grow1 * DD;
    #pragma unroll
    for (int j = 0; j < 16; j++) {
        int col = 8 * j + 2 * tig;
        float2 v0 = make_float2(Oa[j][0] * inv0, Oa[j][1] * inv0);
        float2 v1 = make_float2(Oa[j][2] * inv1, Oa[j][3] * inv1);
        *(float2*)(op0 + col) = v0;
        *(float2*)(op1 + col) = v1;
    }
}

// ---------------- launch -----------------------------------------------------
extern "C" void kernel_launch(void* const* d_in, const int* in_sizes, int n_in,
                              void* d_out, int out_size) {
    const float* x        = (const float*)d_in[0];
    const float* W_q      = (const float*)d_in[1];
    const float* W_k      = (const float*)d_in[2];
    const float* W_v      = (const float*)d_in[3];
    const float* W_o      = (const float*)d_in[4];
    const float* ln_attn_g= (const float*)d_in[5];
    const float* ln_attn_b= (const float*)d_in[6];
    const float* fc1_w    = (const float*)d_in[7];
    const float* fc1_b    = (const float*)d_in[8];
    const float* fc2_w    = (const float*)d_in[9];
    const float* fc2_b    = (const float*)d_in[10];
    const float* ln_mlp_g = (const float*)d_in[11];
    const float* ln_mlp_b = (const float*)d_in[12];
    float* out = (float*)d_out;

    float *h1, *ao, *x2, *h2, *t;
    __nv_bfloat16 *qhi, *qlo, *khi, *klo, *vhi, *vlo;
    cudaGetSymbolAddress((void**)&h1, g_h1);
    cudaGetSymbolAddress((void**)&ao, g_ao);
    cudaGetSymbolAddress((void**)&x2, g_x2);
    cudaGetSymbolAddress((void**)&h2, g_h2);
    cudaGetSymbolAddress((void**)&t,  g_t);
    cudaGetSymbolAddress((void**)&qhi, g_qhi);
    cudaGetSymbolAddress((void**)&qlo, g_qlo);
    cudaGetSymbolAddress((void**)&khi, g_khi);
    cudaGetSymbolAddress((void**)&klo, g_klo);
    cudaGetSymbolAddress((void**)&vhi, g_vhi);
    cudaGetSymbolAddress((void**)&vlo, g_vlo);

    // 1) LN
    ln_kernel<<<MM/8, 256>>>(x, ln_attn_g, ln_attn_b, h1);

    // 2) QKV projections with fused RoPE / scale / bf16-split / transpose
    dim3 gq(HD/64, MM/64);
    const float qscale = 0.08838834764831845f;  // 1/sqrt(128)
    gemm_k<1,false><<<gq, 256>>>(h1, W_q, nullptr, nullptr, nullptr, qhi, qlo, MM, HD, EE, qscale);
    gemm_k<1,false><<<gq, 256>>>(h1, W_k, nullptr, nullptr, nullptr, khi, klo, MM, HD, EE, 1.0f);
    gemm_k<2,false><<<gq, 256>>>(h1, W_v, nullptr, nullptr, nullptr, vhi, vlo, MM, HD, EE, 1.0f);

    // 3) causal flash attention on mma.sync tensor cores (bf16x3)
    cudaFuncSetAttribute(fa_mma, cudaFuncAttributeMaxDynamicSharedMemorySize, FA_SMEM);
    fa_mma<<<dim3(SS/128, BB*HH), 256, FA_SMEM>>>(qhi, qlo, khi, klo, vhi, vlo, ao);

    // 4) O-projection + residual (A gathered from (B,H,S,D) layout)
    gemm_k<3,true><<<dim3(EE/64, MM/64), 256>>>(ao, W_o, nullptr, x, x2, nullptr, nullptr, MM, EE, HD, 1.0f);

    // 5) LN
    ln_kernel<<<MM/8, 256>>>(x2, ln_mlp_g, ln_mlp_b, h2);

    // 6) MLP
    gemm_k<4,false><<<dim3(DHH/64, MM/64), 256>>>(h2, fc1_w, fc1_b, nullptr, t, nullptr, nullptr, MM, DHH, EE, 1.0f);
    gemm_k<5,false><<<dim3(EE/64,  MM/64), 256>>>(t,  fc2_w, fc2_b, x2, out, nullptr, nullptr, MM, EE, DHH, 1.0f);
}

// round 5
// speedup vs baseline: 2.0183x; 1.1192x over previous
#include <cuda_runtime.h>
#include <cuda_bf16.h>
#include <math.h>
#include <stdint.h>

#define BB 2
#define SS 2048
#define EE 128
#define HH 16
#define DD 128
#define DHH 512
#define MM (BB*SS)     // 4096 rows
#define HD (HH*DD)     // 2048

// ---------------- scratch (static __device__, no allocation) ----------------
__device__ float g_x2[MM*EE];
__device__ __nv_bfloat16 g_h1h[MM*EE],  g_h1l[MM*EE];
__device__ __nv_bfloat16 g_h2h[MM*EE],  g_h2l[MM*EE];
__device__ __nv_bfloat16 g_th [MM*DHH], g_tl [MM*DHH];
__device__ __nv_bfloat16 g_aoh[MM*HD],  g_aol[MM*HD];
__device__ __nv_bfloat16 g_qhi[MM*HD],  g_qlo[MM*HD];
__device__ __nv_bfloat16 g_khi[MM*HD],  g_klo[MM*HD];
__device__ __nv_bfloat16 g_vhi[MM*HD],  g_vlo[MM*HD];
__device__ __nv_bfloat16 g_wqh[EE*HD],  g_wql[EE*HD];
__device__ __nv_bfloat16 g_wkh[EE*HD],  g_wkl[EE*HD];
__device__ __nv_bfloat16 g_wvh[EE*HD],  g_wvl[EE*HD];
__device__ __nv_bfloat16 g_woh[HD*EE],  g_wol[HD*EE];
__device__ __nv_bfloat16 g_f1h[EE*DHH], g_f1l[EE*DHH];
__device__ __nv_bfloat16 g_f2h[DHH*EE], g_f2l[DHH*EE];

// ======================= warp MMA helpers (baseline PTX) =====================
__device__ __forceinline__ uint32_t smem_u32(const void* p) {
    uint32_t a;
    asm("{ .reg .u64 t; cvta.to.shared.u64 t, %1; cvt.u32.u64 %0, t; }"
        : "=r"(a) : "l"(p));
    return a;
}
__device__ __forceinline__ void mma16816(float* c, const uint32_t* a, const uint32_t* b) {
    asm volatile(
        "mma.sync.aligned.m16n8k16.row.col.f32.bf16.bf16.f32 "
        "{%0,%1,%2,%3}, {%4,%5,%6,%7}, {%8,%9}, {%0,%1,%2,%3};"
        : "+f"(c[0]), "+f"(c[1]), "+f"(c[2]), "+f"(c[3])
        : "r"(a[0]), "r"(a[1]), "r"(a[2]), "r"(a[3]), "r"(b[0]), "r"(b[1]));
}
__device__ __forceinline__ void ldsm_x4(uint32_t* r, uint32_t addr) {
    asm volatile("ldmatrix.sync.aligned.m8n8.x4.shared.b16 {%0,%1,%2,%3}, [%4];"
        : "=r"(r[0]), "=r"(r[1]), "=r"(r[2]), "=r"(r[3]) : "r"(addr));
}
__device__ __forceinline__ void ldsm_x4_t(uint32_t* r, uint32_t addr) {
    asm volatile("ldmatrix.sync.aligned.m8n8.x4.trans.shared.b16 {%0,%1,%2,%3}, [%4];"
        : "=r"(r[0]), "=r"(r[1]), "=r"(r[2]), "=r"(r[3]) : "r"(addr));
}
__device__ __forceinline__ uint32_t pack_bf2(float a, float b) {
    __nv_bfloat162 h = __halves2bfloat162(__float2bfloat16(a), __float2bfloat16(b));
    return *(uint32_t*)&h;
}
// 256B-row swizzle (B tiles, FA tiles); 128B-row swizzle (A tiles)
__device__ __forceinline__ uint32_t boff(int r, int cbyte) {
    return (uint32_t)(r * 256 + (cbyte ^ ((r & 7) << 4)));
}
__device__ __forceinline__ uint32_t aoff(int r, int cbyte) {
    return (uint32_t)(r * 128 + (cbyte ^ ((r & 7) << 4)));
}

// ---------------- fp32 -> bf16 hi/lo split ----------------------------------
__global__ void split_k(const float* __restrict__ w, __nv_bfloat16* __restrict__ hi,
                        __nv_bfloat16* __restrict__ lo, int n) {
    int i = (blockIdx.x * 256 + threadIdx.x) * 4;
    if (i >= n) return;
    float4 v = *(const float4*)(w + i);
    __nv_bfloat16 h0 = __float2bfloat16(v.x), h1 = __float2bfloat16(v.y);
    __nv_bfloat16 h2 = __float2bfloat16(v.z), h3 = __float2bfloat16(v.w);
    __nv_bfloat162 hh01 = __halves2bfloat162(h0, h1), hh23 = __halves2bfloat162(h2, h3);
    *(uint2*)(hi + i) = make_uint2(*(uint32_t*)&hh01, *(uint32_t*)&hh23);
    uint32_t l01 = pack_bf2(v.x - __bfloat162float(h0), v.y - __bfloat162float(h1));
    uint32_t l23 = pack_bf2(v.z - __bfloat162float(h2), v.w - __bfloat162float(h3));
    *(uint2*)(lo + i) = make_uint2(l01, l23);
}

// ---------------- LayerNorm: one warp per row, bf16 hi/lo out ---------------
__global__ void ln_kernel(const float* __restrict__ x, const float* __restrict__ g,
                          const float* __restrict__ b,
                          __nv_bfloat16* __restrict__ ohi, __nv_bfloat16* __restrict__ olo) {
    int warp = threadIdx.x >> 5, lane = threadIdx.x & 31;
    int row = blockIdx.x * 8 + warp;
    float4 v = ((const float4*)(x + (size_t)row * EE))[lane];
    float s = v.x + v.y + v.z + v.w;
    #pragma unroll
    for (int o = 16; o; o >>= 1) s += __shfl_xor_sync(0xffffffffu, s, o);
    float mu = s * (1.0f / EE);
    float d0 = v.x - mu, d1 = v.y - mu, d2 = v.z - mu, d3 = v.w - mu;
    float q = d0*d0 + d1*d1 + d2*d2 + d3*d3;
    #pragma unroll
    for (int o = 16; o; o >>= 1) q += __shfl_xor_sync(0xffffffffu, q, o);
    float inv = rsqrtf(q * (1.0f / EE) + 1e-5f);
    float4 gg = ((const float4*)g)[lane];
    float4 bb = ((const float4*)b)[lane];
    float r0 = d0 * inv * gg.x + bb.x;
    float r1 = d1 * inv * gg.y + bb.y;
    float r2 = d2 * inv * gg.z + bb.z;
    float r3 = d3 * inv * gg.w + bb.w;
    __nv_bfloat16 h0 = __float2bfloat16(r0), h1 = __float2bfloat16(r1);
    __nv_bfloat16 h2 = __float2bfloat16(r2), h3 = __float2bfloat16(r3);
    __nv_bfloat162 hh01 = __halves2bfloat162(h0, h1), hh23 = __halves2bfloat162(h2, h3);
    size_t base = (size_t)row * EE + lane * 4;
    *(uint2*)(ohi + base) = make_uint2(*(uint32_t*)&hh01, *(uint32_t*)&hh23);
    uint32_t l01 = pack_bf2(r0 - __bfloat162float(h0), r1 - __bfloat162float(h1));
    uint32_t l23 = pack_bf2(r2 - __bfloat162float(h2), r3 - __bfloat162float(h3));
    *(uint2*)(olo + base) = make_uint2(l01, l23);
}

// =============== bf16x3 tensor-core GEMM with fused epilogues ================
// C = A(hi,lo)[MxK] * B(hi,lo)[KxN], fp32 accum via 3-term mma.sync.
// MODE 1: RoPE + qscale -> bf16 hi/lo at (B,H,S,D)     (Q / K)
// MODE 2: plain        -> bf16 hi/lo at (B,H,S,D)      (V)
// MODE 3: out = resid + acc (fp32)                     (O-proj)
// MODE 4: gelu(acc + bias) -> bf16 hi/lo               (fc1)
// MODE 5: out = resid + acc + bias (fp32)              (fc2)
// AG: gather A from (B,H,S,D) viewed as (B*S, H*D)
// HALFM: CTA tile 64x128 (warps 0-3 cols 0-63, warps 4-7 cols 64-127)
#define MM3_AHI 0u
#define MM3_ALO 16384u
#define MM3_BHI 32768u
#define MM3_BLO 49152u
#define MM3_SMEM 65536

template<int MODE, bool AG, bool HALFM>
__global__ __launch_bounds__(256)
void mm3(const __nv_bfloat16* __restrict__ Ahi, const __nv_bfloat16* __restrict__ Alo,
         const __nv_bfloat16* __restrict__ Bhi, const __nv_bfloat16* __restrict__ Blo,
         const float* __restrict__ bias, const float* __restrict__ resid,
         float* __restrict__ out,
         __nv_bfloat16* __restrict__ ohi, __nv_bfloat16* __restrict__ olo,
         int M, int N, int K, float qscale)
{
    extern __shared__ char sm[];
    uint32_t sb = smem_u32(sm);
    constexpr int MT = HALFM ? 64 : 128;
    constexpr int NJ = HALFM ? 8 : 16;
    const int tid = threadIdx.x;
    const int w = tid >> 5, ln = tid & 31;
    const int tig = ln & 3, gid = ln >> 2;
    const int wr = HALFM ? (w & 3) : w;        // warp row-group
    const int wc = HALFM ? (w >> 2) * 64 : 0;  // warp col offset
    const int m0 = blockIdx.y * MT, n0 = blockIdx.x * 128;

    float C[NJ][4];
    #pragma unroll
    for (int j = 0; j < NJ; j++)
        #pragma unroll
        for (int e = 0; e < 4; e++) C[j][e] = 0.f;

    const int arow = 16 * wr + ((ln >> 3) & 1) * 8 + (ln & 7);
    const int akb  = (ln >> 4) * 16;
    const int brow = ((ln >> 3) & 1) * 8 + (ln & 7);
    const int bcb  = (ln >> 4) << 4;

    for (int k0 = 0; k0 < K; k0 += 64) {
        // ---- stage A tile [MT x 64] hi/lo ----
        for (int f = tid; f < MT * 8; f += 256) {
            int r = f >> 3, seg = f & 7;
            size_t g;
            if (!AG) {
                g = (size_t)(m0 + r) * K + k0 + seg * 8;
            } else {
                int rr = m0 + r;
                int b_ = rr >> 11, s_ = rr & 2047;
                int kk = k0 + seg * 8;
                g = ((size_t)(b_ * HH + (kk >> 7)) * SS + s_) * DD + (kk & 127);
            }
            uint32_t so = aoff(r, seg * 16);
            *(uint4*)(sm + MM3_AHI + so) = *(const uint4*)(Ahi + g);
            *(uint4*)(sm + MM3_ALO + so) = *(const uint4*)(Alo + g);
        }
        // ---- stage B tile [64 x 128] hi/lo ----
        for (int f = tid; f < 1024; f += 256) {
            int r = f >> 4, seg = f & 15;
            size_t g = (size_t)(k0 + r) * N + n0 + seg * 8;
            uint32_t so = boff(r, seg * 16);
            *(uint4*)(sm + MM3_BHI + so) = *(const uint4*)(Bhi + g);
            *(uint4*)(sm + MM3_BLO + so) = *(const uint4*)(Blo + g);
        }
        __syncthreads();

        uint32_t Ah[4][4], Al[4][4];
        #pragma unroll
        for (int kk = 0; kk < 4; kk++) {
            uint32_t off = aoff(arow, kk * 32 + akb);
            ldsm_x4(Ah[kk], sb + MM3_AHI + off);
            ldsm_x4(Al[kk], sb + MM3_ALO + off);
        }
        #pragma unroll
        for (int jp = 0; jp < NJ / 2; jp++) {
            int ncb = (wc + 16 * jp) * 2;
            #pragma unroll
            for (int kk = 0; kk < 4; kk++) {
                uint32_t off = boff(16 * kk + brow, ncb + bcb);
                uint32_t Bh[4], Bl[4];
                ldsm_x4_t(Bh, sb + MM3_BHI + off);
                mma16816(C[2*jp],   Ah[kk], Bh);
                mma16816(C[2*jp+1], Ah[kk], Bh + 2);
                mma16816(C[2*jp],   Al[kk], Bh);
                mma16816(C[2*jp+1], Al[kk], Bh + 2);
                ldsm_x4_t(Bl, sb + MM3_BLO + off);
                mma16816(C[2*jp],   Ah[kk], Bl);
                mma16816(C[2*jp+1], Ah[kk], Bl + 2);
            }
        }
        __syncthreads();
    }

    // ---- epilogue ----
    const int r0 = m0 + 16 * wr + gid;
    const int r1 = r0 + 8;
    if (MODE == 1 || MODE == 2) {
        int b_ = r0 >> 11, s0 = r0 & 2047, s1 = r1 & 2047;
        #pragma unroll
        for (int j = 0; j < NJ; j++) {
            int colg = n0 + wc + 8 * j + 2 * tig;      // even
            int h = colg >> 7, d = colg & 127;
            float o00 = C[j][0] * qscale, o01 = C[j][1] * qscale;
            float o10 = C[j][2] * qscale, o11 = C[j][3] * qscale;
            if (MODE == 1) {
                int t2 = d >> 1;
                float f = expf((float)t2 * -0.14391157f);
                float si0, co0, si1, co1;
                sincosf((float)s0 * f, &si0, &co0);
                sincosf((float)s1 * f, &si1, &co1);
                float a = o00 * co0 - o01 * si0, b2 = o00 * si0 + o01 * co0;
                o00 = a; o01 = b2;
                a = o10 * co1 - o11 * si1; b2 = o10 * si1 + o11 * co1;
                o10 = a; o11 = b2;
            }
            size_t oi0 = (((size_t)(b_ * HH + h) * SS + s0) * DD + d);
            size_t oi1 = (((size_t)(b_ * HH + h) * SS + s1) * DD + d);
            __nv_bfloat16 h00 = __float2bfloat16(o00), h01 = __float2bfloat16(o01);
            __nv_bfloat16 h10 = __float2bfloat16(o10), h11 = __float2bfloat16(o11);
            __nv_bfloat162 p0 = __halves2bfloat162(h00, h01);
            __nv_bfloat162 p1 = __halves2bfloat162(h10, h11);
            *(uint32_t*)(ohi + oi0) = *(uint32_t*)&p0;
            *(uint32_t*)(ohi + oi1) = *(uint32_t*)&p1;
            *(uint32_t*)(olo + oi0) = pack_bf2(o00 - __bfloat162float(h00), o01 - __bfloat162float(h01));
            *(uint32_t*)(olo + oi1) = pack_bf2(o10 - __bfloat162float(h10), o11 - __bfloat162float(h11));
        }
    } else {
        #pragma unroll
        for (int j = 0; j < NJ; j++) {
            int colg = n0 + wc + 8 * j + 2 * tig;
            size_t i0 = (size_t)r0 * N + colg;
            size_t i1 = (size_t)r1 * N + colg;
            float v00 = C[j][0], v01 = C[j][1], v10 = C[j][2], v11 = C[j][3];
            if (MODE == 3) {
                *(float2*)(out + i0) = make_float2(resid[i0] + v00, resid[i0 + 1] + v01);
                *(float2*)(out + i1) = make_float2(resid[i1] + v10, resid[i1 + 1] + v11);
            } else if (MODE == 4) {
                float b0 = bias[colg], b1 = bias[colg + 1];
                v00 += b0; v01 += b1; v10 += b0; v11 += b1;
                v00 = 0.5f * v00 * (1.0f + erff(v00 * 0.70710678f));
                v01 = 0.5f * v01 * (1.0f + erff(v01 * 0.70710678f));
                v10 = 0.5f * v10 * (1.0f + erff(v10 * 0.70710678f));
                v11 = 0.5f * v11 * (1.0f + erff(v11 * 0.70710678f));
                __nv_bfloat16 h00 = __float2bfloat16(v00), h01 = __float2bfloat16(v01);
                __nv_bfloat16 h10 = __float2bfloat16(v10), h11 = __float2bfloat16(v11);
                __nv_bfloat162 p0 = __halves2bfloat162(h00, h01);
                __nv_bfloat162 p1 = __halves2bfloat162(h10, h11);
                *(uint32_t*)(ohi + i0) = *(uint32_t*)&p0;
                *(uint32_t*)(ohi + i1) = *(uint32_t*)&p1;
                *(uint32_t*)(olo + i0) = pack_bf2(v00 - __bfloat162float(h00), v01 - __bfloat162float(h01));
                *(uint32_t*)(olo + i1) = pack_bf2(v10 - __bfloat162float(h10), v11 - __bfloat162float(h11));
            } else if (MODE == 5) {
                float b0 = bias[colg], b1 = bias[colg + 1];
                *(float2*)(out + i0) = make_float2(resid[i0] + v00 + b0, resid[i0 + 1] + v01 + b1);
                *(float2*)(out + i1) = make_float2(resid[i1] + v10 + b0, resid[i1 + 1] + v11 + b1);
            }
        }
    }
}

// ============== mma.sync flash attention (bf16x3, FA2 single pass) ==========
#define KHI_OFF 0u
#define KLO_OFF 16384u
#define VHI_OFF 32768u
#define VLO_OFF 49152u
#define FA_SMEM 65536

__device__ __forceinline__ uint32_t fa_off(int r, int cbyte) {
    return (uint32_t)(r * 256 + (cbyte ^ ((r & 7) << 4)));
}

__global__ __launch_bounds__(256, 1)
void fa_mma(const __nv_bfloat16* __restrict__ qhi, const __nv_bfloat16* __restrict__ qlo,
            const __nv_bfloat16* __restrict__ khi, const __nv_bfloat16* __restrict__ klo,
            const __nv_bfloat16* __restrict__ vhi, const __nv_bfloat16* __restrict__ vlo,
            __nv_bfloat16* __restrict__ Ohi, __nv_bfloat16* __restrict__ Olo)
{
    extern __shared__ char sm[];
    uint32_t sb = smem_u32(sm);
    const int tid = threadIdx.x;
    const int w = tid >> 5, ln = tid & 31;
    const int tig = ln & 3, gid = ln >> 2;
    const int m0 = (gridDim.x - 1 - blockIdx.x) * 128;   // big tiles first
    const int bh = blockIdx.y;
    const size_t base = (size_t)bh * SS * DD;

    // ---- stage Q tile (128 x 128 bf16, hi then lo) through smem ----
    for (int f = tid; f < 2048; f += 256) {
        int r = f >> 4, c16 = f & 15;
        size_t g = base + (size_t)(m0 + r) * DD + c16 * 8;
        uint32_t so = fa_off(r, c16 * 16);
        *(uint4*)(sm + so)          = *(const uint4*)(qhi + g);
        *(uint4*)(sm + 32768 + so)  = *(const uint4*)(qlo + g);
    }
    __syncthreads();
    uint32_t Qh[8][4], Ql[8][4];
    {
        int row = 16 * w + ((ln >> 3) & 1) * 8 + (ln & 7);
        int kb0 = (ln >> 4) * 16;
        #pragma unroll
        for (int kk = 0; kk < 8; kk++) {
            uint32_t off = fa_off(row, kk * 32 + kb0);
            ldsm_x4(Qh[kk], sb + off);
            ldsm_x4(Ql[kk], sb + 32768 + off);
        }
    }
    __syncthreads();

    float Oa[16][4];
    #pragma unroll
    for (int j = 0; j < 16; j++)
        #pragma unroll
        for (int e = 0; e < 4; e++) Oa[j][e] = 0.f;
    float m0r = -1e30f, m1r = -1e30f, l0r = 0.f, l1r = 0.f;

    const int grow0 = m0 + 16 * w + gid;
    const int grow1 = grow0 + 8;
    const int nk = m0 / 64 + 2;

    for (int t = 0; t < nk; t++) {
        int n0 = t * 64;
        __syncthreads();
        for (int f = tid; f < 1024; f += 256) {
            int r = f >> 4, c16 = f & 15;
            size_t g = base + (size_t)(n0 + r) * DD + c16 * 8;
            uint32_t so = fa_off(r, c16 * 16);
            *(uint4*)(sm + KHI_OFF + so) = *(const uint4*)(khi + g);
            *(uint4*)(sm + KLO_OFF + so) = *(const uint4*)(klo + g);
            *(uint4*)(sm + VHI_OFF + so) = *(const uint4*)(vhi + g);
            *(uint4*)(sm + VLO_OFF + so) = *(const uint4*)(vlo + g);
        }
        __syncthreads();

        // ---- S = Q K^T (3-term) ----
        float S[8][4];
        #pragma unroll
        for (int j = 0; j < 8; j++)
            #pragma unroll
            for (int e = 0; e < 4; e++) S[j][e] = 0.f;
        {
            int brow = ((ln >> 4) << 3) + (ln & 7);
            int bkb  = ((ln >> 3) & 1) << 4;
            #pragma unroll
            for (int jp = 0; jp < 4; jp++) {
                #pragma unroll
                for (int kk = 0; kk < 8; kk++) {
                    int r_ = 16 * jp + brow;
                    uint32_t off = fa_off(r_, kk * 32 + bkb);
                    uint32_t Bh[4], Bl[4];
                    ldsm_x4(Bh, sb + KHI_OFF + off);
                    mma16816(S[2*jp],   Qh[kk], Bh);
                    mma16816(S[2*jp+1], Qh[kk], Bh + 2);
                    mma16816(S[2*jp],   Ql[kk], Bh);
                    mma16816(S[2*jp+1], Ql[kk], Bh + 2);
                    ldsm_x4(Bl, sb + KLO_OFF + off);
                    mma16816(S[2*jp],   Qh[kk], Bl);
                    mma16816(S[2*jp+1], Qh[kk], Bl + 2);
                }
            }
        }

        // ---- causal mask (only near-diagonal tiles) ----
        if (n0 + 63 > m0 + 16 * w) {
            #pragma unroll
            for (int j = 0; j < 8; j++) {
                int c = n0 + 8 * j + 2 * tig;
                if (c     > grow0) S[j][0] = -1e30f;
                if (c + 1 > grow0) S[j][1] = -1e30f;
                if (c     > grow1) S[j][2] = -1e30f;
                if (c + 1 > grow1) S[j][3] = -1e30f;
            }
        }

        // ---- online softmax ----
        float mx0 = -1e30f, mx1 = -1e30f;
        #pragma unroll
        for (int j = 0; j < 8; j++) {
            mx0 = fmaxf(mx0, fmaxf(S[j][0], S[j][1]));
            mx1 = fmaxf(mx1, fmaxf(S[j][2], S[j][3]));
        }
        mx0 = fmaxf(mx0, __shfl_xor_sync(0xffffffffu, mx0, 1));
        mx0 = fmaxf(mx0, __shfl_xor_sync(0xffffffffu, mx0, 2));
        mx1 = fmaxf(mx1, __shfl_xor_sync(0xffffffffu, mx1, 1));
        mx1 = fmaxf(mx1, __shfl_xor_sync(0xffffffffu, mx1, 2));
        float mn0 = fmaxf(m0r, mx0), mn1 = fmaxf(m1r, mx1);
        float a0 = __expf(m0r - mn0), a1 = __expf(m1r - mn1);
        m0r = mn0; m1r = mn1;
        l0r *= a0; l1r *= a1;

        uint32_t Phi[4][4], Plo[4][4];
        float ls0 = 0.f, ls1 = 0.f;
        #pragma unroll
        for (int j = 0; j < 8; j++) {
            float p0 = __expf(S[j][0] - mn0);
            float p1 = __expf(S[j][1] - mn0);
            float p2 = __expf(S[j][2] - mn1);
            float p3 = __expf(S[j][3] - mn1);
            ls0 += p0 + p1; ls1 += p2 + p3;
            __nv_bfloat16 h0 = __float2bfloat16(p0);
            __nv_bfloat16 h1 = __float2bfloat16(p1);
            __nv_bfloat16 h2 = __float2bfloat16(p2);
            __nv_bfloat16 h3 = __float2bfloat16(p3);
            int kk = j >> 1, q = (j & 1) * 2;
            __nv_bfloat162 hh01 = __halves2bfloat162(h0, h1);
            __nv_bfloat162 hh23 = __halves2bfloat162(h2, h3);
            Phi[kk][q]     = *(uint32_t*)&hh01;
            Phi[kk][q + 1] = *(uint32_t*)&hh23;
            Plo[kk][q]     = pack_bf2(p0 - __bfloat162float(h0), p1 - __bfloat162float(h1));
            Plo[kk][q + 1] = pack_bf2(p2 - __bfloat162float(h2), p3 - __bfloat162float(h3));
        }
        l0r += ls0; l1r += ls1;

        #pragma unroll
        for (int j = 0; j < 16; j++) {
            Oa[j][0] *= a0; Oa[j][1] *= a0;
            Oa[j][2] *= a1; Oa[j][3] *= a1;
        }

        // ---- O += P V (3-term) ----
        {
            int vrow = ((ln >> 3) & 1) * 8 + (ln & 7);
            int vcb  = (ln >> 4) << 4;
            #pragma unroll
            for (int jp = 0; jp < 8; jp++) {
                #pragma unroll
                for (int kk = 0; kk < 4; kk++) {
                    int r_ = 16 * kk + vrow;
                    uint32_t off = fa_off(r_, 32 * jp + vcb);
                    uint32_t Bh[4], Bl[4];
                    ldsm_x4_t(Bh, sb + VHI_OFF + off);
                    mma16816(Oa[2*jp],   Phi[kk], Bh);
                    mma16816(Oa[2*jp+1], Phi[kk], Bh + 2);
                    mma16816(Oa[2*jp],   Plo[kk], Bh);
                    mma16816(Oa[2*jp+1], Plo[kk], Bh + 2);
                    ldsm_x4_t(Bl, sb + VLO_OFF + off);
                    mma16816(Oa[2*jp],   Phi[kk], Bl);
                    mma16816(Oa[2*jp+1], Phi[kk], Bl + 2);
                }
            }
        }
    }

    // ---- finalize: reduce l, normalize, split hi/lo, store ----
    l0r += __shfl_xor_sync(0xffffffffu, l0r, 1);
    l0r += __shfl_xor_sync(0xffffffffu, l0r, 2);
    l1r += __shfl_xor_sync(0xffffffffu, l1r, 1);
    l1r += __shfl_xor_sync(0xffffffffu, l1r, 2);
    float inv0 = 1.0f / l0r, inv1 = 1.0f / l1r;
    #pragma unroll
    for (int j = 0; j < 16; j++) {
        int col = 8 * j + 2 * tig;
        size_t i0 = base + (size_t)grow0 * DD + col;
        size_t i1 = base + (size_t)grow1 * DD + col;
        float v00 = Oa[j][0] * inv0, v01 = Oa[j][1] * inv0;
        float v10 = Oa[j][2] * inv1, v11 = Oa[j][3] * inv1;
        __nv_bfloat16 h00 = __float2bfloat16(v00), h01 = __float2bfloat16(v01);
        __nv_bfloat16 h10 = __float2bfloat16(v10), h11 = __float2bfloat16(v11);
        __nv_bfloat162 p0 = __halves2bfloat162(h00, h01);
        __nv_bfloat162 p1 = __halves2bfloat162(h10, h11);
        *(uint32_t*)(Ohi + i0) = *(uint32_t*)&p0;
        *(uint32_t*)(Ohi + i1) = *(uint32_t*)&p1;
        *(uint32_t*)(Olo + i0) = pack_bf2(v00 - __bfloat162float(h00), v01 - __bfloat162float(h01));
        *(uint32_t*)(Olo + i1) = pack_bf2(v10 - __bfloat162float(h10), v11 - __bfloat162float(h11));
    }
}

// ---------------- launch -----------------------------------------------------
extern "C" void kernel_launch(void* const* d_in, const int* in_sizes, int n_in,
                              void* d_out, int out_size) {
    const float* x        = (const float*)d_in[0];
    const float* W_q      = (const float*)d_in[1];
    const float* W_k      = (const float*)d_in[2];
    const float* W_v      = (const float*)d_in[3];
    const float* W_o      = (const float*)d_in[4];
    const float* ln_attn_g= (const float*)d_in[5];
    const float* ln_attn_b= (const float*)d_in[6];
    const float* fc1_w    = (const float*)d_in[7];
    const float* fc1_b    = (const float*)d_in[8];
    const float* fc2_w    = (const float*)d_in[9];
    const float* fc2_b    = (const float*)d_in[10];
    const float* ln_mlp_g = (const float*)d_in[11];
    const float* ln_mlp_b = (const float*)d_in[12];
    float* out = (float*)d_out;

    float* x2;
    __nv_bfloat16 *h1h, *h1l, *h2h, *h2l, *th, *tl, *aoh, *aol;
    __nv_bfloat16 *qhi, *qlo, *khi, *klo, *vhi, *vlo;
    __nv_bfloat16 *wqh, *wql, *wkh, *wkl, *wvh, *wvl, *woh, *wol, *f1h, *f1l, *f2h, *f2l;
    cudaGetSymbolAddress((void**)&x2,  g_x2);
    cudaGetSymbolAddress((void**)&h1h, g_h1h); cudaGetSymbolAddress((void**)&h1l, g_h1l);
    cudaGetSymbolAddress((void**)&h2h, g_h2h); cudaGetSymbolAddress((void**)&h2l, g_h2l);
    cudaGetSymbolAddress((void**)&th,  g_th);  cudaGetSymbolAddress((void**)&tl,  g_tl);
    cudaGetSymbolAddress((void**)&aoh, g_aoh); cudaGetSymbolAddress((void**)&aol, g_aol);
    cudaGetSymbolAddress((void**)&qhi, g_qhi); cudaGetSymbolAddress((void**)&qlo, g_qlo);
    cudaGetSymbolAddress((void**)&khi, g_khi); cudaGetSymbolAddress((void**)&klo, g_klo);
    cudaGetSymbolAddress((void**)&vhi, g_vhi); cudaGetSymbolAddress((void**)&vlo, g_vlo);
    cudaGetSymbolAddress((void**)&wqh, g_wqh); cudaGetSymbolAddress((void**)&wql, g_wql);
    cudaGetSymbolAddress((void**)&wkh, g_wkh); cudaGetSymbolAddress((void**)&wkl, g_wkl);
    cudaGetSymbolAddress((void**)&wvh, g_wvh); cudaGetSymbolAddress((void**)&wvl, g_wvl);
    cudaGetSymbolAddress((void**)&woh, g_woh); cudaGetSymbolAddress((void**)&wol, g_wol);
    cudaGetSymbolAddress((void**)&f1h, g_f1h); cudaGetSymbolAddress((void**)&f1l, g_f1l);
    cudaGetSymbolAddress((void**)&f2h, g_f2h); cudaGetSymbolAddress((void**)&f2l, g_f2l);

    // 0) split weights to bf16 hi/lo
    split_k<<<(EE*HD)/1024, 256>>>(W_q, wqh, wql, EE*HD);
    split_k<<<(EE*HD)/1024, 256>>>(W_k, wkh, wkl, EE*HD);
    split_k<<<(EE*HD)/1024, 256>>>(W_v, wvh, wvl, EE*HD);
    split_k<<<(HD*EE)/1024, 256>>>(W_o, woh, wol, HD*EE);
    split_k<<<(EE*DHH)/1024, 256>>>(fc1_w, f1h, f1l, EE*DHH);
    split_k<<<(DHH*EE)/1024, 256>>>(fc2_w, f2h, f2l, DHH*EE);

    // 1) LN -> bf16 hi/lo
    ln_kernel<<<MM/8, 256>>>(x, ln_attn_g, ln_attn_b, h1h, h1l);

    // 2) QKV projections (tensor core) with fused RoPE / scale / split
    const float qscale = 0.08838834764831845f;  // 1/sqrt(128)
    dim3 gq(HD/128, MM/128);
    cudaFuncSetAttribute(mm3<1,false,false>, cudaFuncAttributeMaxDynamicSharedMemorySize, MM3_SMEM);
    cudaFuncSetAttribute(mm3<2,false,false>, cudaFuncAttributeMaxDynamicSharedMemorySize, MM3_SMEM);
    cudaFuncSetAttribute(mm3<3,true,true>,   cudaFuncAttributeMaxDynamicSharedMemorySize, MM3_SMEM);
    cudaFuncSetAttribute(mm3<4,false,false>, cudaFuncAttributeMaxDynamicSharedMemorySize, MM3_SMEM);
    cudaFuncSetAttribute(mm3<5,false,true>,  cudaFuncAttributeMaxDynamicSharedMemorySize, MM3_SMEM);
    mm3<1,false,false><<<gq, 256, MM3_SMEM>>>(h1h, h1l, wqh, wql, nullptr, nullptr, nullptr, qhi, qlo, MM, HD, EE, qscale);
    mm3<1,false,false><<<gq, 256, MM3_SMEM>>>(h1h, h1l, wkh, wkl, nullptr, nullptr, nullptr, khi, klo, MM, HD, EE, 1.0f);
    mm3<2,false,false><<<gq, 256, MM3_SMEM>>>(h1h, h1l, wvh, wvl, nullptr, nullptr, nullptr, vhi, vlo, MM, HD, EE, 1.0f);

    // 3) causal flash attention (tensor core), emits bf16 hi/lo
    cudaFuncSetAttribute(fa_mma, cudaFuncAttributeMaxDynamicSharedMemorySize, FA_SMEM);
    fa_mma<<<dim3(SS/128, BB*HH), 256, FA_SMEM>>>(qhi, qlo, khi, klo, vhi, vlo, aoh, aol);

    // 4) O-projection + residual (tensor core, A gathered from (B,H,S,D))
    mm3<3,true,true><<<dim3(1, MM/64), 256, MM3_SMEM>>>(aoh, aol, woh, wol, nullptr, x, x2, nullptr, nullptr, MM, EE, HD, 1.0f);

    // 5) LN -> bf16 hi/lo
    ln_kernel<<<MM/8, 256>>>(x2, ln_mlp_g, ln_mlp_b, h2h, h2l);

    // 6) MLP (tensor core)
    mm3<4,false,false><<<dim3(DHH/128, MM/128), 256, MM3_SMEM>>>(h2h, h2l, f1h, f1l, fc1_b, nullptr, nullptr, th, tl, MM, DHH, EE, 1.0f);
    mm3<5,false,true><<<dim3(1, MM/64), 256, MM3_SMEM>>>(th, tl, f2h, f2l, fc2_b, x2, out, nullptr, nullptr, MM, EE, DHH, 1.0f);
}

// round 8
// speedup vs baseline: 2.3653x; 1.1719x over previous
#include <cuda_runtime.h>
#include <cuda_bf16.h>
#include <math.h>
#include <stdint.h>

#define BB 2
#define SS 2048
#define EE 128
#define HH 16
#define DD 128
#define DHH 512
#define MM (BB*SS)     // 4096 rows
#define HD (HH*DD)     // 2048

// ---------------- scratch (static __device__, no allocation) ----------------
__device__ float g_x2[MM*EE];
__device__ __nv_bfloat16 g_h1h[MM*EE],  g_h1l[MM*EE];
__device__ __nv_bfloat16 g_h2h[MM*EE],  g_h2l[MM*EE];
__device__ __nv_bfloat16 g_th [MM*DHH], g_tl [MM*DHH];
__device__ __nv_bfloat16 g_aoh[MM*HD],  g_aol[MM*HD];
__device__ __nv_bfloat16 g_qhi[MM*HD],  g_qlo[MM*HD];
__device__ __nv_bfloat16 g_khi[MM*HD],  g_klo[MM*HD];
__device__ __nv_bfloat16 g_vhi[MM*HD],  g_vlo[MM*HD];
__device__ __nv_bfloat16 g_wqh[EE*HD],  g_wql[EE*HD];
__device__ __nv_bfloat16 g_wkh[EE*HD],  g_wkl[EE*HD];
__device__ __nv_bfloat16 g_wvh[EE*HD],  g_wvl[EE*HD];
__device__ __nv_bfloat16 g_woh[HD*EE],  g_wol[HD*EE];
__device__ __nv_bfloat16 g_f1h[EE*DHH], g_f1l[EE*DHH];
__device__ __nv_bfloat16 g_f2h[DHH*EE], g_f2l[DHH*EE];

// ======================= warp MMA helpers (baseline PTX) =====================
__device__ __forceinline__ uint32_t smem_u32(const void* p) {
    uint32_t a;
    asm("{ .reg .u64 t; cvta.to.shared.u64 t, %1; cvt.u32.u64 %0, t; }"
        : "=r"(a) : "l"(p));
    return a;
}
__device__ __forceinline__ void mma16816(float* c, const uint32_t* a, const uint32_t* b) {
    asm volatile(
        "mma.sync.aligned.m16n8k16.row.col.f32.bf16.bf16.f32 "
        "{%0,%1,%2,%3}, {%4,%5,%6,%7}, {%8,%9}, {%0,%1,%2,%3};"
        : "+f"(c[0]), "+f"(c[1]), "+f"(c[2]), "+f"(c[3])
        : "r"(a[0]), "r"(a[1]), "r"(a[2]), "r"(a[3]), "r"(b[0]), "r"(b[1]));
}
__device__ __forceinline__ void ldsm_x4(uint32_t* r, uint32_t addr) {
    asm volatile("ldmatrix.sync.aligned.m8n8.x4.shared.b16 {%0,%1,%2,%3}, [%4];"
        : "=r"(r[0]), "=r"(r[1]), "=r"(r[2]), "=r"(r[3]) : "r"(addr));
}
__device__ __forceinline__ void ldsm_x4_t(uint32_t* r, uint32_t addr) {
    asm volatile("ldmatrix.sync.aligned.m8n8.x4.trans.shared.b16 {%0,%1,%2,%3}, [%4];"
        : "=r"(r[0]), "=r"(r[1]), "=r"(r[2]), "=r"(r[3]) : "r"(addr));
}
__device__ __forceinline__ uint32_t pack_bf2(float a, float b) {
    __nv_bfloat162 h = __halves2bfloat162(__float2bfloat16(a), __float2bfloat16(b));
    return *(uint32_t*)&h;
}
__device__ __forceinline__ void cp16(uint32_t smem_addr, const void* gptr) {
    asm volatile("cp.async.cg.shared.global [%0], [%1], 16;"
        :: "r"(smem_addr), "l"(gptr) : "memory");
}
#define CP_COMMIT() asm volatile("cp.async.commit_group;" ::: "memory")
#define CP_WAIT(n)  asm volatile("cp.async.wait_group %0;" :: "n"(n) : "memory")

// 256B-row swizzle (B tiles, FA tiles); 128B-row swizzle (A tiles)
__device__ __forceinline__ uint32_t boff(int r, int cbyte) {
    return (uint32_t)(r * 256 + (cbyte ^ ((r & 7) << 4)));
}
__device__ __forceinline__ uint32_t aoff(int r, int cbyte) {
    return (uint32_t)(r * 128 + (cbyte ^ ((r & 7) << 4)));
}

// ---------------- fp32 -> bf16 hi/lo split ----------------------------------
__global__ void split_k(const float* __restrict__ w, __nv_bfloat16* __restrict__ hi,
                        __nv_bfloat16* __restrict__ lo, int n) {
    int i = (blockIdx.x * 256 + threadIdx.x) * 4;
    if (i >= n) return;
    float4 v = *(const float4*)(w + i);
    __nv_bfloat16 h0 = __float2bfloat16(v.x), h1 = __float2bfloat16(v.y);
    __nv_bfloat16 h2 = __float2bfloat16(v.z), h3 = __float2bfloat16(v.w);
    __nv_bfloat162 hh01 = __halves2bfloat162(h0, h1), hh23 = __halves2bfloat162(h2, h3);
    *(uint2*)(hi + i) = make_uint2(*(uint32_t*)&hh01, *(uint32_t*)&hh23);
    uint32_t l01 = pack_bf2(v.x - __bfloat162float(h0), v.y - __bfloat162float(h1));
    uint32_t l23 = pack_bf2(v.z - __bfloat162float(h2), v.w - __bfloat162float(h3));
    *(uint2*)(lo + i) = make_uint2(l01, l23);
}

// ---------------- LayerNorm: one warp per row, bf16 hi/lo out ---------------
__global__ void ln_kernel(const float* __restrict__ x, const float* __restrict__ g,
                          const float* __restrict__ b,
                          __nv_bfloat16* __restrict__ ohi, __nv_bfloat16* __restrict__ olo) {
    int warp = threadIdx.x >> 5, lane = threadIdx.x & 31;
    int row = blockIdx.x * 8 + warp;
    float4 v = ((const float4*)(x + (size_t)row * EE))[lane];
    float s = v.x + v.y + v.z + v.w;
    #pragma unroll
    for (int o = 16; o; o >>= 1) s += __shfl_xor_sync(0xffffffffu, s, o);
    float mu = s * (1.0f / EE);
    float d0 = v.x - mu, d1 = v.y - mu, d2 = v.z - mu, d3 = v.w - mu;
    float q = d0*d0 + d1*d1 + d2*d2 + d3*d3;
    #pragma unroll
    for (int o = 16; o; o >>= 1) q += __shfl_xor_sync(0xffffffffu, q, o);
    float inv = rsqrtf(q * (1.0f / EE) + 1e-5f);
    float4 gg = ((const float4*)g)[lane];
    float4 bb = ((const float4*)b)[lane];
    float r0 = d0 * inv * gg.x + bb.x;
    float r1 = d1 * inv * gg.y + bb.y;
    float r2 = d2 * inv * gg.z + bb.z;
    float r3 = d3 * inv * gg.w + bb.w;
    __nv_bfloat16 h0 = __float2bfloat16(r0), h1 = __float2bfloat16(r1);
    __nv_bfloat16 h2 = __float2bfloat16(r2), h3 = __float2bfloat16(r3);
    __nv_bfloat162 hh01 = __halves2bfloat162(h0, h1), hh23 = __halves2bfloat162(h2, h3);
    size_t base = (size_t)row * EE + lane * 4;
    *(uint2*)(ohi + base) = make_uint2(*(uint32_t*)&hh01, *(uint32_t*)&hh23);
    uint32_t l01 = pack_bf2(r0 - __bfloat162float(h0), r1 - __bfloat162float(h1));
    uint32_t l23 = pack_bf2(r2 - __bfloat162float(h2), r3 - __bfloat162float(h3));
    *(uint2*)(olo + base) = make_uint2(l01, l23);
}

// =============== bf16x3 tensor-core GEMM with fused epilogues ================
#define MM3_AHI 0u
#define MM3_ALO 16384u
#define MM3_BHI 32768u
#define MM3_BLO 49152u
#define MM3_SMEM 65536

template<int MODE, bool AG, bool HALFM>
__global__ __launch_bounds__(256)
void mm3(const __nv_bfloat16* __restrict__ Ahi, const __nv_bfloat16* __restrict__ Alo,
         const __nv_bfloat16* __restrict__ Bhi, const __nv_bfloat16* __restrict__ Blo,
         const float* __restrict__ bias, const float* __restrict__ resid,
         float* __restrict__ out,
         __nv_bfloat16* __restrict__ ohi, __nv_bfloat16* __restrict__ olo,
         int M, int N, int K, float qscale)
{
    extern __shared__ char sm[];
    uint32_t sb = smem_u32(sm);
    constexpr int MT = HALFM ? 64 : 128;
    constexpr int NJ = HALFM ? 8 : 16;
    const int tid = threadIdx.x;
    const int w = tid >> 5, ln = tid & 31;
    const int tig = ln & 3, gid = ln >> 2;
    const int wr = HALFM ? (w & 3) : w;
    const int wc = HALFM ? (w >> 2) * 64 : 0;
    const int m0 = blockIdx.y * MT, n0 = blockIdx.x * 128;

    float C[NJ][4];
    #pragma unroll
    for (int j = 0; j < NJ; j++)
        #pragma unroll
        for (int e = 0; e < 4; e++) C[j][e] = 0.f;

    const int arow = 16 * wr + ((ln >> 3) & 1) * 8 + (ln & 7);
    const int akb  = (ln >> 4) * 16;
    const int brow = ((ln >> 3) & 1) * 8 + (ln & 7);
    const int bcb  = (ln >> 4) << 4;

    for (int k0 = 0; k0 < K; k0 += 64) {
        for (int f = tid; f < MT * 8; f += 256) {
            int r = f >> 3, seg = f & 7;
            size_t g;
            if (!AG) {
                g = (size_t)(m0 + r) * K + k0 + seg * 8;
            } else {
                int rr = m0 + r;
                int b_ = rr >> 11, s_ = rr & 2047;
                int kk = k0 + seg * 8;
                g = ((size_t)(b_ * HH + (kk >> 7)) * SS + s_) * DD + (kk & 127);
            }
            uint32_t so = aoff(r, seg * 16);
            *(uint4*)(sm + MM3_AHI + so) = *(const uint4*)(Ahi + g);
            *(uint4*)(sm + MM3_ALO + so) = *(const uint4*)(Alo + g);
        }
        for (int f = tid; f < 1024; f += 256) {
            int r = f >> 4, seg = f & 15;
            size_t g = (size_t)(k0 + r) * N + n0 + seg * 8;
            uint32_t so = boff(r, seg * 16);
            *(uint4*)(sm + MM3_BHI + so) = *(const uint4*)(Bhi + g);
            *(uint4*)(sm + MM3_BLO + so) = *(const uint4*)(Blo + g);
        }
        __syncthreads();

        uint32_t Ah[4][4], Al[4][4];
        #pragma unroll
        for (int kk = 0; kk < 4; kk++) {
            uint32_t off = aoff(arow, kk * 32 + akb);
            ldsm_x4(Ah[kk], sb + MM3_AHI + off);
            ldsm_x4(Al[kk], sb + MM3_ALO + off);
        }
        #pragma unroll
        for (int jp = 0; jp < NJ / 2; jp++) {
            int ncb = (wc + 16 * jp) * 2;
            #pragma unroll
            for (int kk = 0; kk < 4; kk++) {
                uint32_t off = boff(16 * kk + brow, ncb + bcb);
                uint32_t Bh[4], Bl[4];
                ldsm_x4_t(Bh, sb + MM3_BHI + off);
                mma16816(C[2*jp],   Ah[kk], Bh);
                mma16816(C[2*jp+1], Ah[kk], Bh + 2);
                mma16816(C[2*jp],   Al[kk], Bh);
                mma16816(C[2*jp+1], Al[kk], Bh + 2);
                ldsm_x4_t(Bl, sb + MM3_BLO + off);
                mma16816(C[2*jp],   Ah[kk], Bl);
                mma16816(C[2*jp+1], Ah[kk], Bl + 2);
            }
        }
        __syncthreads();
    }

    const int r0 = m0 + 16 * wr + gid;
    const int r1 = r0 + 8;
    if (MODE == 1 || MODE == 2) {
        int b_ = r0 >> 11, s0 = r0 & 2047, s1 = r1 & 2047;
        #pragma unroll
        for (int j = 0; j < NJ; j++) {
            int colg = n0 + wc + 8 * j + 2 * tig;
            int h = colg >> 7, d = colg & 127;
            float o00 = C[j][0] * qscale, o01 = C[j][1] * qscale;
            float o10 = C[j][2] * qscale, o11 = C[j][3] * qscale;
            if (MODE == 1) {
                int t2 = d >> 1;
                float f = expf((float)t2 * -0.14391157f);
                float si0, co0, si1, co1;
                sincosf((float)s0 * f, &si0, &co0);
                sincosf((float)s1 * f, &si1, &co1);
                float a = o00 * co0 - o01 * si0, b2 = o00 * si0 + o01 * co0;
                o00 = a; o01 = b2;
                a = o10 * co1 - o11 * si1; b2 = o10 * si1 + o11 * co1;
                o10 = a; o11 = b2;
            }
            size_t oi0 = (((size_t)(b_ * HH + h) * SS + s0) * DD + d);
            size_t oi1 = (((size_t)(b_ * HH + h) * SS + s1) * DD + d);
            __nv_bfloat16 h00 = __float2bfloat16(o00), h01 = __float2bfloat16(o01);
            __nv_bfloat16 h10 = __float2bfloat16(o10), h11 = __float2bfloat16(o11);
            __nv_bfloat162 p0 = __halves2bfloat162(h00, h01);
            __nv_bfloat162 p1 = __halves2bfloat162(h10, h11);
            *(uint32_t*)(ohi + oi0) = *(uint32_t*)&p0;
            *(uint32_t*)(ohi + oi1) = *(uint32_t*)&p1;
            *(uint32_t*)(olo + oi0) = pack_bf2(o00 - __bfloat162float(h00), o01 - __bfloat162float(h01));
            *(uint32_t*)(olo + oi1) = pack_bf2(o10 - __bfloat162float(h10), o11 - __bfloat162float(h11));
        }
    } else {
        #pragma unroll
        for (int j = 0; j < NJ; j++) {
            int colg = n0 + wc + 8 * j + 2 * tig;
            size_t i0 = (size_t)r0 * N + colg;
            size_t i1 = (size_t)r1 * N + colg;
            float v00 = C[j][0], v01 = C[j][1], v10 = C[j][2], v11 = C[j][3];
            if (MODE == 3) {
                *(float2*)(out + i0) = make_float2(resid[i0] + v00, resid[i0 + 1] + v01);
                *(float2*)(out + i1) = make_float2(resid[i1] + v10, resid[i1 + 1] + v11);
            } else if (MODE == 4) {
                float b0 = bias[colg], b1 = bias[colg + 1];
                v00 += b0; v01 += b1; v10 += b0; v11 += b1;
                v00 = 0.5f * v00 * (1.0f + erff(v00 * 0.70710678f));
                v01 = 0.5f * v01 * (1.0f + erff(v01 * 0.70710678f));
                v10 = 0.5f * v10 * (1.0f + erff(v10 * 0.70710678f));
                v11 = 0.5f * v11 * (1.0f + erff(v11 * 0.70710678f));
                __nv_bfloat16 h00 = __float2bfloat16(v00), h01 = __float2bfloat16(v01);
                __nv_bfloat16 h10 = __float2bfloat16(v10), h11 = __float2bfloat16(v11);
                __nv_bfloat162 p0 = __halves2bfloat162(h00, h01);
                __nv_bfloat162 p1 = __halves2bfloat162(h10, h11);
                *(uint32_t*)(ohi + i0) = *(uint32_t*)&p0;
                *(uint32_t*)(ohi + i1) = *(uint32_t*)&p1;
                *(uint32_t*)(olo + i0) = pack_bf2(v00 - __bfloat162float(h00), v01 - __bfloat162float(h01));
                *(uint32_t*)(olo + i1) = pack_bf2(v10 - __bfloat162float(h10), v11 - __bfloat162float(h11));
            } else if (MODE == 5) {
                float b0 = bias[colg], b1 = bias[colg + 1];
                *(float2*)(out + i0) = make_float2(resid[i0] + v00 + b0, resid[i0 + 1] + v01 + b1);
                *(float2*)(out + i1) = make_float2(resid[i1] + v10 + b0, resid[i1 + 1] + v11 + b1);
            }
        }
    }
}

// ============== mma.sync flash attention (bf16x3, cp.async double-buffer) ===
// Per stage (64KB): Khi[16K] Klo[16K] Vhi[16K] Vlo[16K]; 2 stages = 128KB.
#define KHI_OFF 0u
#define KLO_OFF 16384u
#define VHI_OFF 32768u
#define VLO_OFF 49152u
#define FA_STAGE 65536u
#define FA_SMEM 131072

__device__ __forceinline__ uint32_t fa_off(int r, int cbyte) {
    return (uint32_t)(r * 256 + (cbyte ^ ((r & 7) << 4)));
}

__global__ __launch_bounds__(256, 1)
void fa_mma(const __nv_bfloat16* __restrict__ qhi, const __nv_bfloat16* __restrict__ qlo,
            const __nv_bfloat16* __restrict__ khi, const __nv_bfloat16* __restrict__ klo,
            const __nv_bfloat16* __restrict__ vhi, const __nv_bfloat16* __restrict__ vlo,
            __nv_bfloat16* __restrict__ Ohi, __nv_bfloat16* __restrict__ Olo)
{
    extern __shared__ char sm[];
    uint32_t sb = smem_u32(sm);
    const int tid = threadIdx.x;
    const int w = tid >> 5, ln = tid & 31;
    const int tig = ln & 3, gid = ln >> 2;
    const int m0 = (gridDim.x - 1 - blockIdx.x) * 128;   // big tiles first
    const int bh = blockIdx.y;
    const size_t base = (size_t)bh * SS * DD;

    // ---- stage Q tile through smem (regions overwritten later by K/V) ----
    for (int f = tid; f < 2048; f += 256) {
        int r = f >> 4, c16 = f & 15;
        size_t g = base + (size_t)(m0 + r) * DD + c16 * 8;
        uint32_t so = fa_off(r, c16 * 16);
        *(uint4*)(sm + so)              = *(const uint4*)(qhi + g);
        *(uint4*)(sm + FA_STAGE + so)   = *(const uint4*)(qlo + g);
    }
    __syncthreads();
    uint32_t Qh[8][4], Ql[8][4];
    {
        int row = 16 * w + ((ln >> 3) & 1) * 8 + (ln & 7);
        int kb0 = (ln >> 4) * 16;
        #pragma unroll
        for (int kk = 0; kk < 8; kk++) {
            uint32_t off = fa_off(row, kk * 32 + kb0);
            ldsm_x4(Qh[kk], sb + off);
            ldsm_x4(Ql[kk], sb + FA_STAGE + off);
        }
    }
    __syncthreads();

    float Oa[16][4];
    #pragma unroll
    for (int j = 0; j < 16; j++)
        #pragma unroll
        for (int e = 0; e < 4; e++) Oa[j][e] = 0.f;
    float m0r = -1e30f, m1r = -1e30f, l0r = 0.f, l1r = 0.f;

    const int grow0 = m0 + 16 * w + gid;
    const int grow1 = grow0 + 8;
    const int nk = m0 / 64 + 2;

    // ---- prologue: prefetch tile 0 into stage 0 ----
    {
        for (int f = tid; f < 1024; f += 256) {
            int r = f >> 4, c16 = f & 15;
            size_t g = base + (size_t)r * DD + c16 * 8;
            uint32_t so = fa_off(r, c16 * 16);
            cp16(sb + KHI_OFF + so, khi + g);
            cp16(sb + KLO_OFF + so, klo + g);
            cp16(sb + VHI_OFF + so, vhi + g);
            cp16(sb + VLO_OFF + so, vlo + g);
        }
        CP_COMMIT();
    }

    for (int t = 0; t < nk; t++) {
        int n0 = t * 64;
        uint32_t st = (uint32_t)(t & 1) * FA_STAGE;
        __syncthreads();   // everyone done with the stage we're about to overwrite
        if (t + 1 < nk) {
            uint32_t stn = (uint32_t)((t + 1) & 1) * FA_STAGE;
            int n1 = n0 + 64;
            for (int f = tid; f < 1024; f += 256) {
                int r = f >> 4, c16 = f & 15;
                size_t g = base + (size_t)(n1 + r) * DD + c16 * 8;
                uint32_t so = fa_off(r, c16 * 16);
                cp16(sb + stn + KHI_OFF + so, khi + g);
                cp16(sb + stn + KLO_OFF + so, klo + g);
                cp16(sb + stn + VHI_OFF + so, vhi + g);
                cp16(sb + stn + VLO_OFF + so, vlo + g);
            }
            CP_COMMIT();
            CP_WAIT(1);
        } else {
            CP_WAIT(0);
        }
        __syncthreads();   // current stage data visible to all

        // ---- S = Q K^T (3-term) ----
        float S[8][4];
        #pragma unroll
        for (int j = 0; j < 8; j++)
            #pragma unroll
            for (int e = 0; e < 4; e++) S[j][e] = 0.f;
        {
            int brow = ((ln >> 4) << 3) + (ln & 7);
            int bkb  = ((ln >> 3) & 1) << 4;
            #pragma unroll
            for (int jp = 0; jp < 4; jp++) {
                #pragma unroll
                for (int kk = 0; kk < 8; kk++) {
                    int r_ = 16 * jp + brow;
                    uint32_t off = fa_off(r_, kk * 32 + bkb);
                    uint32_t Bh[4], Bl[4];
                    ldsm_x4(Bh, sb + st + KHI_OFF + off);
                    mma16816(S[2*jp],   Qh[kk], Bh);
                    mma16816(S[2*jp+1], Qh[kk], Bh + 2);
                    mma16816(S[2*jp],   Ql[kk], Bh);
                    mma16816(S[2*jp+1], Ql[kk], Bh + 2);
                    ldsm_x4(Bl, sb + st + KLO_OFF + off);
                    mma16816(S[2*jp],   Qh[kk], Bl);
                    mma16816(S[2*jp+1], Qh[kk], Bl + 2);
                }
            }
        }

        // ---- causal mask (only near-diagonal tiles) ----
        if (n0 + 63 > m0 + 16 * w) {
            #pragma unroll
            for (int j = 0; j < 8; j++) {
                int c = n0 + 8 * j + 2 * tig;
                if (c     > grow0) S[j][0] = -1e30f;
                if (c + 1 > grow0) S[j][1] = -1e30f;
                if (c     > grow1) S[j][2] = -1e30f;
                if (c + 1 > grow1) S[j][3] = -1e30f;
            }
        }

        // ---- online softmax ----
        float mx0 = -1e30f, mx1 = -1e30f;
        #pragma unroll
        for (int j = 0; j < 8; j++) {
            mx0 = fmaxf(mx0, fmaxf(S[j][0], S[j][1]));
            mx1 = fmaxf(mx1, fmaxf(S[j][2], S[j][3]));
        }
        mx0 = fmaxf(mx0, __shfl_xor_sync(0xffffffffu, mx0, 1));
        mx0 = fmaxf(mx0, __shfl_xor_sync(0xffffffffu, mx0, 2));
        mx1 = fmaxf(mx1, __shfl_xor_sync(0xffffffffu, mx1, 1));
        mx1 = fmaxf(mx1, __shfl_xor_sync(0xffffffffu, mx1, 2));
        float mn0 = fmaxf(m0r, mx0), mn1 = fmaxf(m1r, mx1);
        bool nochg = (mn0 == m0r) && (mn1 == m1r);
        float a0 = nochg ? 1.f : __expf(m0r - mn0);
        float a1 = nochg ? 1.f : __expf(m1r - mn1);
        m0r = mn0; m1r = mn1;
        l0r *= a0; l1r *= a1;

        uint32_t Phi[4][4], Plo[4][4];
        float ls0 = 0.f, ls1 = 0.f;
        #pragma unroll
        for (int j = 0; j < 8; j++) {
            float p0 = __expf(S[j][0] - mn0);
            float p1 = __expf(S[j][1] - mn0);
            float p2 = __expf(S[j][2] - mn1);
            float p3 = __expf(S[j][3] - mn1);
            ls0 += p0 + p1; ls1 += p2 + p3;
            __nv_bfloat16 h0 = __float2bfloat16(p0);
            __nv_bfloat16 h1 = __float2bfloat16(p1);
            __nv_bfloat16 h2 = __float2bfloat16(p2);
            __nv_bfloat16 h3 = __float2bfloat16(p3);
            int kk = j >> 1, q = (j & 1) * 2;
            __nv_bfloat162 hh01 = __halves2bfloat162(h0, h1);
            __nv_bfloat162 hh23 = __halves2bfloat162(h2, h3);
            Phi[kk][q]     = *(uint32_t*)&hh01;
            Phi[kk][q + 1] = *(uint32_t*)&hh23;
            Plo[kk][q]     = pack_bf2(p0 - __bfloat162float(h0), p1 - __bfloat162float(h1));
            Plo[kk][q + 1] = pack_bf2(p2 - __bfloat162float(h2), p3 - __bfloat162float(h3));
        }
        l0r += ls0; l1r += ls1;

        if (!__all_sync(0xffffffffu, nochg)) {
            #pragma unroll
            for (int j = 0; j < 16; j++) {
                Oa[j][0] *= a0; Oa[j][1] *= a0;
                Oa[j][2] *= a1; Oa[j][3] *= a1;
            }
        }

        // ---- O += P V (3-term) ----
        {
            int vrow = ((ln >> 3) & 1) * 8 + (ln & 7);
            int vcb  = (ln >> 4) << 4;
            #pragma unroll
            for (int jp = 0; jp < 8; jp++) {
                #pragma unroll
                for (int kk = 0; kk < 4; kk++) {
                    int r_ = 16 * kk + vrow;
                    uint32_t off = fa_off(r_, 32 * jp + vcb);
                    uint32_t Bh[4], Bl[4];
                    ldsm_x4_t(Bh, sb + st + VHI_OFF + off);
                    mma16816(Oa[2*jp],   Phi[kk], Bh);
                    mma16816(Oa[2*jp+1], Phi[kk], Bh + 2);
                    mma16816(Oa[2*jp],   Plo[kk], Bh);
                    mma16816(Oa[2*jp+1], Plo[kk], Bh + 2);
                    ldsm_x4_t(Bl, sb + st + VLO_OFF + off);
                    mma16816(Oa[2*jp],   Phi[kk], Bl);
                    mma16816(Oa[2*jp+1], Phi[kk], Bl + 2);
                }
            }
        }
    }

    // ---- finalize: reduce l, normalize, split hi/lo, store ----
    l0r += __shfl_xor_sync(0xffffffffu, l0r, 1);
    l0r += __shfl_xor_sync(0xffffffffu, l0r, 2);
    l1r += __shfl_xor_sync(0xffffffffu, l1r, 1);
    l1r += __shfl_xor_sync(0xffffffffu, l1r, 2);
    float inv0 = 1.0f / l0r, inv1 = 1.0f / l1r;
    #pragma unroll
    for (int j = 0; j < 16; j++) {
        int col = 8 * j + 2 * tig;
        size_t i0 = base + (size_t)grow0 * DD + col;
        size_t i1 = base + (size_t)grow1 * DD + col;
        float v00 = Oa[j][0] * inv0, v01 = Oa[j][1] * inv0;
        float v10 = Oa[j][2] * inv1, v11 = Oa[j][3] * inv1;
        __nv_bfloat16 h00 = __float2bfloat16(v00), h01 = __float2bfloat16(v01);
        __nv_bfloat16 h10 = __float2bfloat16(v10), h11 = __float2bfloat16(v11);
        __nv_bfloat162 p0 = __halves2bfloat162(h00, h01);
        __nv_bfloat162 p1 = __halves2bfloat162(h10, h11);
        *(uint32_t*)(Ohi + i0) = *(uint32_t*)&p0;
        *(uint32_t*)(Ohi + i1) = *(uint32_t*)&p1;
        *(uint32_t*)(Olo + i0) = pack_bf2(v00 - __bfloat162float(h00), v01 - __bfloat162float(h01));
        *(uint32_t*)(Olo + i1) = pack_bf2(v10 - __bfloat162float(h10), v11 - __bfloat162float(h11));
    }
}

// ---------------- launch -----------------------------------------------------
extern "C" void kernel_launch(void* const* d_in, const int* in_sizes, int n_in,
                              void* d_out, int out_size) {
    const float* x        = (const float*)d_in[0];
    const float* W_q      = (const float*)d_in[1];
    const float* W_k      = (const float*)d_in[2];
    const float* W_v      = (const float*)d_in[3];
    const float* W_o      = (const float*)d_in[4];
    const float* ln_attn_g= (const float*)d_in[5];
    const float* ln_attn_b= (const float*)d_in[6];
    const float* fc1_w    = (const float*)d_in[7];
    const float* fc1_b    = (const float*)d_in[8];
    const float* fc2_w    = (const float*)d_in[9];
    const float* fc2_b    = (const float*)d_in[10];
    const float* ln_mlp_g = (const float*)d_in[11];
    const float* ln_mlp_b = (const float*)d_in[12];
    float* out = (float*)d_out;

    float* x2;
    __nv_bfloat16 *h1h, *h1l, *h2h, *h2l, *th, *tl, *aoh, *aol;
    __nv_bfloat16 *qhi, *qlo, *khi, *klo, *vhi, *vlo;
    __nv_bfloat16 *wqh, *wql, *wkh, *wkl, *wvh, *wvl, *woh, *wol, *f1h, *f1l, *f2h, *f2l;
    cudaGetSymbolAddress((void**)&x2,  g_x2);
    cudaGetSymbolAddress((void**)&h1h, g_h1h); cudaGetSymbolAddress((void**)&h1l, g_h1l);
    cudaGetSymbolAddress((void**)&h2h, g_h2h); cudaGetSymbolAddress((void**)&h2l, g_h2l);
    cudaGetSymbolAddress((void**)&th,  g_th);  cudaGetSymbolAddress((void**)&tl,  g_tl);
    cudaGetSymbolAddress((void**)&aoh, g_aoh); cudaGetSymbolAddress((void**)&aol, g_aol);
    cudaGetSymbolAddress((void**)&qhi, g_qhi); cudaGetSymbolAddress((void**)&qlo, g_qlo);
    cudaGetSymbolAddress((void**)&khi, g_khi); cudaGetSymbolAddress((void**)&klo, g_klo);
    cudaGetSymbolAddress((void**)&vhi, g_vhi); cudaGetSymbolAddress((void**)&vlo, g_vlo);
    cudaGetSymbolAddress((void**)&wqh, g_wqh); cudaGetSymbolAddress((void**)&wql, g_wql);
    cudaGetSymbolAddress((void**)&wkh, g_wkh); cudaGetSymbolAddress((void**)&wkl, g_wkl);
    cudaGetSymbolAddress((void**)&wvh, g_wvh); cudaGetSymbolAddress((void**)&wvl, g_wvl);
    cudaGetSymbolAddress((void**)&woh, g_woh); cudaGetSymbolAddress((void**)&wol, g_wol);
    cudaGetSymbolAddress((void**)&f1h, g_f1h); cudaGetSymbolAddress((void**)&f1l, g_f1l);
    cudaGetSymbolAddress((void**)&f2h, g_f2h); cudaGetSymbolAddress((void**)&f2l, g_f2l);

    // 0) split weights to bf16 hi/lo
    split_k<<<(EE*HD)/1024, 256>>>(W_q, wqh, wql, EE*HD);
    split_k<<<(EE*HD)/1024, 256>>>(W_k, wkh, wkl, EE*HD);
    split_k<<<(EE*HD)/1024, 256>>>(W_v, wvh, wvl, EE*HD);
    split_k<<<(HD*EE)/1024, 256>>>(W_o, woh, wol, HD*EE);
    split_k<<<(EE*DHH)/1024, 256>>>(fc1_w, f1h, f1l, EE*DHH);
    split_k<<<(DHH*EE)/1024, 256>>>(fc2_w, f2h, f2l, DHH*EE);

    // 1) LN -> bf16 hi/lo
    ln_kernel<<<MM/8, 256>>>(x, ln_attn_g, ln_attn_b, h1h, h1l);

    // 2) QKV projections (tensor core) with fused RoPE / scale / split
    const float qscale = 0.08838834764831845f;  // 1/sqrt(128)
    dim3 gq(HD/128, MM/128);
    cudaFuncSetAttribute(mm3<1,false,false>, cudaFuncAttributeMaxDynamicSharedMemorySize, MM3_SMEM);
    cudaFuncSetAttribute(mm3<2,false,false>, cudaFuncAttributeMaxDynamicSharedMemorySize, MM3_SMEM);
    cudaFuncSetAttribute(mm3<3,true,true>,   cudaFuncAttributeMaxDynamicSharedMemorySize, MM3_SMEM);
    cudaFuncSetAttribute(mm3<4,false,false>, cudaFuncAttributeMaxDynamicSharedMemorySize, MM3_SMEM);
    cudaFuncSetAttribute(mm3<5,false,true>,  cudaFuncAttributeMaxDynamicSharedMemorySize, MM3_SMEM);
    mm3<1,false,false><<<gq, 256, MM3_SMEM>>>(h1h, h1l, wqh, wql, nullptr, nullptr, nullptr, qhi, qlo, MM, HD, EE, qscale);
    mm3<1,false,false><<<gq, 256, MM3_SMEM>>>(h1h, h1l, wkh, wkl, nullptr, nullptr, nullptr, khi, klo, MM, HD, EE, 1.0f);
    mm3<2,false,false><<<gq, 256, MM3_SMEM>>>(h1h, h1l, wvh, wvl, nullptr, nullptr, nullptr, vhi, vlo, MM, HD, EE, 1.0f);

    // 3) causal flash attention (tensor core, cp.async double-buffered)
    cudaFuncSetAttribute(fa_mma, cudaFuncAttributeMaxDynamicSharedMemorySize, FA_SMEM);
    fa_mma<<<dim3(SS/128, BB*HH), 256, FA_SMEM>>>(qhi, qlo, khi, klo, vhi, vlo, aoh, aol);

    // 4) O-projection + residual (tensor core, A gathered from (B,H,S,D))
    mm3<3,true,true><<<dim3(1, MM/64), 256, MM3_SMEM>>>(aoh, aol, woh, wol, nullptr, x, x2, nullptr, nullptr, MM, EE, HD, 1.0f);

    // 5) LN -> bf16 hi/lo
    ln_kernel<<<MM/8, 256>>>(x2, ln_mlp_g, ln_mlp_b, h2h, h2l);

    // 6) MLP (tensor core)
    mm3<4,false,false><<<dim3(DHH/128, MM/128), 256, MM3_SMEM>>>(h2h, h2l, f1h, f1l, fc1_b, nullptr, nullptr, th, tl, MM, DHH, EE, 1.0f);
    mm3<5,false,true><<<dim3(1, MM/64), 256, MM3_SMEM>>>(th, tl, f2h, f2l, fc2_b, x2, out, nullptr, nullptr, MM, EE, DHH, 1.0f);
}

// round 9
// speedup vs baseline: 2.7151x; 1.1479x over previous
#include <cuda_runtime.h>
#include <cuda_bf16.h>
#include <math.h>
#include <stdint.h>

#define BB 2
#define SS 2048
#define EE 128
#define HH 16
#define DD 128
#define DHH 512
#define MM (BB*SS)     // 4096 rows
#define HD (HH*DD)     // 2048

// ---------------- scratch (static __device__, no allocation) ----------------
__device__ float g_x2[MM*EE];
__device__ float g_part[4*MM*EE];
__device__ __nv_bfloat16 g_h1h[MM*EE],  g_h1l[MM*EE];
__device__ __nv_bfloat16 g_h2h[MM*EE],  g_h2l[MM*EE];
__device__ __nv_bfloat16 g_th [MM*DHH], g_tl [MM*DHH];
__device__ __nv_bfloat16 g_aoh[MM*HD],  g_aol[MM*HD];
__device__ __nv_bfloat16 g_qhi[MM*HD],  g_qlo[MM*HD];
__device__ __nv_bfloat16 g_khi[MM*HD],  g_klo[MM*HD];
__device__ __nv_bfloat16 g_vhi[MM*HD],  g_vlo[MM*HD];
__device__ __nv_bfloat16 g_wqh[EE*HD],  g_wql[EE*HD];
__device__ __nv_bfloat16 g_wkh[EE*HD],  g_wkl[EE*HD];
__device__ __nv_bfloat16 g_wvh[EE*HD],  g_wvl[EE*HD];
__device__ __nv_bfloat16 g_woh[HD*EE],  g_wol[HD*EE];
__device__ __nv_bfloat16 g_f1h[EE*DHH], g_f1l[EE*DHH];
__device__ __nv_bfloat16 g_f2h[DHH*EE], g_f2l[DHH*EE];

// ======================= warp MMA helpers (baseline PTX) =====================
__device__ __forceinline__ uint32_t smem_u32(const void* p) {
    uint32_t a;
    asm("{ .reg .u64 t; cvta.to.shared.u64 t, %1; cvt.u32.u64 %0, t; }"
        : "=r"(a) : "l"(p));
    return a;
}
__device__ __forceinline__ void mma16816(float* c, const uint32_t* a, const uint32_t* b) {
    asm volatile(
        "mma.sync.aligned.m16n8k16.row.col.f32.bf16.bf16.f32 "
        "{%0,%1,%2,%3}, {%4,%5,%6,%7}, {%8,%9}, {%0,%1,%2,%3};"
        : "+f"(c[0]), "+f"(c[1]), "+f"(c[2]), "+f"(c[3])
        : "r"(a[0]), "r"(a[1]), "r"(a[2]), "r"(a[3]), "r"(b[0]), "r"(b[1]));
}
__device__ __forceinline__ void ldsm_x4(uint32_t* r, uint32_t addr) {
    asm volatile("ldmatrix.sync.aligned.m8n8.x4.shared.b16 {%0,%1,%2,%3}, [%4];"
        : "=r"(r[0]), "=r"(r[1]), "=r"(r[2]), "=r"(r[3]) : "r"(addr));
}
__device__ __forceinline__ void ldsm_x4_t(uint32_t* r, uint32_t addr) {
    asm volatile("ldmatrix.sync.aligned.m8n8.x4.trans.shared.b16 {%0,%1,%2,%3}, [%4];"
        : "=r"(r[0]), "=r"(r[1]), "=r"(r[2]), "=r"(r[3]) : "r"(addr));
}
__device__ __forceinline__ uint32_t pack_bf2(float a, float b) {
    __nv_bfloat162 h = __halves2bfloat162(__float2bfloat16(a), __float2bfloat16(b));
    return *(uint32_t*)&h;
}
__device__ __forceinline__ void cp16(uint32_t smem_addr, const void* gptr) {
    asm volatile("cp.async.cg.shared.global [%0], [%1], 16;"
        :: "r"(smem_addr), "l"(gptr) : "memory");
}
#define CP_COMMIT() asm volatile("cp.async.commit_group;" ::: "memory")
#define CP_WAIT(n)  asm volatile("cp.async.wait_group %0;" :: "n"(n) : "memory")

// 256B-row swizzle (B tiles, FA tiles); 128B-row swizzle (A tiles)
__device__ __forceinline__ uint32_t boff(int r, int cbyte) {
    return (uint32_t)(r * 256 + (cbyte ^ ((r & 7) << 4)));
}
__device__ __forceinline__ uint32_t aoff(int r, int cbyte) {
    return (uint32_t)(r * 128 + (cbyte ^ ((r & 7) << 4)));
}

// ---------------- fp32 -> bf16 hi/lo split: all six weights in ONE launch ----
// segments: w0..w3 = 262144 elems (256 blocks each), w4..w5 = 65536 (64 blocks)
__global__ void split6(const float* __restrict__ a0, const float* __restrict__ a1,
                       const float* __restrict__ a2, const float* __restrict__ a3,
                       const float* __restrict__ a4, const float* __restrict__ a5,
                       __nv_bfloat16* h0, __nv_bfloat16* l0,
                       __nv_bfloat16* h1, __nv_bfloat16* l1,
                       __nv_bfloat16* h2, __nv_bfloat16* l2,
                       __nv_bfloat16* h3, __nv_bfloat16* l3,
                       __nv_bfloat16* h4, __nv_bfloat16* l4,
                       __nv_bfloat16* h5, __nv_bfloat16* l5) {
    const float* ws[6] = {a0, a1, a2, a3, a4, a5};
    __nv_bfloat16* hs[6] = {h0, h1, h2, h3, h4, h5};
    __nv_bfloat16* ls[6] = {l0, l1, l2, l3, l4, l5};
    int b = blockIdx.x, wi, off;
    if (b < 1024) { wi = b >> 8;       off = (b & 255) * 1024; }
    else          { b -= 1024; wi = 4 + (b >> 6); off = (b & 63) * 1024; }
    int i = off + threadIdx.x * 4;
    float4 v = *(const float4*)(ws[wi] + i);
    __nv_bfloat16 b0 = __float2bfloat16(v.x), b1 = __float2bfloat16(v.y);
    __nv_bfloat16 b2 = __float2bfloat16(v.z), b3 = __float2bfloat16(v.w);
    __nv_bfloat162 hh01 = __halves2bfloat162(b0, b1), hh23 = __halves2bfloat162(b2, b3);
    *(uint2*)(hs[wi] + i) = make_uint2(*(uint32_t*)&hh01, *(uint32_t*)&hh23);
    uint32_t l01 = pack_bf2(v.x - __bfloat162float(b0), v.y - __bfloat162float(b1));
    uint32_t l23 = pack_bf2(v.z - __bfloat162float(b2), v.w - __bfloat162float(b3));
    *(uint2*)(ls[wi] + i) = make_uint2(l01, l23);
}

// ---------------- split-K reduce: out = resid (+bias) + sum partials --------
template<int NS, bool BIAS>
__global__ void reduce_k(const float* __restrict__ part, const float* __restrict__ resid,
                         const float* __restrict__ bias, float* __restrict__ out) {
    int i = (blockIdx.x * 256 + threadIdx.x) * 4;
    float4 acc = *(const float4*)(resid + i);
    if (BIAS) {
        float4 bv = *(const float4*)(bias + (i & (EE - 1)));
        acc.x += bv.x; acc.y += bv.y; acc.z += bv.z; acc.w += bv.w;
    }
    #pragma unroll
    for (int z = 0; z < NS; z++) {
        float4 p = *(const float4*)(part + (size_t)z * (MM * EE) + i);
        acc.x += p.x; acc.y += p.y; acc.z += p.z; acc.w += p.w;
    }
    *(float4*)(out + i) = acc;
}

// ---------------- LayerNorm: one warp per row, bf16 hi/lo out ---------------
__global__ void ln_kernel(const float* __restrict__ x, const float* __restrict__ g,
                          const float* __restrict__ b,
                          __nv_bfloat16* __restrict__ ohi, __nv_bfloat16* __restrict__ olo) {
    int warp = threadIdx.x >> 5, lane = threadIdx.x & 31;
    int row = blockIdx.x * 8 + warp;
    float4 v = ((const float4*)(x + (size_t)row * EE))[lane];
    float s = v.x + v.y + v.z + v.w;
    #pragma unroll
    for (int o = 16; o; o >>= 1) s += __shfl_xor_sync(0xffffffffu, s, o);
    float mu = s * (1.0f / EE);
    float d0 = v.x - mu, d1 = v.y - mu, d2 = v.z - mu, d3 = v.w - mu;
    float q = d0*d0 + d1*d1 + d2*d2 + d3*d3;
    #pragma unroll
    for (int o = 16; o; o >>= 1) q += __shfl_xor_sync(0xffffffffu, q, o);
    float inv = rsqrtf(q * (1.0f / EE) + 1e-5f);
    float4 gg = ((const float4*)g)[lane];
    float4 bb = ((const float4*)b)[lane];
    float r0 = d0 * inv * gg.x + bb.x;
    float r1 = d1 * inv * gg.y + bb.y;
    float r2 = d2 * inv * gg.z + bb.z;
    float r3 = d3 * inv * gg.w + bb.w;
    __nv_bfloat16 h0 = __float2bfloat16(r0), h1 = __float2bfloat16(r1);
    __nv_bfloat16 h2 = __float2bfloat16(r2), h3 = __float2bfloat16(r3);
    __nv_bfloat162 hh01 = __halves2bfloat162(h0, h1), hh23 = __halves2bfloat162(h2, h3);
    size_t base = (size_t)row * EE + lane * 4;
    *(uint2*)(ohi + base) = make_uint2(*(uint32_t*)&hh01, *(uint32_t*)&hh23);
    uint32_t l01 = pack_bf2(r0 - __bfloat162float(h0), r1 - __bfloat162float(h1));
    uint32_t l23 = pack_bf2(r2 - __bfloat162float(h2), r3 - __bfloat162float(h3));
    *(uint2*)(olo + base) = make_uint2(l01, l23);
}

// =============== bf16x3 tensor-core GEMM with fused epilogues ================
// MODE 1: RoPE + qscale -> bf16 hi/lo at (B,H,S,D)     (Q / K)
// MODE 2: plain        -> bf16 hi/lo at (B,H,S,D)      (V)
// MODE 4: gelu(acc + bias) -> bf16 hi/lo               (fc1)
// MODE 6: split-K partial: fp32 to out + blockIdx.x*M*N, k in [bx*kspl, +kspl)
#define MM3_AHI 0u
#define MM3_ALO 16384u
#define MM3_BHI 32768u
#define MM3_BLO 49152u
#define MM3_SMEM 65536

template<int MODE, bool AG, bool HALFM>
__global__ __launch_bounds__(256)
void mm3(const __nv_bfloat16* __restrict__ Ahi, const __nv_bfloat16* __restrict__ Alo,
         const __nv_bfloat16* __restrict__ Bhi, const __nv_bfloat16* __restrict__ Blo,
         const float* __restrict__ bias, const float* __restrict__ resid,
         float* __restrict__ out,
         __nv_bfloat16* __restrict__ ohi, __nv_bfloat16* __restrict__ olo,
         int M, int N, int K, int kspl, float qscale)
{
    extern __shared__ char sm[];
    uint32_t sb = smem_u32(sm);
    constexpr int MT = HALFM ? 64 : 128;
    constexpr int NJ = HALFM ? 8 : 16;
    const int tid = threadIdx.x;
    const int w = tid >> 5, ln = tid & 31;
    const int tig = ln & 3, gid = ln >> 2;
    const int wr = HALFM ? (w & 3) : w;
    const int wc = HALFM ? (w >> 2) * 64 : 0;
    const int m0 = blockIdx.y * MT;
    const int n0 = (MODE == 6) ? 0 : blockIdx.x * 128;
    const int kb = (MODE == 6) ? blockIdx.x * kspl : 0;
    const int ke = (MODE == 6) ? kb + kspl : K;

    float C[NJ][4];
    #pragma unroll
    for (int j = 0; j < NJ; j++)
        #pragma unroll
        for (int e = 0; e < 4; e++) C[j][e] = 0.f;

    const int arow = 16 * wr + ((ln >> 3) & 1) * 8 + (ln & 7);
    const int akb  = (ln >> 4) * 16;
    const int brow = ((ln >> 3) & 1) * 8 + (ln & 7);
    const int bcb  = (ln >> 4) << 4;

    for (int k0 = kb; k0 < ke; k0 += 64) {
        for (int f = tid; f < MT * 8; f += 256) {
            int r = f >> 3, seg = f & 7;
            size_t g;
            if (!AG) {
                g = (size_t)(m0 + r) * K + k0 + seg * 8;
            } else {
                int rr = m0 + r;
                int b_ = rr >> 11, s_ = rr & 2047;
                int kk = k0 + seg * 8;
                g = ((size_t)(b_ * HH + (kk >> 7)) * SS + s_) * DD + (kk & 127);
            }
            uint32_t so = aoff(r, seg * 16);
            *(uint4*)(sm + MM3_AHI + so) = *(const uint4*)(Ahi + g);
            *(uint4*)(sm + MM3_ALO + so) = *(const uint4*)(Alo + g);
        }
        for (int f = tid; f < 1024; f += 256) {
            int r = f >> 4, seg = f & 15;
            size_t g = (size_t)(k0 + r) * N + n0 + seg * 8;
            uint32_t so = boff(r, seg * 16);
            *(uint4*)(sm + MM3_BHI + so) = *(const uint4*)(Bhi + g);
            *(uint4*)(sm + MM3_BLO + so) = *(const uint4*)(Blo + g);
        }
        __syncthreads();

        uint32_t Ah[4][4], Al[4][4];
        #pragma unroll
        for (int kk = 0; kk < 4; kk++) {
            uint32_t off = aoff(arow, kk * 32 + akb);
            ldsm_x4(Ah[kk], sb + MM3_AHI + off);
            ldsm_x4(Al[kk], sb + MM3_ALO + off);
        }
        #pragma unroll
        for (int jp = 0; jp < NJ / 2; jp++) {
            int ncb = (wc + 16 * jp) * 2;
            #pragma unroll
            for (int kk = 0; kk < 4; kk++) {
                uint32_t off = boff(16 * kk + brow, ncb + bcb);
                uint32_t Bh[4], Bl[4];
                ldsm_x4_t(Bh, sb + MM3_BHI + off);
                mma16816(C[2*jp],   Ah[kk], Bh);
                mma16816(C[2*jp+1], Ah[kk], Bh + 2);
                mma16816(C[2*jp],   Al[kk], Bh);
                mma16816(C[2*jp+1], Al[kk], Bh + 2);
                ldsm_x4_t(Bl, sb + MM3_BLO + off);
                mma16816(C[2*jp],   Ah[kk], Bl);
                mma16816(C[2*jp+1], Ah[kk], Bl + 2);
            }
        }
        __syncthreads();
    }

    const int r0 = m0 + 16 * wr + gid;
    const int r1 = r0 + 8;
    if (MODE == 1 || MODE == 2) {
        int b_ = r0 >> 11, s0 = r0 & 2047, s1 = r1 & 2047;
        #pragma unroll
        for (int j = 0; j < NJ; j++) {
            int colg = n0 + wc + 8 * j + 2 * tig;
            int h = colg >> 7, d = colg & 127;
            float o00 = C[j][0] * qscale, o01 = C[j][1] * qscale;
            float o10 = C[j][2] * qscale, o11 = C[j][3] * qscale;
            if (MODE == 1) {
                int t2 = d >> 1;
                float f = expf((float)t2 * -0.14391157f);
                float si0, co0, si1, co1;
                sincosf((float)s0 * f, &si0, &co0);
                sincosf((float)s1 * f, &si1, &co1);
                float a = o00 * co0 - o01 * si0, b2 = o00 * si0 + o01 * co0;
                o00 = a; o01 = b2;
                a = o10 * co1 - o11 * si1; b2 = o10 * si1 + o11 * co1;
                o10 = a; o11 = b2;
            }
            size_t oi0 = (((size_t)(b_ * HH + h) * SS + s0) * DD + d);
            size_t oi1 = (((size_t)(b_ * HH + h) * SS + s1) * DD + d);
            __nv_bfloat16 h00 = __float2bfloat16(o00), h01 = __float2bfloat16(o01);
            __nv_bfloat16 h10 = __float2bfloat16(o10), h11 = __float2bfloat16(o11);
            __nv_bfloat162 p0 = __halves2bfloat162(h00, h01);
            __nv_bfloat162 p1 = __halves2bfloat162(h10, h11);
            *(uint32_t*)(ohi + oi0) = *(uint32_t*)&p0;
            *(uint32_t*)(ohi + oi1) = *(uint32_t*)&p1;
            *(uint32_t*)(olo + oi0) = pack_bf2(o00 - __bfloat162float(h00), o01 - __bfloat162float(h01));
            *(uint32_t*)(olo + oi1) = pack_bf2(o10 - __bfloat162float(h10), o11 - __bfloat162float(h11));
        }
    } else if (MODE == 6) {
        float* po = out + (size_t)blockIdx.x * M * N;
        #pragma unroll
        for (int j = 0; j < NJ; j++) {
            int colg = wc + 8 * j + 2 * tig;
            size_t i0 = (size_t)r0 * N + colg;
            size_t i1 = (size_t)r1 * N + colg;
            *(float2*)(po + i0) = make_float2(C[j][0], C[j][1]);
            *(float2*)(po + i1) = make_float2(C[j][2], C[j][3]);
        }
    } else {
        #pragma unroll
        for (int j = 0; j < NJ; j++) {
            int colg = n0 + wc + 8 * j + 2 * tig;
            size_t i0 = (size_t)r0 * N + colg;
            size_t i1 = (size_t)r1 * N + colg;
            float v00 = C[j][0], v01 = C[j][1], v10 = C[j][2], v11 = C[j][3];
            if (MODE == 4) {
                float b0 = bias[colg], b1 = bias[colg + 1];
                v00 += b0; v01 += b1; v10 += b0; v11 += b1;
                v00 = 0.5f * v00 * (1.0f + erff(v00 * 0.70710678f));
                v01 = 0.5f * v01 * (1.0f + erff(v01 * 0.70710678f));
                v10 = 0.5f * v10 * (1.0f + erff(v10 * 0.70710678f));
                v11 = 0.5f * v11 * (1.0f + erff(v11 * 0.70710678f));
                __nv_bfloat16 h00 = __float2bfloat16(v00), h01 = __float2bfloat16(v01);
                __nv_bfloat16 h10 = __float2bfloat16(v10), h11 = __float2bfloat16(v11);
                __nv_bfloat162 p0 = __halves2bfloat162(h00, h01);
                __nv_bfloat162 p1 = __halves2bfloat162(h10, h11);
                *(uint32_t*)(ohi + i0) = *(uint32_t*)&p0;
                *(uint32_t*)(ohi + i1) = *(uint32_t*)&p1;
                *(uint32_t*)(olo + i0) = pack_bf2(v00 - __bfloat162float(h00), v01 - __bfloat162float(h01));
                *(uint32_t*)(olo + i1) = pack_bf2(v10 - __bfloat162float(h10), v11 - __bfloat162float(h11));
            }
        }
    }
}

// ============== mma.sync flash attention (bf16x3, cp.async double-buffer) ===
#define KHI_OFF 0u
#define KLO_OFF 16384u
#define VHI_OFF 32768u
#define VLO_OFF 49152u
#define FA_STAGE 65536u
#define FA_SMEM 131072

__device__ __forceinline__ uint32_t fa_off(int r, int cbyte) {
    return (uint32_t)(r * 256 + (cbyte ^ ((r & 7) << 4)));
}

__global__ __launch_bounds__(256, 1)
void fa_mma(const __nv_bfloat16* __restrict__ qhi, const __nv_bfloat16* __restrict__ qlo,
            const __nv_bfloat16* __restrict__ khi, const __nv_bfloat16* __restrict__ klo,
            const __nv_bfloat16* __restrict__ vhi, const __nv_bfloat16* __restrict__ vlo,
            __nv_bfloat16* __restrict__ Ohi, __nv_bfloat16* __restrict__ Olo)
{
    extern __shared__ char sm[];
    uint32_t sb = smem_u32(sm);
    const int tid = threadIdx.x;
    const int w = tid >> 5, ln = tid & 31;
    const int tig = ln & 3, gid = ln >> 2;
    const int m0 = (gridDim.x - 1 - blockIdx.x) * 128;   // big tiles first
    const int bh = blockIdx.y;
    const size_t base = (size_t)bh * SS * DD;

    // ---- stage Q tile through smem (regions overwritten later by K/V) ----
    for (int f = tid; f < 2048; f += 256) {
        int r = f >> 4, c16 = f & 15;
        size_t g = base + (size_t)(m0 + r) * DD + c16 * 8;
        uint32_t so = fa_off(r, c16 * 16);
        *(uint4*)(sm + so)              = *(const uint4*)(qhi + g);
        *(uint4*)(sm + FA_STAGE + so)   = *(const uint4*)(qlo + g);
    }
    __syncthreads();
    uint32_t Qh[8][4], Ql[8][4];
    {
        int row = 16 * w + ((ln >> 3) & 1) * 8 + (ln & 7);
        int kb0 = (ln >> 4) * 16;
        #pragma unroll
        for (int kk = 0; kk < 8; kk++) {
            uint32_t off = fa_off(row, kk * 32 + kb0);
            ldsm_x4(Qh[kk], sb + off);
            ldsm_x4(Ql[kk], sb + FA_STAGE + off);
        }
    }
    __syncthreads();

    float Oa[16][4];
    #pragma unroll
    for (int j = 0; j < 16; j++)
        #pragma unroll
        for (int e = 0; e < 4; e++) Oa[j][e] = 0.f;
    float m0r = -1e30f, m1r = -1e30f, l0r = 0.f, l1r = 0.f;

    const int grow0 = m0 + 16 * w + gid;
    const int grow1 = grow0 + 8;
    const int nk = m0 / 64 + 2;

    // ---- prologue: prefetch tile 0 into stage 0 ----
    {
        for (int f = tid; f < 1024; f += 256) {
            int r = f >> 4, c16 = f & 15;
            size_t g = base + (size_t)r * DD + c16 * 8;
            uint32_t so = fa_off(r, c16 * 16);
            cp16(sb + KHI_OFF + so, khi + g);
            cp16(sb + KLO_OFF + so, klo + g);
            cp16(sb + VHI_OFF + so, vhi + g);
            cp16(sb + VLO_OFF + so, vlo + g);
        }
        CP_COMMIT();
    }

    for (int t = 0; t < nk; t++) {
        int n0 = t * 64;
        uint32_t st = (uint32_t)(t & 1) * FA_STAGE;
        __syncthreads();   // everyone done with the stage we're about to overwrite
        if (t + 1 < nk) {
            uint32_t stn = (uint32_t)((t + 1) & 1) * FA_STAGE;
            int n1 = n0 + 64;
            for (int f = tid; f < 1024; f += 256) {
                int r = f >> 4, c16 = f & 15;
                size_t g = base + (size_t)(n1 + r) * DD + c16 * 8;
                uint32_t so = fa_off(r, c16 * 16);
                cp16(sb + stn + KHI_OFF + so, khi + g);
                cp16(sb + stn + KLO_OFF + so, klo + g);
                cp16(sb + stn + VHI_OFF + so, vhi + g);
                cp16(sb + stn + VLO_OFF + so, vlo + g);
            }
            CP_COMMIT();
            CP_WAIT(1);
        } else {
            CP_WAIT(0);
        }
        __syncthreads();   // current stage data visible to all

        // ---- S = Q K^T (3-term) ----
        float S[8][4];
        #pragma unroll
        for (int j = 0; j < 8; j++)
            #pragma unroll
            for (int e = 0; e < 4; e++) S[j][e] = 0.f;
        {
            int brow = ((ln >> 4) << 3) + (ln & 7);
            int bkb  = ((ln >> 3) & 1) << 4;
            #pragma unroll
            for (int jp = 0; jp < 4; jp++) {
                #pragma unroll
                for (int kk = 0; kk < 8; kk++) {
                    int r_ = 16 * jp + brow;
                    uint32_t off = fa_off(r_, kk * 32 + bkb);
                    uint32_t Bh[4], Bl[4];
                    ldsm_x4(Bh, sb + st + KHI_OFF + off);
                    mma16816(S[2*jp],   Qh[kk], Bh);
                    mma16816(S[2*jp+1], Qh[kk], Bh + 2);
                    mma16816(S[2*jp],   Ql[kk], Bh);
                    mma16816(S[2*jp+1], Ql[kk], Bh + 2);
                    ldsm_x4(Bl, sb + st + KLO_OFF + off);
                    mma16816(S[2*jp],   Qh[kk], Bl);
                    mma16816(S[2*jp+1], Qh[kk], Bl + 2);
                }
            }
        }

        // ---- causal mask (only near-diagonal tiles) ----
        if (n0 + 63 > m0 + 16 * w) {
            #pragma unroll
            for (int j = 0; j < 8; j++) {
                int c = n0 + 8 * j + 2 * tig;
                if (c     > grow0) S[j][0] = -1e30f;
                if (c + 1 > grow0) S[j][1] = -1e30f;
                if (c     > grow1) S[j][2] = -1e30f;
                if (c + 1 > grow1) S[j][3] = -1e30f;
            }
        }

        // ---- online softmax ----
        float mx0 = -1e30f, mx1 = -1e30f;
        #pragma unroll
        for (int j = 0; j < 8; j++) {
            mx0 = fmaxf(mx0, fmaxf(S[j][0], S[j][1]));
            mx1 = fmaxf(mx1, fmaxf(S[j][2], S[j][3]));
        }
        mx0 = fmaxf(mx0, __shfl_xor_sync(0xffffffffu, mx0, 1));
        mx0 = fmaxf(mx0, __shfl_xor_sync(0xffffffffu, mx0, 2));
        mx1 = fmaxf(mx1, __shfl_xor_sync(0xffffffffu, mx1, 1));
        mx1 = fmaxf(mx1, __shfl_xor_sync(0xffffffffu, mx1, 2));
        float mn0 = fmaxf(m0r, mx0), mn1 = fmaxf(m1r, mx1);
        bool nochg = (mn0 == m0r) && (mn1 == m1r);
        float a0 = nochg ? 1.f : __expf(m0r - mn0);
        float a1 = nochg ? 1.f : __expf(m1r - mn1);
        m0r = mn0; m1r = mn1;
        l0r *= a0; l1r *= a1;

        uint32_t Phi[4][4], Plo[4][4];
        float ls0 = 0.f, ls1 = 0.f;
        #pragma unroll
        for (int j = 0; j < 8; j++) {
            float p0 = __expf(S[j][0] - mn0);
            float p1 = __expf(S[j][1] - mn0);
            float p2 = __expf(S[j][2] - mn1);
            float p3 = __expf(S[j][3] - mn1);
            ls0 += p0 + p1; ls1 += p2 + p3;
            __nv_bfloat16 h0 = __float2bfloat16(p0);
            __nv_bfloat16 h1 = __float2bfloat16(p1);
            __nv_bfloat16 h2 = __float2bfloat16(p2);
            __nv_bfloat16 h3 = __float2bfloat16(p3);
            int kk = j >> 1, q = (j & 1) * 2;
            __nv_bfloat162 hh01 = __halves2bfloat162(h0, h1);
            __nv_bfloat162 hh23 = __halves2bfloat162(h2, h3);
            Phi[kk][q]     = *(uint32_t*)&hh01;
            Phi[kk][q + 1] = *(uint32_t*)&hh23;
            Plo[kk][q]     = pack_bf2(p0 - __bfloat162float(h0), p1 - __bfloat162float(h1));
            Plo[kk][q + 1] = pack_bf2(p2 - __bfloat162float(h2), p3 - __bfloat162float(h3));
        }
        l0r += ls0; l1r += ls1;

        if (!__all_sync(0xffffffffu, nochg)) {
            #pragma unroll
            for (int j = 0; j < 16; j++) {
                Oa[j][0] *= a0; Oa[j][1] *= a0;
                Oa[j][2] *= a1; Oa[j][3] *= a1;
            }
        }

        // ---- O += P V (3-term) ----
        {
            int vrow = ((ln >> 3) & 1) * 8 + (ln & 7);
            int vcb  = (ln >> 4) << 4;
            #pragma unroll
            for (int jp = 0; jp < 8; jp++) {
                #pragma unroll
                for (int kk = 0; kk < 4; kk++) {
                    int r_ = 16 * kk + vrow;
                    uint32_t off = fa_off(r_, 32 * jp + vcb);
                    uint32_t Bh[4], Bl[4];
                    ldsm_x4_t(Bh, sb + st + VHI_OFF + off);
                    mma16816(Oa[2*jp],   Phi[kk], Bh);
                    mma16816(Oa[2*jp+1], Phi[kk], Bh + 2);
                    mma16816(Oa[2*jp],   Plo[kk], Bh);
                    mma16816(Oa[2*jp+1], Plo[kk], Bh + 2);
                    ldsm_x4_t(Bl, sb + st + VLO_OFF + off);
                    mma16816(Oa[2*jp],   Phi[kk], Bl);
                    mma16816(Oa[2*jp+1], Phi[kk], Bl + 2);
                }
            }
        }
    }

    // ---- finalize: reduce l, normalize, split hi/lo, store ----
    l0r += __shfl_xor_sync(0xffffffffu, l0r, 1);
    l0r += __shfl_xor_sync(0xffffffffu, l0r, 2);
    l1r += __shfl_xor_sync(0xffffffffu, l1r, 1);
    l1r += __shfl_xor_sync(0xffffffffu, l1r, 2);
    float inv0 = 1.0f / l0r, inv1 = 1.0f / l1r;
    #pragma unroll
    for (int j = 0; j < 16; j++) {
        int col = 8 * j + 2 * tig;
        size_t i0 = base + (size_t)grow0 * DD + col;
        size_t i1 = base + (size_t)grow1 * DD + col;
        float v00 = Oa[j][0] * inv0, v01 = Oa[j][1] * inv0;
        float v10 = Oa[j][2] * inv1, v11 = Oa[j][3] * inv1;
        __nv_bfloat16 h00 = __float2bfloat16(v00), h01 = __float2bfloat16(v01);
        __nv_bfloat16 h10 = __float2bfloat16(v10), h11 = __float2bfloat16(v11);
        __nv_bfloat162 p0 = __halves2bfloat162(h00, h01);
        __nv_bfloat162 p1 = __halves2bfloat162(h10, h11);
        *(uint32_t*)(Ohi + i0) = *(uint32_t*)&p0;
        *(uint32_t*)(Ohi + i1) = *(uint32_t*)&p1;
        *(uint32_t*)(Olo + i0) = pack_bf2(v00 - __bfloat162float(h00), v01 - __bfloat162float(h01));
        *(uint32_t*)(Olo + i1) = pack_bf2(v10 - __bfloat162float(h10), v11 - __bfloat162float(h11));
    }
}

// ---------------- launch -----------------------------------------------------
extern "C" void kernel_launch(void* const* d_in, const int* in_sizes, int n_in,
                              void* d_out, int out_size) {
    const float* x        = (const float*)d_in[0];
    const float* W_q      = (const float*)d_in[1];
    const float* W_k      = (const float*)d_in[2];
    const float* W_v      = (const float*)d_in[3];
    const float* W_o      = (const float*)d_in[4];
    const float* ln_attn_g= (const float*)d_in[5];
    const float* ln_attn_b= (const float*)d_in[6];
    const float* fc1_w    = (const float*)d_in[7];
    const float* fc1_b    = (const float*)d_in[8];
    const float* fc2_w    = (const float*)d_in[9];
    const float* fc2_b    = (const float*)d_in[10];
    const float* ln_mlp_g = (const float*)d_in[11];
    const float* ln_mlp_b = (const float*)d_in[12];
    float* out = (float*)d_out;

    float *x2, *part;
    __nv_bfloat16 *h1h, *h1l, *h2h, *h2l, *th, *tl, *aoh, *aol;
    __nv_bfloat16 *qhi, *qlo, *khi, *klo, *vhi, *vlo;
    __nv_bfloat16 *wqh, *wql, *wkh, *wkl, *wvh, *wvl, *woh, *wol, *f1h, *f1l, *f2h, *f2l;
    cudaGetSymbolAddress((void**)&x2,  g_x2);
    cudaGetSymbolAddress((void**)&part, g_part);
    cudaGetSymbolAddress((void**)&h1h, g_h1h); cudaGetSymbolAddress((void**)&h1l, g_h1l);
    cudaGetSymbolAddress((void**)&h2h, g_h2h); cudaGetSymbolAddress((void**)&h2l, g_h2l);
    cudaGetSymbolAddress((void**)&th,  g_th);  cudaGetSymbolAddress((void**)&tl,  g_tl);
    cudaGetSymbolAddress((void**)&aoh, g_aoh); cudaGetSymbolAddress((void**)&aol, g_aol);
    cudaGetSymbolAddress((void**)&qhi, g_qhi); cudaGetSymbolAddress((void**)&qlo, g_qlo);
    cudaGetSymbolAddress((void**)&khi, g_khi); cudaGetSymbolAddress((void**)&klo, g_klo);
    cudaGetSymbolAddress((void**)&vhi, g_vhi); cudaGetSymbolAddress((void**)&vlo, g_vlo);
    cudaGetSymbolAddress((void**)&wqh, g_wqh); cudaGetSymbolAddress((void**)&wql, g_wql);
    cudaGetSymbolAddress((void**)&wkh, g_wkh); cudaGetSymbolAddress((void**)&wkl, g_wkl);
    cudaGetSymbolAddress((void**)&wvh, g_wvh); cudaGetSymbolAddress((void**)&wvl, g_wvl);
    cudaGetSymbolAddress((void**)&woh, g_woh); cudaGetSymbolAddress((void**)&wol, g_wol);
    cudaGetSymbolAddress((void**)&f1h, g_f1h); cudaGetSymbolAddress((void**)&f1l, g_f1l);
    cudaGetSymbolAddress((void**)&f2h, g_f2h); cudaGetSymbolAddress((void**)&f2l, g_f2l);

    // 0) split all six weights to bf16 hi/lo in one launch
    split6<<<1152, 256>>>(W_q, W_k, W_v, W_o, fc1_w, fc2_w,
                          wqh, wql, wkh, wkl, wvh, wvl,
                          woh, wol, f1h, f1l, f2h, f2l);

    // 1) LN -> bf16 hi/lo
    ln_kernel<<<MM/8, 256>>>(x, ln_attn_g, ln_attn_b, h1h, h1l);

    // 2) QKV projections (tensor core) with fused RoPE / scale / split
    const float qscale = 0.08838834764831845f;  // 1/sqrt(128)
    dim3 gq(HD/128, MM/128);
    cudaFuncSetAttribute(mm3<1,false,false>, cudaFuncAttributeMaxDynamicSharedMemorySize, MM3_SMEM);
    cudaFuncSetAttribute(mm3<2,false,false>, cudaFuncAttributeMaxDynamicSharedMemorySize, MM3_SMEM);
    cudaFuncSetAttribute(mm3<4,false,false>, cudaFuncAttributeMaxDynamicSharedMemorySize, MM3_SMEM);
    cudaFuncSetAttribute(mm3<6,true,true>,   cudaFuncAttributeMaxDynamicSharedMemorySize, MM3_SMEM);
    cudaFuncSetAttribute(mm3<6,false,true>,  cudaFuncAttributeMaxDynamicSharedMemorySize, MM3_SMEM);
    mm3<1,false,false><<<gq, 256, MM3_SMEM>>>(h1h, h1l, wqh, wql, nullptr, nullptr, nullptr, qhi, qlo, MM, HD, EE, EE, qscale);
    mm3<1,false,false><<<gq, 256, MM3_SMEM>>>(h1h, h1l, wkh, wkl, nullptr, nullptr, nullptr, khi, klo, MM, HD, EE, EE, 1.0f);
    mm3<2,false,false><<<gq, 256, MM3_SMEM>>>(h1h, h1l, wvh, wvl, nullptr, nullptr, nullptr, vhi, vlo, MM, HD, EE, EE, 1.0f);

    // 3) causal flash attention (tensor core, cp.async double-buffered)
    cudaFuncSetAttribute(fa_mma, cudaFuncAttributeMaxDynamicSharedMemorySize, FA_SMEM);
    fa_mma<<<dim3(SS/128, BB*HH), 256, FA_SMEM>>>(qhi, qlo, khi, klo, vhi, vlo, aoh, aol);

    // 4) O-projection via split-K (4 x 512), then reduce with residual
    mm3<6,true,true><<<dim3(4, MM/64), 256, MM3_SMEM>>>(aoh, aol, woh, wol, nullptr, nullptr, part, nullptr, nullptr, MM, EE, HD, 512, 1.0f);
    reduce_k<4,false><<<(MM*EE)/1024, 256>>>(part, x, nullptr, x2);

    // 5) LN -> bf16 hi/lo
    ln_kernel<<<MM/8, 256>>>(x2, ln_mlp_g, ln_mlp_b, h2h, h2l);

    // 6) MLP: fc1 (tensor core, fused bias+GELU+split), fc2 via split-K (2 x 256)
    mm3<4,false,false><<<dim3(DHH/128, MM/128), 256, MM3_SMEM>>>(h2h, h2l, f1h, f1l, fc1_b, nullptr, nullptr, th, tl, MM, DHH, EE, EE, 1.0f);
    mm3<6,false,true><<<dim3(2, MM/64), 256, MM3_SMEM>>>(th, tl, f2h, f2l, nullptr, nullptr, part, nullptr, nullptr, MM, EE, DHH, 256, 1.0f);
    reduce_k<2,true><<<(MM*EE)/1024, 256>>>(part, x2, fc2_b, out);
}

// round 10
// speedup vs baseline: 3.1840x; 1.1727x over previous
#include <cuda_runtime.h>
#include <cuda_bf16.h>
#include <math.h>
#include <stdint.h>

#define BB 2
#define SS 2048
#define EE 128
#define HH 16
#define DD 128
#define DHH 512
#define MM (BB*SS)     // 4096 rows
#define HD (HH*DD)     // 2048

// ---------------- scratch (static __device__, no allocation) ----------------
__device__ float g_x2[MM*EE];
__device__ float g_part[4*MM*EE];
__device__ __nv_bfloat16 g_h1h[MM*EE],  g_h1l[MM*EE];
__device__ __nv_bfloat16 g_h2h[MM*EE],  g_h2l[MM*EE];
__device__ __nv_bfloat16 g_th [MM*DHH], g_tl [MM*DHH];
__device__ __nv_bfloat16 g_aoh[MM*HD],  g_aol[MM*HD];
__device__ __nv_bfloat16 g_qhi[MM*HD],  g_qlo[MM*HD];
__device__ __nv_bfloat16 g_khi[MM*HD],  g_klo[MM*HD];
__device__ __nv_bfloat16 g_vhi[MM*HD],  g_vlo[MM*HD];
__device__ __nv_bfloat16 g_wqh[EE*HD],  g_wql[EE*HD];
__device__ __nv_bfloat16 g_wkh[EE*HD],  g_wkl[EE*HD];
__device__ __nv_bfloat16 g_wvh[EE*HD],  g_wvl[EE*HD];
__device__ __nv_bfloat16 g_woh[HD*EE],  g_wol[HD*EE];
__device__ __nv_bfloat16 g_f1h[EE*DHH], g_f1l[EE*DHH];
__device__ __nv_bfloat16 g_f2h[DHH*EE], g_f2l[DHH*EE];

// ======================= warp MMA helpers (baseline PTX) =====================
__device__ __forceinline__ uint32_t smem_u32(const void* p) {
    uint32_t a;
    asm("{ .reg .u64 t; cvta.to.shared.u64 t, %1; cvt.u32.u64 %0, t; }"
        : "=r"(a) : "l"(p));
    return a;
}
__device__ __forceinline__ void mma16816(float* c, const uint32_t* a, const uint32_t* b) {
    asm volatile(
        "mma.sync.aligned.m16n8k16.row.col.f32.bf16.bf16.f32 "
        "{%0,%1,%2,%3}, {%4,%5,%6,%7}, {%8,%9}, {%0,%1,%2,%3};"
        : "+f"(c[0]), "+f"(c[1]), "+f"(c[2]), "+f"(c[3])
        : "r"(a[0]), "r"(a[1]), "r"(a[2]), "r"(a[3]), "r"(b[0]), "r"(b[1]));
}
__device__ __forceinline__ void ldsm_x4(uint32_t* r, uint32_t addr) {
    asm volatile("ldmatrix.sync.aligned.m8n8.x4.shared.b16 {%0,%1,%2,%3}, [%4];"
        : "=r"(r[0]), "=r"(r[1]), "=r"(r[2]), "=r"(r[3]) : "r"(addr));
}
__device__ __forceinline__ void ldsm_x4_t(uint32_t* r, uint32_t addr) {
    asm volatile("ldmatrix.sync.aligned.m8n8.x4.trans.shared.b16 {%0,%1,%2,%3}, [%4];"
        : "=r"(r[0]), "=r"(r[1]), "=r"(r[2]), "=r"(r[3]) : "r"(addr));
}
__device__ __forceinline__ uint32_t pack_bf2(float a, float b) {
    __nv_bfloat162 h = __halves2bfloat162(__float2bfloat16(a), __float2bfloat16(b));
    return *(uint32_t*)&h;
}
__device__ __forceinline__ void cp16(uint32_t smem_addr, const void* gptr) {
    asm volatile("cp.async.cg.shared.global [%0], [%1], 16;"
        :: "r"(smem_addr), "l"(gptr) : "memory");
}
#define CP_COMMIT() asm volatile("cp.async.commit_group;" ::: "memory")
#define CP_WAIT(n)  asm volatile("cp.async.wait_group %0;" :: "n"(n) : "memory")

// 256B-row swizzle (B tiles, FA tiles); 128B-row swizzle (A tiles)
__device__ __forceinline__ uint32_t boff(int r, int cbyte) {
    return (uint32_t)(r * 256 + (cbyte ^ ((r & 7) << 4)));
}
__device__ __forceinline__ uint32_t aoff(int r, int cbyte) {
    return (uint32_t)(r * 128 + (cbyte ^ ((r & 7) << 4)));
}

// ---------------- fp32 -> bf16 hi/lo split: all six weights in ONE launch ----
__global__ void split6(const float* __restrict__ a0, const float* __restrict__ a1,
                       const float* __restrict__ a2, const float* __restrict__ a3,
                       const float* __restrict__ a4, const float* __restrict__ a5,
                       __nv_bfloat16* h0, __nv_bfloat16* l0,
                       __nv_bfloat16* h1, __nv_bfloat16* l1,
                       __nv_bfloat16* h2, __nv_bfloat16* l2,
                       __nv_bfloat16* h3, __nv_bfloat16* l3,
                       __nv_bfloat16* h4, __nv_bfloat16* l4,
                       __nv_bfloat16* h5, __nv_bfloat16* l5) {
    const float* ws[6] = {a0, a1, a2, a3, a4, a5};
    __nv_bfloat16* hs[6] = {h0, h1, h2, h3, h4, h5};
    __nv_bfloat16* ls[6] = {l0, l1, l2, l3, l4, l5};
    int b = blockIdx.x, wi, off;
    if (b < 1024) { wi = b >> 8;       off = (b & 255) * 1024; }
    else          { b -= 1024; wi = 4 + (b >> 6); off = (b & 63) * 1024; }
    int i = off + threadIdx.x * 4;
    float4 v = *(const float4*)(ws[wi] + i);
    __nv_bfloat16 b0 = __float2bfloat16(v.x), b1 = __float2bfloat16(v.y);
    __nv_bfloat16 b2 = __float2bfloat16(v.z), b3 = __float2bfloat16(v.w);
    __nv_bfloat162 hh01 = __halves2bfloat162(b0, b1), hh23 = __halves2bfloat162(b2, b3);
    *(uint2*)(hs[wi] + i) = make_uint2(*(uint32_t*)&hh01, *(uint32_t*)&hh23);
    uint32_t l01 = pack_bf2(v.x - __bfloat162float(b0), v.y - __bfloat162float(b1));
    uint32_t l23 = pack_bf2(v.z - __bfloat162float(b2), v.w - __bfloat162float(b3));
    *(uint2*)(ls[wi] + i) = make_uint2(l01, l23);
}

// ---------------- split-K reduce: out = resid (+bias) + sum partials --------
template<int NS, bool BIAS>
__global__ void reduce_k(const float* __restrict__ part, const float* __restrict__ resid,
                         const float* __restrict__ bias, float* __restrict__ out) {
    int i = (blockIdx.x * 256 + threadIdx.x) * 4;
    float4 acc = *(const float4*)(resid + i);
    if (BIAS) {
        float4 bv = *(const float4*)(bias + (i & (EE - 1)));
        acc.x += bv.x; acc.y += bv.y; acc.z += bv.z; acc.w += bv.w;
    }
    #pragma unroll
    for (int z = 0; z < NS; z++) {
        float4 p = *(const float4*)(part + (size_t)z * (MM * EE) + i);
        acc.x += p.x; acc.y += p.y; acc.z += p.z; acc.w += p.w;
    }
    *(float4*)(out + i) = acc;
}

// ---------------- LayerNorm: one warp per row, bf16 hi/lo out ---------------
__global__ void ln_kernel(const float* __restrict__ x, const float* __restrict__ g,
                          const float* __restrict__ b,
                          __nv_bfloat16* __restrict__ ohi, __nv_bfloat16* __restrict__ olo) {
    int warp = threadIdx.x >> 5, lane = threadIdx.x & 31;
    int row = blockIdx.x * 8 + warp;
    float4 v = ((const float4*)(x + (size_t)row * EE))[lane];
    float s = v.x + v.y + v.z + v.w;
    #pragma unroll
    for (int o = 16; o; o >>= 1) s += __shfl_xor_sync(0xffffffffu, s, o);
    float mu = s * (1.0f / EE);
    float d0 = v.x - mu, d1 = v.y - mu, d2 = v.z - mu, d3 = v.w - mu;
    float q = d0*d0 + d1*d1 + d2*d2 + d3*d3;
    #pragma unroll
    for (int o = 16; o; o >>= 1) q += __shfl_xor_sync(0xffffffffu, q, o);
    float inv = rsqrtf(q * (1.0f / EE) + 1e-5f);
    float4 gg = ((const float4*)g)[lane];
    float4 bb = ((const float4*)b)[lane];
    float r0 = d0 * inv * gg.x + bb.x;
    float r1 = d1 * inv * gg.y + bb.y;
    float r2 = d2 * inv * gg.z + bb.z;
    float r3 = d3 * inv * gg.w + bb.w;
    __nv_bfloat16 h0 = __float2bfloat16(r0), h1 = __float2bfloat16(r1);
    __nv_bfloat16 h2 = __float2bfloat16(r2), h3 = __float2bfloat16(r3);
    __nv_bfloat162 hh01 = __halves2bfloat162(h0, h1), hh23 = __halves2bfloat162(h2, h3);
    size_t base = (size_t)row * EE + lane * 4;
    *(uint2*)(ohi + base) = make_uint2(*(uint32_t*)&hh01, *(uint32_t*)&hh23);
    uint32_t l01 = pack_bf2(r0 - __bfloat162float(h0), r1 - __bfloat162float(h1));
    uint32_t l23 = pack_bf2(r2 - __bfloat162float(h2), r3 - __bfloat162float(h3));
    *(uint2*)(olo + base) = make_uint2(l01, l23);
}

// =============== shared smem layout for projection GEMMs (2 stages) =========
#define MM3_AHI 0u
#define MM3_ALO 16384u
#define MM3_BHI 32768u
#define MM3_BLO 49152u
#define MM3_STAGE 65536u
#define MM3_SMEM 131072

// =============== fused QKV projection (pipelined, bf16x3) ===================
// grid (48, 32): blockIdx.x>>4 selects matrix (0=Q,1=K,2=V); weights/outputs
// referenced directly as device globals. Full tile 128x128, K=128 (2 iters).
__global__ __launch_bounds__(256, 1)
void qkv_mm(float qscale)
{
    extern __shared__ char sm[];
    uint32_t sb = smem_u32(sm);
    const int tid = threadIdx.x;
    const int w = tid >> 5, ln = tid & 31;
    const int tig = ln & 3, gid = ln >> 2;
    const int mi = blockIdx.x >> 4;
    const int n0 = (blockIdx.x & 15) * 128;
    const int m0 = blockIdx.y * 128;
    const __nv_bfloat16* Bh_ = (mi == 0) ? g_wqh : (mi == 1) ? g_wkh : g_wvh;
    const __nv_bfloat16* Bl_ = (mi == 0) ? g_wql : (mi == 1) ? g_wkl : g_wvl;
    __nv_bfloat16* Oh_ = (mi == 0) ? g_qhi : (mi == 1) ? g_khi : g_vhi;
    __nv_bfloat16* Ol_ = (mi == 0) ? g_qlo : (mi == 1) ? g_klo : g_vlo;
    const float scale = (mi == 0) ? qscale : 1.0f;

    float C[16][4];
    #pragma unroll
    for (int j = 0; j < 16; j++)
        #pragma unroll
        for (int e = 0; e < 4; e++) C[j][e] = 0.f;

    const int arow = 16 * w + ((ln >> 3) & 1) * 8 + (ln & 7);
    const int akb  = (ln >> 4) * 16;
    const int brow = ((ln >> 3) & 1) * 8 + (ln & 7);
    const int bcb  = (ln >> 4) << 4;

    // prologue: prefetch k-iter 0 into stage 0
    for (int f = tid; f < 1024; f += 256) {
        int r = f >> 3, seg = f & 7;
        size_t g = (size_t)(m0 + r) * EE + seg * 8;
        uint32_t so = aoff(r, seg * 16);
        cp16(sb + MM3_AHI + so, g_h1h + g);
        cp16(sb + MM3_ALO + so, g_h1l + g);
    }
    for (int f = tid; f < 1024; f += 256) {
        int r = f >> 4, seg = f & 15;
        size_t g = (size_t)r * HD + n0 + seg * 8;
        uint32_t so = boff(r, seg * 16);
        cp16(sb + MM3_BHI + so, Bh_ + g);
        cp16(sb + MM3_BLO + so, Bl_ + g);
    }
    CP_COMMIT();

    #pragma unroll
    for (int it = 0; it < 2; it++) {
        int k0 = it * 64;
        uint32_t st = (uint32_t)(it & 1) * MM3_STAGE;
        __syncthreads();
        if (it == 0) {
            for (int f = tid; f < 1024; f += 256) {
                int r = f >> 3, seg = f & 7;
                size_t g = (size_t)(m0 + r) * EE + 64 + seg * 8;
                uint32_t so = aoff(r, seg * 16);
                cp16(sb + MM3_STAGE + MM3_AHI + so, g_h1h + g);
                cp16(sb + MM3_STAGE + MM3_ALO + so, g_h1l + g);
            }
            for (int f = tid; f < 1024; f += 256) {
                int r = f >> 4, seg = f & 15;
                size_t g = (size_t)(64 + r) * HD + n0 + seg * 8;
                uint32_t so = boff(r, seg * 16);
                cp16(sb + MM3_STAGE + MM3_BHI + so, Bh_ + g);
                cp16(sb + MM3_STAGE + MM3_BLO + so, Bl_ + g);
            }
            CP_COMMIT();
            CP_WAIT(1);
        } else {
            CP_WAIT(0);
        }
        __syncthreads();
        (void)k0;

        uint32_t Ah[4][4], Al[4][4];
        #pragma unroll
        for (int kk = 0; kk < 4; kk++) {
            uint32_t off = aoff(arow, kk * 32 + akb);
            ldsm_x4(Ah[kk], sb + st + MM3_AHI + off);
            ldsm_x4(Al[kk], sb + st + MM3_ALO + off);
        }
        #pragma unroll
        for (int jp = 0; jp < 8; jp++) {
            int ncb = 32 * jp;
            #pragma unroll
            for (int kk = 0; kk < 4; kk++) {
                uint32_t off = boff(16 * kk + brow, ncb + bcb);
                uint32_t Bh[4], Bl[4];
                ldsm_x4_t(Bh, sb + st + MM3_BHI + off);
                mma16816(C[2*jp],   Ah[kk], Bh);
                mma16816(C[2*jp+1], Ah[kk], Bh + 2);
                mma16816(C[2*jp],   Al[kk], Bh);
                mma16816(C[2*jp+1], Al[kk], Bh + 2);
                ldsm_x4_t(Bl, sb + st + MM3_BLO + off);
                mma16816(C[2*jp],   Ah[kk], Bl);
                mma16816(C[2*jp+1], Ah[kk], Bl + 2);
            }
        }
    }

    // epilogue: scale, RoPE (Q/K), bf16 hi/lo split to (B,H,S,D)
    const int r0 = m0 + 16 * w + gid;
    const int r1 = r0 + 8;
    int b_ = r0 >> 11, s0 = r0 & 2047, s1 = r1 & 2047;
    #pragma unroll
    for (int j = 0; j < 16; j++) {
        int colg = n0 + 8 * j + 2 * tig;
        int h = colg >> 7, d = colg & 127;
        float o00 = C[j][0] * scale, o01 = C[j][1] * scale;
        float o10 = C[j][2] * scale, o11 = C[j][3] * scale;
        if (mi < 2) {
            int t2 = d >> 1;
            float f = expf((float)t2 * -0.14391157f);
            float si0, co0, si1, co1;
            sincosf((float)s0 * f, &si0, &co0);
            sincosf((float)s1 * f, &si1, &co1);
            float a = o00 * co0 - o01 * si0, b2 = o00 * si0 + o01 * co0;
            o00 = a; o01 = b2;
            a = o10 * co1 - o11 * si1; b2 = o10 * si1 + o11 * co1;
            o10 = a; o11 = b2;
        }
        size_t oi0 = (((size_t)(b_ * HH + h) * SS + s0) * DD + d);
        size_t oi1 = (((size_t)(b_ * HH + h) * SS + s1) * DD + d);
        __nv_bfloat16 h00 = __float2bfloat16(o00), h01 = __float2bfloat16(o01);
        __nv_bfloat16 h10 = __float2bfloat16(o10), h11 = __float2bfloat16(o11);
        __nv_bfloat162 p0 = __halves2bfloat162(h00, h01);
        __nv_bfloat162 p1 = __halves2bfloat162(h10, h11);
        *(uint32_t*)(Oh_ + oi0) = *(uint32_t*)&p0;
        *(uint32_t*)(Oh_ + oi1) = *(uint32_t*)&p1;
        *(uint32_t*)(Ol_ + oi0) = pack_bf2(o00 - __bfloat162float(h00), o01 - __bfloat162float(h01));
        *(uint32_t*)(Ol_ + oi1) = pack_bf2(o10 - __bfloat162float(h10), o11 - __bfloat162float(h11));
    }
}

// =============== bf16x3 tensor-core GEMM (pipelined) ========================
// MODE 4: gelu(acc + bias) -> bf16 hi/lo               (fc1)
// MODE 6: split-K partial: fp32 to out + blockIdx.x*M*N, k in [bx*kspl, +kspl)
template<int MODE, bool AG, bool HALFM>
__global__ __launch_bounds__(256)
void mm3(const __nv_bfloat16* __restrict__ Ahi, const __nv_bfloat16* __restrict__ Alo,
         const __nv_bfloat16* __restrict__ Bhi, const __nv_bfloat16* __restrict__ Blo,
         const float* __restrict__ bias, const float* __restrict__ resid,
         float* __restrict__ out,
         __nv_bfloat16* __restrict__ ohi, __nv_bfloat16* __restrict__ olo,
         int M, int N, int K, int kspl, float qscale)
{
    extern __shared__ char sm[];
    uint32_t sb = smem_u32(sm);
    constexpr int MT = HALFM ? 64 : 128;
    constexpr int NJ = HALFM ? 8 : 16;
    const int tid = threadIdx.x;
    const int w = tid >> 5, ln = tid & 31;
    const int tig = ln & 3, gid = ln >> 2;
    const int wr = HALFM ? (w & 3) : w;
    const int wc = HALFM ? (w >> 2) * 64 : 0;
    const int m0 = blockIdx.y * MT;
    const int n0 = (MODE == 6) ? 0 : blockIdx.x * 128;
    const int kb = (MODE == 6) ? blockIdx.x * kspl : 0;
    const int ke = (MODE == 6) ? kb + kspl : K;
    const int niter = (ke - kb) >> 6;

    float C[NJ][4];
    #pragma unroll
    for (int j = 0; j < NJ; j++)
        #pragma unroll
        for (int e = 0; e < 4; e++) C[j][e] = 0.f;

    const int arow = 16 * wr + ((ln >> 3) & 1) * 8 + (ln & 7);
    const int akb  = (ln >> 4) * 16;
    const int brow = ((ln >> 3) & 1) * 8 + (ln & 7);
    const int bcb  = (ln >> 4) << 4;

    // prologue: prefetch iter 0
    {
        int k0 = kb;
        for (int f = tid; f < MT * 8; f += 256) {
            int r = f >> 3, seg = f & 7;
            size_t g;
            if (!AG) {
                g = (size_t)(m0 + r) * K + k0 + seg * 8;
            } else {
                int rr = m0 + r;
                int b_ = rr >> 11, s_ = rr & 2047;
                int kk = k0 + seg * 8;
                g = ((size_t)(b_ * HH + (kk >> 7)) * SS + s_) * DD + (kk & 127);
            }
            uint32_t so = aoff(r, seg * 16);
            cp16(sb + MM3_AHI + so, Ahi + g);
            cp16(sb + MM3_ALO + so, Alo + g);
        }
        for (int f = tid; f < 1024; f += 256) {
            int r = f >> 4, seg = f & 15;
            size_t g = (size_t)(k0 + r) * N + n0 + seg * 8;
            uint32_t so = boff(r, seg * 16);
            cp16(sb + MM3_BHI + so, Bhi + g);
            cp16(sb + MM3_BLO + so, Blo + g);
        }
        CP_COMMIT();
    }

    for (int it = 0; it < niter; it++) {
        uint32_t st = (uint32_t)(it & 1) * MM3_STAGE;
        __syncthreads();
        if (it + 1 < niter) {
            int k0 = kb + (it + 1) * 64;
            uint32_t stn = (uint32_t)((it + 1) & 1) * MM3_STAGE;
            for (int f = tid; f < MT * 8; f += 256) {
                int r = f >> 3, seg = f & 7;
                size_t g;
                if (!AG) {
                    g = (size_t)(m0 + r) * K + k0 + seg * 8;
                } else {
                    int rr = m0 + r;
                    int b_ = rr >> 11, s_ = rr & 2047;
                    int kk = k0 + seg * 8;
                    g = ((size_t)(b_ * HH + (kk >> 7)) * SS + s_) * DD + (kk & 127);
                }
                uint32_t so = aoff(r, seg * 16);
                cp16(sb + stn + MM3_AHI + so, Ahi + g);
                cp16(sb + stn + MM3_ALO + so, Alo + g);
            }
            for (int f = tid; f < 1024; f += 256) {
                int r = f >> 4, seg = f & 15;
                size_t g = (size_t)(k0 + r) * N + n0 + seg * 8;
                uint32_t so = boff(r, seg * 16);
                cp16(sb + stn + MM3_BHI + so, Bhi + g);
                cp16(sb + stn + MM3_BLO + so, Blo + g);
            }
            CP_COMMIT();
            CP_WAIT(1);
        } else {
            CP_WAIT(0);
        }
        __syncthreads();

        uint32_t Ah[4][4], Al[4][4];
        #pragma unroll
        for (int kk = 0; kk < 4; kk++) {
            uint32_t off = aoff(arow, kk * 32 + akb);
            ldsm_x4(Ah[kk], sb + st + MM3_AHI + off);
            ldsm_x4(Al[kk], sb + st + MM3_ALO + off);
        }
        #pragma unroll
        for (int jp = 0; jp < NJ / 2; jp++) {
            int ncb = (wc + 16 * jp) * 2;
            #pragma unroll
            for (int kk = 0; kk < 4; kk++) {
                uint32_t off = boff(16 * kk + brow, ncb + bcb);
                uint32_t Bh[4], Bl[4];
                ldsm_x4_t(Bh, sb + st + MM3_BHI + off);
                mma16816(C[2*jp],   Ah[kk], Bh);
                mma16816(C[2*jp+1], Ah[kk], Bh + 2);
                mma16816(C[2*jp],   Al[kk], Bh);
                mma16816(C[2*jp+1], Al[kk], Bh + 2);
                ldsm_x4_t(Bl, sb + st + MM3_BLO + off);
                mma16816(C[2*jp],   Ah[kk], Bl);
                mma16816(C[2*jp+1], Ah[kk], Bl + 2);
            }
        }
    }

    const int r0 = m0 + 16 * wr + gid;
    const int r1 = r0 + 8;
    if (MODE == 6) {
        float* po = out + (size_t)blockIdx.x * M * N;
        #pragma unroll
        for (int j = 0; j < NJ; j++) {
            int colg = wc + 8 * j + 2 * tig;
            size_t i0 = (size_t)r0 * N + colg;
            size_t i1 = (size_t)r1 * N + colg;
            *(float2*)(po + i0) = make_float2(C[j][0], C[j][1]);
            *(float2*)(po + i1) = make_float2(C[j][2], C[j][3]);
        }
    } else if (MODE == 4) {
        #pragma unroll
        for (int j = 0; j < NJ; j++) {
            int colg = n0 + wc + 8 * j + 2 * tig;
            size_t i0 = (size_t)r0 * N + colg;
            size_t i1 = (size_t)r1 * N + colg;
            float v00 = C[j][0], v01 = C[j][1], v10 = C[j][2], v11 = C[j][3];
            float b0 = bias[colg], b1 = bias[colg + 1];
            v00 += b0; v01 += b1; v10 += b0; v11 += b1;
            v00 = 0.5f * v00 * (1.0f + erff(v00 * 0.70710678f));
            v01 = 0.5f * v01 * (1.0f + erff(v01 * 0.70710678f));
            v10 = 0.5f * v10 * (1.0f + erff(v10 * 0.70710678f));
            v11 = 0.5f * v11 * (1.0f + erff(v11 * 0.70710678f));
            __nv_bfloat16 h00 = __float2bfloat16(v00), h01 = __float2bfloat16(v01);
            __nv_bfloat16 h10 = __float2bfloat16(v10), h11 = __float2bfloat16(v11);
            __nv_bfloat162 p0 = __halves2bfloat162(h00, h01);
            __nv_bfloat162 p1 = __halves2bfloat162(h10, h11);
            *(uint32_t*)(ohi + i0) = *(uint32_t*)&p0;
            *(uint32_t*)(ohi + i1) = *(uint32_t*)&p1;
            *(uint32_t*)(olo + i0) = pack_bf2(v00 - __bfloat162float(h00), v01 - __bfloat162float(h01));
            *(uint32_t*)(olo + i1) = pack_bf2(v10 - __bfloat162float(h10), v11 - __bfloat162float(h11));
        }
    }
}

// ============== mma.sync flash attention (bf16x3, cp.async double-buffer) ===
#define KHI_OFF 0u
#define KLO_OFF 16384u
#define VHI_OFF 32768u
#define VLO_OFF 49152u
#define FA_STAGE 65536u
#define FA_SMEM 131072

__device__ __forceinline__ uint32_t fa_off(int r, int cbyte) {
    return (uint32_t)(r * 256 + (cbyte ^ ((r & 7) << 4)));
}

__global__ __launch_bounds__(256, 1)
void fa_mma(const __nv_bfloat16* __restrict__ qhi, const __nv_bfloat16* __restrict__ qlo,
            const __nv_bfloat16* __restrict__ khi, const __nv_bfloat16* __restrict__ klo,
            const __nv_bfloat16* __restrict__ vhi, const __nv_bfloat16* __restrict__ vlo,
            __nv_bfloat16* __restrict__ Ohi, __nv_bfloat16* __restrict__ Olo)
{
    extern __shared__ char sm[];
    uint32_t sb = smem_u32(sm);
    const int tid = threadIdx.x;
    const int w = tid >> 5, ln = tid & 31;
    const int tig = ln & 3, gid = ln >> 2;
    const int m0 = (gridDim.x - 1 - blockIdx.x) * 128;   // big tiles first
    const int bh = blockIdx.y;
    const size_t base = (size_t)bh * SS * DD;

    // ---- stage Q tile through smem (regions overwritten later by K/V) ----
    for (int f = tid; f < 2048; f += 256) {
        int r = f >> 4, c16 = f & 15;
        size_t g = base + (size_t)(m0 + r) * DD + c16 * 8;
        uint32_t so = fa_off(r, c16 * 16);
        *(uint4*)(sm + so)              = *(const uint4*)(qhi + g);
        *(uint4*)(sm + FA_STAGE + so)   = *(const uint4*)(qlo + g);
    }
    __syncthreads();
    uint32_t Qh[8][4], Ql[8][4];
    {
        int row = 16 * w + ((ln >> 3) & 1) * 8 + (ln & 7);
        int kb0 = (ln >> 4) * 16;
        #pragma unroll
        for (int kk = 0; kk < 8; kk++) {
            uint32_t off = fa_off(row, kk * 32 + kb0);
            ldsm_x4(Qh[kk], sb + off);
            ldsm_x4(Ql[kk], sb + FA_STAGE + off);
        }
    }
    __syncthreads();

    float Oa[16][4];
    #pragma unroll
    for (int j = 0; j < 16; j++)
        #pragma unroll
        for (int e = 0; e < 4; e++) Oa[j][e] = 0.f;
    float m0r = -1e30f, m1r = -1e30f, l0r = 0.f, l1r = 0.f;

    const int grow0 = m0 + 16 * w + gid;
    const int grow1 = grow0 + 8;
    const int nk = m0 / 64 + 2;

    // ---- prologue: prefetch tile 0 into stage 0 ----
    {
        for (int f = tid; f < 1024; f += 256) {
            int r = f >> 4, c16 = f & 15;
            size_t g = base + (size_t)r * DD + c16 * 8;
            uint32_t so = fa_off(r, c16 * 16);
            cp16(sb + KHI_OFF + so, khi + g);
            cp16(sb + KLO_OFF + so, klo + g);
            cp16(sb + VHI_OFF + so, vhi + g);
            cp16(sb + VLO_OFF + so, vlo + g);
        }
        CP_COMMIT();
    }

    for (int t = 0; t < nk; t++) {
        int n0 = t * 64;
        uint32_t st = (uint32_t)(t & 1) * FA_STAGE;
        __syncthreads();   // everyone done with the stage we're about to overwrite
        if (t + 1 < nk) {
            uint32_t stn = (uint32_t)((t + 1) & 1) * FA_STAGE;
            int n1 = n0 + 64;
            for (int f = tid; f < 1024; f += 256) {
                int r = f >> 4, c16 = f & 15;
                size_t g = base + (size_t)(n1 + r) * DD + c16 * 8;
                uint32_t so = fa_off(r, c16 * 16);
                cp16(sb + stn + KHI_OFF + so, khi + g);
                cp16(sb + stn + KLO_OFF + so, klo + g);
                cp16(sb + stn + VHI_OFF + so, vhi + g);
                cp16(sb + stn + VLO_OFF + so, vlo + g);
            }
            CP_COMMIT();
            CP_WAIT(1);
        } else {
            CP_WAIT(0);
        }
        __syncthreads();   // current stage data visible to all

        // ---- S = Q K^T (3-term) ----
        float S[8][4];
        #pragma unroll
        for (int j = 0; j < 8; j++)
            #pragma unroll
            for (int e = 0; e < 4; e++) S[j][e] = 0.f;
        {
            int brow = ((ln >> 4) << 3) + (ln & 7);
            int bkb  = ((ln >> 3) & 1) << 4;
            #pragma unroll
            for (int jp = 0; jp < 4; jp++) {
                #pragma unroll
                for (int kk = 0; kk < 8; kk++) {
                    int r_ = 16 * jp + brow;
                    uint32_t off = fa_off(r_, kk * 32 + bkb);
                    uint32_t Bh[4], Bl[4];
                    ldsm_x4(Bh, sb + st + KHI_OFF + off);
                    mma16816(S[2*jp],   Qh[kk], Bh);
                    mma16816(S[2*jp+1], Qh[kk], Bh + 2);
                    mma16816(S[2*jp],   Ql[kk], Bh);
                    mma16816(S[2*jp+1], Ql[kk], Bh + 2);
                    ldsm_x4(Bl, sb + st + KLO_OFF + off);
                    mma16816(S[2*jp],   Qh[kk], Bl);
                    mma16816(S[2*jp+1], Qh[kk], Bl + 2);
                }
            }
        }

        // ---- causal mask (only near-diagonal tiles) ----
        if (n0 + 63 > m0 + 16 * w) {
            #pragma unroll
            for (int j = 0; j < 8; j++) {
                int c = n0 + 8 * j + 2 * tig;
                if (c     > grow0) S[j][0] = -1e30f;
                if (c + 1 > grow0) S[j][1] = -1e30f;
                if (c     > grow1) S[j][2] = -1e30f;
                if (c + 1 > grow1) S[j][3] = -1e30f;
            }
        }

        // ---- online softmax ----
        float mx0 = -1e30f, mx1 = -1e30f;
        #pragma unroll
        for (int j = 0; j < 8; j++) {
            mx0 = fmaxf(mx0, fmaxf(S[j][0], S[j][1]));
            mx1 = fmaxf(mx1, fmaxf(S[j][2], S[j][3]));
        }
        mx0 = fmaxf(mx0, __shfl_xor_sync(0xffffffffu, mx0, 1));
        mx0 = fmaxf(mx0, __shfl_xor_sync(0xffffffffu, mx0, 2));
        mx1 = fmaxf(mx1, __shfl_xor_sync(0xffffffffu, mx1, 1));
        mx1 = fmaxf(mx1, __shfl_xor_sync(0xffffffffu, mx1, 2));
        float mn0 = fmaxf(m0r, mx0), mn1 = fmaxf(m1r, mx1);
        bool nochg = (mn0 == m0r) && (mn1 == m1r);
        float a0 = nochg ? 1.f : __expf(m0r - mn0);
        float a1 = nochg ? 1.f : __expf(m1r - mn1);
        m0r = mn0; m1r = mn1;
        l0r *= a0; l1r *= a1;

        uint32_t Phi[4][4], Plo[4][4];
        float ls0 = 0.f, ls1 = 0.f;
        #pragma unroll
        for (int j = 0; j < 8; j++) {
            float p0 = __expf(S[j][0] - mn0);
            float p1 = __expf(S[j][1] - mn0);
            float p2 = __expf(S[j][2] - mn1);
            float p3 = __expf(S[j][3] - mn1);
            ls0 += p0 + p1; ls1 += p2 + p3;
            __nv_bfloat16 h0 = __float2bfloat16(p0);
            __nv_bfloat16 h1 = __float2bfloat16(p1);
            __nv_bfloat16 h2 = __float2bfloat16(p2);
            __nv_bfloat16 h3 = __float2bfloat16(p3);
            int kk = j >> 1, q = (j & 1) * 2;
            __nv_bfloat162 hh01 = __halves2bfloat162(h0, h1);
            __nv_bfloat162 hh23 = __halves2bfloat162(h2, h3);
            Phi[kk][q]     = *(uint32_t*)&hh01;
            Phi[kk][q + 1] = *(uint32_t*)&hh23;
            Plo[kk][q]     = pack_bf2(p0 - __bfloat162float(h0), p1 - __bfloat162float(h1));
            Plo[kk][q + 1] = pack_bf2(p2 - __bfloat162float(h2), p3 - __bfloat162float(h3));
        }
        l0r += ls0; l1r += ls1;

        if (!__all_sync(0xffffffffu, nochg)) {
            #pragma unroll
            for (int j = 0; j < 16; j++) {
                Oa[j][0] *= a0; Oa[j][1] *= a0;
                Oa[j][2] *= a1; Oa[j][3] *= a1;
            }
        }

        // ---- O += P V (3-term) ----
        {
            int vrow = ((ln >> 3) & 1) * 8 + (ln & 7);
            int vcb  = (ln >> 4) << 4;
            #pragma unroll
            for (int jp = 0; jp < 8; jp++) {
                #pragma unroll
                for (int kk = 0; kk < 4; kk++) {
                    int r_ = 16 * kk + vrow;
                    uint32_t off = fa_off(r_, 32 * jp + vcb);
                    uint32_t Bh[4], Bl[4];
                    ldsm_x4_t(Bh, sb + st + VHI_OFF + off);
                    mma16816(Oa[2*jp],   Phi[kk], Bh);
                    mma16816(Oa[2*jp+1], Phi[kk], Bh + 2);
                    mma16816(Oa[2*jp],   Plo[kk], Bh);
                    mma16816(Oa[2*jp+1], Plo[kk], Bh + 2);
                    ldsm_x4_t(Bl, sb + st + VLO_OFF + off);
                    mma16816(Oa[2*jp],   Phi[kk], Bl);
                    mma16816(Oa[2*jp+1], Phi[kk], Bl + 2);
                }
            }
        }
    }

    // ---- finalize: reduce l, normalize, split hi/lo, store ----
    l0r += __shfl_xor_sync(0xffffffffu, l0r, 1);
    l0r += __shfl_xor_sync(0xffffffffu, l0r, 2);
    l1r += __shfl_xor_sync(0xffffffffu, l1r, 1);
    l1r += __shfl_xor_sync(0xffffffffu, l1r, 2);
    float inv0 = 1.0f / l0r, inv1 = 1.0f / l1r;
    #pragma unroll
    for (int j = 0; j < 16; j++) {
        int col = 8 * j + 2 * tig;
        size_t i0 = base + (size_t)grow0 * DD + col;
        size_t i1 = base + (size_t)grow1 * DD + col;
        float v00 = Oa[j][0] * inv0, v01 = Oa[j][1] * inv0;
        float v10 = Oa[j][2] * inv1, v11 = Oa[j][3] * inv1;
        __nv_bfloat16 h00 = __float2bfloat16(v00), h01 = __float2bfloat16(v01);
        __nv_bfloat16 h10 = __float2bfloat16(v10), h11 = __float2bfloat16(v11);
        __nv_bfloat162 p0 = __halves2bfloat162(h00, h01);
        __nv_bfloat162 p1 = __halves2bfloat162(h10, h11);
        *(uint32_t*)(Ohi + i0) = *(uint32_t*)&p0;
        *(uint32_t*)(Ohi + i1) = *(uint32_t*)&p1;
        *(uint32_t*)(Olo + i0) = pack_bf2(v00 - __bfloat162float(h00), v01 - __bfloat162float(h01));
        *(uint32_t*)(Olo + i1) = pack_bf2(v10 - __bfloat162float(h10), v11 - __bfloat162float(h11));
    }
}

// ---------------- launch -----------------------------------------------------
extern "C" void kernel_launch(void* const* d_in, const int* in_sizes, int n_in,
                              void* d_out, int out_size) {
    const float* x        = (const float*)d_in[0];
    const float* W_q      = (const float*)d_in[1];
    const float* W_k      = (const float*)d_in[2];
    const float* W_v      = (const float*)d_in[3];
    const float* W_o      = (const float*)d_in[4];
    const float* ln_attn_g= (const float*)d_in[5];
    const float* ln_attn_b= (const float*)d_in[6];
    const float* fc1_w    = (const float*)d_in[7];
    const float* fc1_b    = (const float*)d_in[8];
    const float* fc2_w    = (const float*)d_in[9];
    const float* fc2_b    = (const float*)d_in[10];
    const float* ln_mlp_g = (const float*)d_in[11];
    const float* ln_mlp_b = (const float*)d_in[12];
    float* out = (float*)d_out;

    float *x2, *part;
    __nv_bfloat16 *h1h, *h1l, *h2h, *h2l, *th, *tl, *aoh, *aol;
    __nv_bfloat16 *qhi, *qlo, *khi, *klo, *vhi, *vlo;
    __nv_bfloat16 *wqh, *wql, *wkh, *wkl, *wvh, *wvl, *woh, *wol, *f1h, *f1l, *f2h, *f2l;
    cudaGetSymbolAddress((void**)&x2,  g_x2);
    cudaGetSymbolAddress((void**)&part, g_part);
    cudaGetSymbolAddress((void**)&h1h, g_h1h); cudaGetSymbolAddress((void**)&h1l, g_h1l);
    cudaGetSymbolAddress((void**)&h2h, g_h2h); cudaGetSymbolAddress((void**)&h2l, g_h2l);
    cudaGetSymbolAddress((void**)&th,  g_th);  cudaGetSymbolAddress((void**)&tl,  g_tl);
    cudaGetSymbolAddress((void**)&aoh, g_aoh); cudaGetSymbolAddress((void**)&aol, g_aol);
    cudaGetSymbolAddress((void**)&qhi, g_qhi); cudaGetSymbolAddress((void**)&qlo, g_qlo);
    cudaGetSymbolAddress((void**)&khi, g_khi); cudaGetSymbolAddress((void**)&klo, g_klo);
    cudaGetSymbolAddress((void**)&vhi, g_vhi); cudaGetSymbolAddress((void**)&vlo, g_vlo);
    cudaGetSymbolAddress((void**)&wqh, g_wqh); cudaGetSymbolAddress((void**)&wql, g_wql);
    cudaGetSymbolAddress((void**)&wkh, g_wkh); cudaGetSymbolAddress((void**)&wkl, g_wkl);
    cudaGetSymbolAddress((void**)&wvh, g_wvh); cudaGetSymbolAddress((void**)&wvl, g_wvl);
    cudaGetSymbolAddress((void**)&woh, g_woh); cudaGetSymbolAddress((void**)&wol, g_wol);
    cudaGetSymbolAddress((void**)&f1h, g_f1h); cudaGetSymbolAddress((void**)&f1l, g_f1l);
    cudaGetSymbolAddress((void**)&f2h, g_f2h); cudaGetSymbolAddress((void**)&f2l, g_f2l);

    // 0) split all six weights to bf16 hi/lo in one launch
    split6<<<1152, 256>>>(W_q, W_k, W_v, W_o, fc1_w, fc2_w,
                          wqh, wql, wkh, wkl, wvh, wvl,
                          woh, wol, f1h, f1l, f2h, f2l);

    // 1) LN -> bf16 hi/lo
    ln_kernel<<<MM/8, 256>>>(x, ln_attn_g, ln_attn_b, h1h, h1l);

    // 2) fused QKV projection (pipelined tensor core, fused RoPE/scale/split)
    const float qscale = 0.08838834764831845f;  // 1/sqrt(128)
    cudaFuncSetAttribute(qkv_mm, cudaFuncAttributeMaxDynamicSharedMemorySize, MM3_SMEM);
    qkv_mm<<<dim3(48, MM/128), 256, MM3_SMEM>>>(qscale);

    // 3) causal flash attention (tensor core, cp.async double-buffered)
    cudaFuncSetAttribute(fa_mma, cudaFuncAttributeMaxDynamicSharedMemorySize, FA_SMEM);
    fa_mma<<<dim3(SS/128, BB*HH), 256, FA_SMEM>>>(qhi, qlo, khi, klo, vhi, vlo, aoh, aol);

    // 4) O-projection via split-K (4 x 512, pipelined), then reduce + residual
    cudaFuncSetAttribute(mm3<6,true,true>,  cudaFuncAttributeMaxDynamicSharedMemorySize, MM3_SMEM);
    cudaFuncSetAttribute(mm3<6,false,true>, cudaFuncAttributeMaxDynamicSharedMemorySize, MM3_SMEM);
    cudaFuncSetAttribute(mm3<4,false,true>, cudaFuncAttributeMaxDynamicSharedMemorySize, MM3_SMEM);
    mm3<6,true,true><<<dim3(4, MM/64), 256, MM3_SMEM>>>(aoh, aol, woh, wol, nullptr, nullptr, part, nullptr, nullptr, MM, EE, HD, 512, 1.0f);
    reduce_k<4,false><<<(MM*EE)/1024, 256>>>(part, x, nullptr, x2);

    // 5) LN -> bf16 hi/lo
    ln_kernel<<<MM/8, 256>>>(x2, ln_mlp_g, ln_mlp_b, h2h, h2l);

    // 6) MLP: fc1 (pipelined, HALFM, fused bias+GELU+split), fc2 split-K 4x128
    mm3<4,false,true><<<dim3(DHH/128, MM/64), 256, MM3_SMEM>>>(h2h, h2l, f1h, f1l, fc1_b, nullptr, nullptr, th, tl, MM, DHH, EE, EE, 1.0f);
    mm3<6,false,true><<<dim3(4, MM/64), 256, MM3_SMEM>>>(th, tl, f2h, f2l, nullptr, nullptr, part, nullptr, nullptr, MM, EE, DHH, 128, 1.0f);
    reduce_k<4,true><<<(MM*EE)/1024, 256>>>(part, x2, fc2_b, out);
}

// round 11
// speedup vs baseline: 3.6998x; 1.1620x over previous
#include <cuda_runtime.h>
#include <cuda_bf16.h>
#include <math.h>
#include <stdint.h>

#define BB 2
#define SS 2048
#define EE 128
#define HH 16
#define DD 128
#define DHH 512
#define MM (BB*SS)     // 4096 rows
#define HD (HH*DD)     // 2048

// ---------------- scratch (static __device__, no allocation) ----------------
__device__ float g_x2[MM*EE];
__device__ float g_part[4*MM*EE];
__device__ __nv_bfloat16 g_h1h[MM*EE],  g_h1l[MM*EE];
__device__ __nv_bfloat16 g_h2h[MM*EE],  g_h2l[MM*EE];
__device__ __nv_bfloat16 g_th [MM*DHH], g_tl [MM*DHH];
__device__ __nv_bfloat16 g_aoh[MM*HD],  g_aol[MM*HD];
__device__ __nv_bfloat16 g_qhi[MM*HD],  g_qlo[MM*HD];
__device__ __nv_bfloat16 g_khi[MM*HD],  g_klo[MM*HD];
__device__ __nv_bfloat16 g_vhi[MM*HD],  g_vlo[MM*HD];
__device__ __nv_bfloat16 g_wqh[EE*HD],  g_wql[EE*HD];
__device__ __nv_bfloat16 g_wkh[EE*HD],  g_wkl[EE*HD];
__device__ __nv_bfloat16 g_wvh[EE*HD],  g_wvl[EE*HD];
__device__ __nv_bfloat16 g_woh[HD*EE],  g_wol[HD*EE];
__device__ __nv_bfloat16 g_f1h[EE*DHH], g_f1l[EE*DHH];
__device__ __nv_bfloat16 g_f2h[DHH*EE], g_f2l[DHH*EE];

// ======================= warp MMA helpers (baseline PTX) =====================
__device__ __forceinline__ uint32_t smem_u32(const void* p) {
    uint32_t a;
    asm("{ .reg .u64 t; cvta.to.shared.u64 t, %1; cvt.u32.u64 %0, t; }"
        : "=r"(a) : "l"(p));
    return a;
}
__device__ __forceinline__ void mma16816(float* c, const uint32_t* a, const uint32_t* b) {
    asm volatile(
        "mma.sync.aligned.m16n8k16.row.col.f32.bf16.bf16.f32 "
        "{%0,%1,%2,%3}, {%4,%5,%6,%7}, {%8,%9}, {%0,%1,%2,%3};"
        : "+f"(c[0]), "+f"(c[1]), "+f"(c[2]), "+f"(c[3])
        : "r"(a[0]), "r"(a[1]), "r"(a[2]), "r"(a[3]), "r"(b[0]), "r"(b[1]));
}
__device__ __forceinline__ void ldsm_x4(uint32_t* r, uint32_t addr) {
    asm volatile("ldmatrix.sync.aligned.m8n8.x4.shared.b16 {%0,%1,%2,%3}, [%4];"
        : "=r"(r[0]), "=r"(r[1]), "=r"(r[2]), "=r"(r[3]) : "r"(addr));
}
__device__ __forceinline__ void ldsm_x4_t(uint32_t* r, uint32_t addr) {
    asm volatile("ldmatrix.sync.aligned.m8n8.x4.trans.shared.b16 {%0,%1,%2,%3}, [%4];"
        : "=r"(r[0]), "=r"(r[1]), "=r"(r[2]), "=r"(r[3]) : "r"(addr));
}
__device__ __forceinline__ uint32_t pack_bf2(float a, float b) {
    __nv_bfloat162 h = __halves2bfloat162(__float2bfloat16(a), __float2bfloat16(b));
    return *(uint32_t*)&h;
}
__device__ __forceinline__ void cp16(uint32_t smem_addr, const void* gptr) {
    asm volatile("cp.async.cg.shared.global [%0], [%1], 16;"
        :: "r"(smem_addr), "l"(gptr) : "memory");
}
#define CP_COMMIT() asm volatile("cp.async.commit_group;" ::: "memory")
#define CP_WAIT(n)  asm volatile("cp.async.wait_group %0;" :: "n"(n) : "memory")

// 256B-row swizzle (B tiles, FA tiles); 128B-row swizzle (A tiles)
__device__ __forceinline__ uint32_t boff(int r, int cbyte) {
    return (uint32_t)(r * 256 + (cbyte ^ ((r & 7) << 4)));
}
__device__ __forceinline__ uint32_t aoff(int r, int cbyte) {
    return (uint32_t)(r * 128 + (cbyte ^ ((r & 7) << 4)));
}

// ---------------- fp32 -> bf16 hi/lo split: all six weights in ONE launch ----
__global__ void split6(const float* __restrict__ a0, const float* __restrict__ a1,
                       const float* __restrict__ a2, const float* __restrict__ a3,
                       const float* __restrict__ a4, const float* __restrict__ a5,
                       __nv_bfloat16* h0, __nv_bfloat16* l0,
                       __nv_bfloat16* h1, __nv_bfloat16* l1,
                       __nv_bfloat16* h2, __nv_bfloat16* l2,
                       __nv_bfloat16* h3, __nv_bfloat16* l3,
                       __nv_bfloat16* h4, __nv_bfloat16* l4,
                       __nv_bfloat16* h5, __nv_bfloat16* l5) {
    const float* ws[6] = {a0, a1, a2, a3, a4, a5};
    __nv_bfloat16* hs[6] = {h0, h1, h2, h3, h4, h5};
    __nv_bfloat16* ls[6] = {l0, l1, l2, l3, l4, l5};
    int b = blockIdx.x, wi, off;
    if (b < 1024) { wi = b >> 8;       off = (b & 255) * 1024; }
    else          { b -= 1024; wi = 4 + (b >> 6); off = (b & 63) * 1024; }
    int i = off + threadIdx.x * 4;
    float4 v = *(const float4*)(ws[wi] + i);
    __nv_bfloat16 b0 = __float2bfloat16(v.x), b1 = __float2bfloat16(v.y);
    __nv_bfloat16 b2 = __float2bfloat16(v.z), b3 = __float2bfloat16(v.w);
    __nv_bfloat162 hh01 = __halves2bfloat162(b0, b1), hh23 = __halves2bfloat162(b2, b3);
    *(uint2*)(hs[wi] + i) = make_uint2(*(uint32_t*)&hh01, *(uint32_t*)&hh23);
    uint32_t l01 = pack_bf2(v.x - __bfloat162float(b0), v.y - __bfloat162float(b1));
    uint32_t l23 = pack_bf2(v.z - __bfloat162float(b2), v.w - __bfloat162float(b3));
    *(uint2*)(ls[wi] + i) = make_uint2(l01, l23);
}

// ---------------- split-K reduce: out = resid (+bias) + sum partials --------
template<int NS, bool BIAS>
__global__ void reduce_k(const float* __restrict__ part, const float* __restrict__ resid,
                         const float* __restrict__ bias, float* __restrict__ out) {
    int i = (blockIdx.x * 256 + threadIdx.x) * 4;
    float4 acc = *(const float4*)(resid + i);
    if (BIAS) {
        float4 bv = *(const float4*)(bias + (i & (EE - 1)));
        acc.x += bv.x; acc.y += bv.y; acc.z += bv.z; acc.w += bv.w;
    }
    #pragma unroll
    for (int z = 0; z < NS; z++) {
        float4 p = *(const float4*)(part + (size_t)z * (MM * EE) + i);
        acc.x += p.x; acc.y += p.y; acc.z += p.z; acc.w += p.w;
    }
    *(float4*)(out + i) = acc;
}

// ---------------- LayerNorm: one warp per row, bf16 hi/lo out ---------------
__global__ void ln_kernel(const float* __restrict__ x, const float* __restrict__ g,
                          const float* __restrict__ b,
                          __nv_bfloat16* __restrict__ ohi, __nv_bfloat16* __restrict__ olo) {
    int warp = threadIdx.x >> 5, lane = threadIdx.x & 31;
    int row = blockIdx.x * 8 + warp;
    float4 v = ((const float4*)(x + (size_t)row * EE))[lane];
    float s = v.x + v.y + v.z + v.w;
    #pragma unroll
    for (int o = 16; o; o >>= 1) s += __shfl_xor_sync(0xffffffffu, s, o);
    float mu = s * (1.0f / EE);
    float d0 = v.x - mu, d1 = v.y - mu, d2 = v.z - mu, d3 = v.w - mu;
    float q = d0*d0 + d1*d1 + d2*d2 + d3*d3;
    #pragma unroll
    for (int o = 16; o; o >>= 1) q += __shfl_xor_sync(0xffffffffu, q, o);
    float inv = rsqrtf(q * (1.0f / EE) + 1e-5f);
    float4 gg = ((const float4*)g)[lane];
    float4 bb = ((const float4*)b)[lane];
    float r0 = d0 * inv * gg.x + bb.x;
    float r1 = d1 * inv * gg.y + bb.y;
    float r2 = d2 * inv * gg.z + bb.z;
    float r3 = d3 * inv * gg.w + bb.w;
    __nv_bfloat16 h0 = __float2bfloat16(r0), h1 = __float2bfloat16(r1);
    __nv_bfloat16 h2 = __float2bfloat16(r2), h3 = __float2bfloat16(r3);
    __nv_bfloat162 hh01 = __halves2bfloat162(h0, h1), hh23 = __halves2bfloat162(h2, h3);
    size_t base = (size_t)row * EE + lane * 4;
    *(uint2*)(ohi + base) = make_uint2(*(uint32_t*)&hh01, *(uint32_t*)&hh23);
    uint32_t l01 = pack_bf2(r0 - __bfloat162float(h0), r1 - __bfloat162float(h1));
    uint32_t l23 = pack_bf2(r2 - __bfloat162float(h2), r3 - __bfloat162float(h3));
    *(uint2*)(olo + base) = make_uint2(l01, l23);
}

// =============== shared smem layout for projection GEMMs (2 stages) =========
#define MM3_AHI 0u
#define MM3_ALO 16384u
#define MM3_BHI 32768u
#define MM3_BLO 49152u
#define MM3_STAGE 65536u
#define MM3_SMEM 131072

// =============== fused QKV projection (pipelined, bf16x3) ===================
__global__ __launch_bounds__(256, 1)
void qkv_mm(float qscale)
{
    extern __shared__ char sm[];
    uint32_t sb = smem_u32(sm);
    const int tid = threadIdx.x;
    const int w = tid >> 5, ln = tid & 31;
    const int tig = ln & 3, gid = ln >> 2;
    const int mi = blockIdx.x >> 4;
    const int n0 = (blockIdx.x & 15) * 128;
    const int m0 = blockIdx.y * 128;
    const __nv_bfloat16* Bh_ = (mi == 0) ? g_wqh : (mi == 1) ? g_wkh : g_wvh;
    const __nv_bfloat16* Bl_ = (mi == 0) ? g_wql : (mi == 1) ? g_wkl : g_wvl;
    __nv_bfloat16* Oh_ = (mi == 0) ? g_qhi : (mi == 1) ? g_khi : g_vhi;
    __nv_bfloat16* Ol_ = (mi == 0) ? g_qlo : (mi == 1) ? g_klo : g_vlo;
    const float scale = (mi == 0) ? qscale : 1.0f;

    float C[16][4];
    #pragma unroll
    for (int j = 0; j < 16; j++)
        #pragma unroll
        for (int e = 0; e < 4; e++) C[j][e] = 0.f;

    const int arow = 16 * w + ((ln >> 3) & 1) * 8 + (ln & 7);
    const int akb  = (ln >> 4) * 16;
    const int brow = ((ln >> 3) & 1) * 8 + (ln & 7);
    const int bcb  = (ln >> 4) << 4;

    // prologue: prefetch k-iter 0 into stage 0
    for (int f = tid; f < 1024; f += 256) {
        int r = f >> 3, seg = f & 7;
        size_t g = (size_t)(m0 + r) * EE + seg * 8;
        uint32_t so = aoff(r, seg * 16);
        cp16(sb + MM3_AHI + so, g_h1h + g);
        cp16(sb + MM3_ALO + so, g_h1l + g);
    }
    for (int f = tid; f < 1024; f += 256) {
        int r = f >> 4, seg = f & 15;
        size_t g = (size_t)r * HD + n0 + seg * 8;
        uint32_t so = boff(r, seg * 16);
        cp16(sb + MM3_BHI + so, Bh_ + g);
        cp16(sb + MM3_BLO + so, Bl_ + g);
    }
    CP_COMMIT();

    #pragma unroll
    for (int it = 0; it < 2; it++) {
        uint32_t st = (uint32_t)(it & 1) * MM3_STAGE;
        __syncthreads();
        if (it == 0) {
            for (int f = tid; f < 1024; f += 256) {
                int r = f >> 3, seg = f & 7;
                size_t g = (size_t)(m0 + r) * EE + 64 + seg * 8;
                uint32_t so = aoff(r, seg * 16);
                cp16(sb + MM3_STAGE + MM3_AHI + so, g_h1h + g);
                cp16(sb + MM3_STAGE + MM3_ALO + so, g_h1l + g);
            }
            for (int f = tid; f < 1024; f += 256) {
                int r = f >> 4, seg = f & 15;
                size_t g = (size_t)(64 + r) * HD + n0 + seg * 8;
                uint32_t so = boff(r, seg * 16);
                cp16(sb + MM3_STAGE + MM3_BHI + so, Bh_ + g);
                cp16(sb + MM3_STAGE + MM3_BLO + so, Bl_ + g);
            }
            CP_COMMIT();
            CP_WAIT(1);
        } else {
            CP_WAIT(0);
        }
        __syncthreads();

        uint32_t Ah[4][4], Al[4][4];
        #pragma unroll
        for (int kk = 0; kk < 4; kk++) {
            uint32_t off = aoff(arow, kk * 32 + akb);
            ldsm_x4(Ah[kk], sb + st + MM3_AHI + off);
            ldsm_x4(Al[kk], sb + st + MM3_ALO + off);
        }
        #pragma unroll
        for (int jp = 0; jp < 8; jp++) {
            int ncb = 32 * jp;
            #pragma unroll
            for (int kk = 0; kk < 4; kk++) {
                uint32_t off = boff(16 * kk + brow, ncb + bcb);
                uint32_t Bh[4], Bl[4];
                ldsm_x4_t(Bh, sb + st + MM3_BHI + off);
                mma16816(C[2*jp],   Ah[kk], Bh);
                mma16816(C[2*jp+1], Ah[kk], Bh + 2);
                mma16816(C[2*jp],   Al[kk], Bh);
                mma16816(C[2*jp+1], Al[kk], Bh + 2);
                ldsm_x4_t(Bl, sb + st + MM3_BLO + off);
                mma16816(C[2*jp],   Ah[kk], Bl);
                mma16816(C[2*jp+1], Ah[kk], Bl + 2);
            }
        }
    }

    // epilogue: scale, RoPE (Q/K), bf16 hi/lo split to (B,H,S,D)
    const int r0 = m0 + 16 * w + gid;
    const int r1 = r0 + 8;
    int b_ = r0 >> 11, s0 = r0 & 2047, s1 = r1 & 2047;
    #pragma unroll
    for (int j = 0; j < 16; j++) {
        int colg = n0 + 8 * j + 2 * tig;
        int h = colg >> 7, d = colg & 127;
        float o00 = C[j][0] * scale, o01 = C[j][1] * scale;
        float o10 = C[j][2] * scale, o11 = C[j][3] * scale;
        if (mi < 2) {
            int t2 = d >> 1;
            float f = expf((float)t2 * -0.14391157f);
            float si0, co0, si1, co1;
            sincosf((float)s0 * f, &si0, &co0);
            sincosf((float)s1 * f, &si1, &co1);
            float a = o00 * co0 - o01 * si0, b2 = o00 * si0 + o01 * co0;
            o00 = a; o01 = b2;
            a = o10 * co1 - o11 * si1; b2 = o10 * si1 + o11 * co1;
            o10 = a; o11 = b2;
        }
        size_t oi0 = (((size_t)(b_ * HH + h) * SS + s0) * DD + d);
        size_t oi1 = (((size_t)(b_ * HH + h) * SS + s1) * DD + d);
        __nv_bfloat16 h00 = __float2bfloat16(o00), h01 = __float2bfloat16(o01);
        __nv_bfloat16 h10 = __float2bfloat16(o10), h11 = __float2bfloat16(o11);
        __nv_bfloat162 p0 = __halves2bfloat162(h00, h01);
        __nv_bfloat162 p1 = __halves2bfloat162(h10, h11);
        *(uint32_t*)(Oh_ + oi0) = *(uint32_t*)&p0;
        *(uint32_t*)(Oh_ + oi1) = *(uint32_t*)&p1;
        *(uint32_t*)(Ol_ + oi0) = pack_bf2(o00 - __bfloat162float(h00), o01 - __bfloat162float(h01));
        *(uint32_t*)(Ol_ + oi1) = pack_bf2(o10 - __bfloat162float(h10), o11 - __bfloat162float(h11));
    }
}

// =============== bf16x3 tensor-core GEMM (pipelined) ========================
// MODE 4: gelu(acc + bias) -> bf16 hi/lo               (fc1)
// MODE 6: split-K partial: fp32 to out + blockIdx.x*M*N, k in [bx*kspl, +kspl)
template<int MODE, bool AG, bool HALFM>
__global__ __launch_bounds__(256)
void mm3(const __nv_bfloat16* __restrict__ Ahi, const __nv_bfloat16* __restrict__ Alo,
         const __nv_bfloat16* __restrict__ Bhi, const __nv_bfloat16* __restrict__ Blo,
         const float* __restrict__ bias, const float* __restrict__ resid,
         float* __restrict__ out,
         __nv_bfloat16* __restrict__ ohi, __nv_bfloat16* __restrict__ olo,
         int M, int N, int K, int kspl, float qscale)
{
    extern __shared__ char sm[];
    uint32_t sb = smem_u32(sm);
    constexpr int MT = HALFM ? 64 : 128;
    constexpr int NJ = HALFM ? 8 : 16;
    const int tid = threadIdx.x;
    const int w = tid >> 5, ln = tid & 31;
    const int tig = ln & 3, gid = ln >> 2;
    const int wr = HALFM ? (w & 3) : w;
    const int wc = HALFM ? (w >> 2) * 64 : 0;
    const int m0 = blockIdx.y * MT;
    const int n0 = (MODE == 6) ? 0 : blockIdx.x * 128;
    const int kb = (MODE == 6) ? blockIdx.x * kspl : 0;
    const int ke = (MODE == 6) ? kb + kspl : K;
    const int niter = (ke - kb) >> 6;

    float C[NJ][4];
    #pragma unroll
    for (int j = 0; j < NJ; j++)
        #pragma unroll
        for (int e = 0; e < 4; e++) C[j][e] = 0.f;

    const int arow = 16 * wr + ((ln >> 3) & 1) * 8 + (ln & 7);
    const int akb  = (ln >> 4) * 16;
    const int brow = ((ln >> 3) & 1) * 8 + (ln & 7);
    const int bcb  = (ln >> 4) << 4;

    // prologue: prefetch iter 0
    {
        int k0 = kb;
        for (int f = tid; f < MT * 8; f += 256) {
            int r = f >> 3, seg = f & 7;
            size_t g;
            if (!AG) {
                g = (size_t)(m0 + r) * K + k0 + seg * 8;
            } else {
                int rr = m0 + r;
                int b_ = rr >> 11, s_ = rr & 2047;
                int kk = k0 + seg * 8;
                g = ((size_t)(b_ * HH + (kk >> 7)) * SS + s_) * DD + (kk & 127);
            }
            uint32_t so = aoff(r, seg * 16);
            cp16(sb + MM3_AHI + so, Ahi + g);
            cp16(sb + MM3_ALO + so, Alo + g);
        }
        for (int f = tid; f < 1024; f += 256) {
            int r = f >> 4, seg = f & 15;
            size_t g = (size_t)(k0 + r) * N + n0 + seg * 8;
            uint32_t so = boff(r, seg * 16);
            cp16(sb + MM3_BHI + so, Bhi + g);
            cp16(sb + MM3_BLO + so, Blo + g);
        }
        CP_COMMIT();
    }

    for (int it = 0; it < niter; it++) {
        uint32_t st = (uint32_t)(it & 1) * MM3_STAGE;
        __syncthreads();
        if (it + 1 < niter) {
            int k0 = kb + (it + 1) * 64;
            uint32_t stn = (uint32_t)((it + 1) & 1) * MM3_STAGE;
            for (int f = tid; f < MT * 8; f += 256) {
                int r = f >> 3, seg = f & 7;
                size_t g;
                if (!AG) {
                    g = (size_t)(m0 + r) * K + k0 + seg * 8;
                } else {
                    int rr = m0 + r;
                    int b_ = rr >> 11, s_ = rr & 2047;
                    int kk = k0 + seg * 8;
                    g = ((size_t)(b_ * HH + (kk >> 7)) * SS + s_) * DD + (kk & 127);
                }
                uint32_t so = aoff(r, seg * 16);
                cp16(sb + stn + MM3_AHI + so, Ahi + g);
                cp16(sb + stn + MM3_ALO + so, Alo + g);
            }
            for (int f = tid; f < 1024; f += 256) {
                int r = f >> 4, seg = f & 15;
                size_t g = (size_t)(k0 + r) * N + n0 + seg * 8;
                uint32_t so = boff(r, seg * 16);
                cp16(sb + stn + MM3_BHI + so, Bhi + g);
                cp16(sb + stn + MM3_BLO + so, Blo + g);
            }
            CP_COMMIT();
            CP_WAIT(1);
        } else {
            CP_WAIT(0);
        }
        __syncthreads();

        uint32_t Ah[4][4], Al[4][4];
        #pragma unroll
        for (int kk = 0; kk < 4; kk++) {
            uint32_t off = aoff(arow, kk * 32 + akb);
            ldsm_x4(Ah[kk], sb + st + MM3_AHI + off);
            ldsm_x4(Al[kk], sb + st + MM3_ALO + off);
        }
        #pragma unroll
        for (int jp = 0; jp < NJ / 2; jp++) {
            int ncb = (wc + 16 * jp) * 2;
            #pragma unroll
            for (int kk = 0; kk < 4; kk++) {
                uint32_t off = boff(16 * kk + brow, ncb + bcb);
                uint32_t Bh[4], Bl[4];
                ldsm_x4_t(Bh, sb + st + MM3_BHI + off);
                mma16816(C[2*jp],   Ah[kk], Bh);
                mma16816(C[2*jp+1], Ah[kk], Bh + 2);
                mma16816(C[2*jp],   Al[kk], Bh);
                mma16816(C[2*jp+1], Al[kk], Bh + 2);
                ldsm_x4_t(Bl, sb + st + MM3_BLO + off);
                mma16816(C[2*jp],   Ah[kk], Bl);
                mma16816(C[2*jp+1], Ah[kk], Bl + 2);
            }
        }
    }

    const int r0 = m0 + 16 * wr + gid;
    const int r1 = r0 + 8;
    if (MODE == 6) {
        float* po = out + (size_t)blockIdx.x * M * N;
        #pragma unroll
        for (int j = 0; j < NJ; j++) {
            int colg = wc + 8 * j + 2 * tig;
            size_t i0 = (size_t)r0 * N + colg;
            size_t i1 = (size_t)r1 * N + colg;
            *(float2*)(po + i0) = make_float2(C[j][0], C[j][1]);
            *(float2*)(po + i1) = make_float2(C[j][2], C[j][3]);
        }
    } else if (MODE == 4) {
        #pragma unroll
        for (int j = 0; j < NJ; j++) {
            int colg = n0 + wc + 8 * j + 2 * tig;
            size_t i0 = (size_t)r0 * N + colg;
            size_t i1 = (size_t)r1 * N + colg;
            float v00 = C[j][0], v01 = C[j][1], v10 = C[j][2], v11 = C[j][3];
            float b0 = bias[colg], b1 = bias[colg + 1];
            v00 += b0; v01 += b1; v10 += b0; v11 += b1;
            v00 = 0.5f * v00 * (1.0f + erff(v00 * 0.70710678f));
            v01 = 0.5f * v01 * (1.0f + erff(v01 * 0.70710678f));
            v10 = 0.5f * v10 * (1.0f + erff(v10 * 0.70710678f));
            v11 = 0.5f * v11 * (1.0f + erff(v11 * 0.70710678f));
            __nv_bfloat16 h00 = __float2bfloat16(v00), h01 = __float2bfloat16(v01);
            __nv_bfloat16 h10 = __float2bfloat16(v10), h11 = __float2bfloat16(v11);
            __nv_bfloat162 p0 = __halves2bfloat162(h00, h01);
            __nv_bfloat162 p1 = __halves2bfloat162(h10, h11);
            *(uint32_t*)(ohi + i0) = *(uint32_t*)&p0;
            *(uint32_t*)(ohi + i1) = *(uint32_t*)&p1;
            *(uint32_t*)(olo + i0) = pack_bf2(v00 - __bfloat162float(h00), v01 - __bfloat162float(h01));
            *(uint32_t*)(olo + i1) = pack_bf2(v10 - __bfloat162float(h10), v11 - __bfloat162float(h11));
        }
    }
}

// ============== mma.sync flash attention (bf16x3, cp.async double-buffer) ===
// 1-D grid of 512: bid>>5 = m-tile index (DESCENDING work: m0=(15-mt)*128),
// bid&31 = (b,h). Globally-descending nk => near-LPT block scheduling.
#define KHI_OFF 0u
#define KLO_OFF 16384u
#define VHI_OFF 32768u
#define VLO_OFF 49152u
#define FA_STAGE 65536u
#define FA_SMEM 131072

__device__ __forceinline__ uint32_t fa_off(int r, int cbyte) {
    return (uint32_t)(r * 256 + (cbyte ^ ((r & 7) << 4)));
}

__global__ __launch_bounds__(256, 1)
void fa_mma(const __nv_bfloat16* __restrict__ qhi, const __nv_bfloat16* __restrict__ qlo,
            const __nv_bfloat16* __restrict__ khi, const __nv_bfloat16* __restrict__ klo,
            const __nv_bfloat16* __restrict__ vhi, const __nv_bfloat16* __restrict__ vlo,
            __nv_bfloat16* __restrict__ Ohi, __nv_bfloat16* __restrict__ Olo)
{
    extern __shared__ char sm[];
    uint32_t sb = smem_u32(sm);
    const int tid = threadIdx.x;
    const int w = tid >> 5, ln = tid & 31;
    const int tig = ln & 3, gid = ln >> 2;
    const int bid = blockIdx.x;
    const int m0 = (15 - (bid >> 5)) * 128;   // globally descending work
    const int bh = bid & 31;
    const size_t base = (size_t)bh * SS * DD;

    // ---- stage Q tile through smem (regions overwritten later by K/V) ----
    for (int f = tid; f < 2048; f += 256) {
        int r = f >> 4, c16 = f & 15;
        size_t g = base + (size_t)(m0 + r) * DD + c16 * 8;
        uint32_t so = fa_off(r, c16 * 16);
        *(uint4*)(sm + so)              = *(const uint4*)(qhi + g);
        *(uint4*)(sm + FA_STAGE + so)   = *(const uint4*)(qlo + g);
    }
    __syncthreads();
    uint32_t Qh[8][4], Ql[8][4];
    {
        int row = 16 * w + ((ln >> 3) & 1) * 8 + (ln & 7);
        int kb0 = (ln >> 4) * 16;
        #pragma unroll
        for (int kk = 0; kk < 8; kk++) {
            uint32_t off = fa_off(row, kk * 32 + kb0);
            ldsm_x4(Qh[kk], sb + off);
            ldsm_x4(Ql[kk], sb + FA_STAGE + off);
        }
    }
    __syncthreads();

    float Oa[16][4];
    #pragma unroll
    for (int j = 0; j < 16; j++)
        #pragma unroll
        for (int e = 0; e < 4; e++) Oa[j][e] = 0.f;
    float m0r = -1e30f, m1r = -1e30f, l0r = 0.f, l1r = 0.f;

    const int grow0 = m0 + 16 * w + gid;
    const int grow1 = grow0 + 8;
    const int nk = m0 / 64 + 2;

    // ---- prologue: prefetch tile 0 into stage 0 ----
    {
        for (int f = tid; f < 1024; f += 256) {
            int r = f >> 4, c16 = f & 15;
            size_t g = base + (size_t)r * DD + c16 * 8;
            uint32_t so = fa_off(r, c16 * 16);
            cp16(sb + KHI_OFF + so, khi + g);
            cp16(sb + KLO_OFF + so, klo + g);
            cp16(sb + VHI_OFF + so, vhi + g);
            cp16(sb + VLO_OFF + so, vlo + g);
        }
        CP_COMMIT();
    }

    for (int t = 0; t < nk; t++) {
        int n0 = t * 64;
        uint32_t st = (uint32_t)(t & 1) * FA_STAGE;
        __syncthreads();   // everyone done with the stage we're about to overwrite
        if (t + 1 < nk) {
            uint32_t stn = (uint32_t)((t + 1) & 1) * FA_STAGE;
            int n1 = n0 + 64;
            for (int f = tid; f < 1024; f += 256) {
                int r = f >> 4, c16 = f & 15;
                size_t g = base + (size_t)(n1 + r) * DD + c16 * 8;
                uint32_t so = fa_off(r, c16 * 16);
                cp16(sb + stn + KHI_OFF + so, khi + g);
                cp16(sb + stn + KLO_OFF + so, klo + g);
                cp16(sb + stn + VHI_OFF + so, vhi + g);
                cp16(sb + stn + VLO_OFF + so, vlo + g);
            }
            CP_COMMIT();
            CP_WAIT(1);
        } else {
            CP_WAIT(0);
        }
        __syncthreads();   // current stage data visible to all

        // ---- S = Q K^T (3-term) ----
        float S[8][4];
        #pragma unroll
        for (int j = 0; j < 8; j++)
            #pragma unroll
            for (int e = 0; e < 4; e++) S[j][e] = 0.f;
        {
            int brow = ((ln >> 4) << 3) + (ln & 7);
            int bkb  = ((ln >> 3) & 1) << 4;
            #pragma unroll
            for (int jp = 0; jp < 4; jp++) {
                #pragma unroll
                for (int kk = 0; kk < 8; kk++) {
                    int r_ = 16 * jp + brow;
                    uint32_t off = fa_off(r_, kk * 32 + bkb);
                    uint32_t Bh[4], Bl[4];
                    ldsm_x4(Bh, sb + st + KHI_OFF + off);
                    mma16816(S[2*jp],   Qh[kk], Bh);
                    mma16816(S[2*jp+1], Qh[kk], Bh + 2);
                    mma16816(S[2*jp],   Ql[kk], Bh);
                    mma16816(S[2*jp+1], Ql[kk], Bh + 2);
                    ldsm_x4(Bl, sb + st + KLO_OFF + off);
                    mma16816(S[2*jp],   Qh[kk], Bl);
                    mma16816(S[2*jp+1], Qh[kk], Bl + 2);
                }
            }
        }

        // ---- causal mask (only near-diagonal tiles) ----
        if (n0 + 63 > m0 + 16 * w) {
            #pragma unroll
            for (int j = 0; j < 8; j++) {
                int c = n0 + 8 * j + 2 * tig;
                if (c     > grow0) S[j][0] = -1e30f;
                if (c + 1 > grow0) S[j][1] = -1e30f;
                if (c     > grow1) S[j][2] = -1e30f;
                if (c + 1 > grow1) S[j][3] = -1e30f;
            }
        }

        // ---- online softmax ----
        float mx0 = -1e30f, mx1 = -1e30f;
        #pragma unroll
        for (int j = 0; j < 8; j++) {
            mx0 = fmaxf(mx0, fmaxf(S[j][0], S[j][1]));
            mx1 = fmaxf(mx1, fmaxf(S[j][2], S[j][3]));
        }
        mx0 = fmaxf(mx0, __shfl_xor_sync(0xffffffffu, mx0, 1));
        mx0 = fmaxf(mx0, __shfl_xor_sync(0xffffffffu, mx0, 2));
        mx1 = fmaxf(mx1, __shfl_xor_sync(0xffffffffu, mx1, 1));
        mx1 = fmaxf(mx1, __shfl_xor_sync(0xffffffffu, mx1, 2));
        float mn0 = fmaxf(m0r, mx0), mn1 = fmaxf(m1r, mx1);
        bool nochg = (mn0 == m0r) && (mn1 == m1r);
        float a0 = nochg ? 1.f : __expf(m0r - mn0);
        float a1 = nochg ? 1.f : __expf(m1r - mn1);
        m0r = mn0; m1r = mn1;
        l0r *= a0; l1r *= a1;

        uint32_t Phi[4][4], Plo[4][4];
        float ls0 = 0.f, ls1 = 0.f;
        #pragma unroll
        for (int j = 0; j < 8; j++) {
            float p0 = __expf(S[j][0] - mn0);
            float p1 = __expf(S[j][1] - mn0);
            float p2 = __expf(S[j][2] - mn1);
            float p3 = __expf(S[j][3] - mn1);
            ls0 += p0 + p1; ls1 += p2 + p3;
            __nv_bfloat16 h0 = __float2bfloat16(p0);
            __nv_bfloat16 h1 = __float2bfloat16(p1);
            __nv_bfloat16 h2 = __float2bfloat16(p2);
            __nv_bfloat16 h3 = __float2bfloat16(p3);
            int kk = j >> 1, q = (j & 1) * 2;
            __nv_bfloat162 hh01 = __halves2bfloat162(h0, h1);
            __nv_bfloat162 hh23 = __halves2bfloat162(h2, h3);
            Phi[kk][q]     = *(uint32_t*)&hh01;
            Phi[kk][q + 1] = *(uint32_t*)&hh23;
            Plo[kk][q]     = pack_bf2(p0 - __bfloat162float(h0), p1 - __bfloat162float(h1));
            Plo[kk][q + 1] = pack_bf2(p2 - __bfloat162float(h2), p3 - __bfloat162float(h3));
        }
        l0r += ls0; l1r += ls1;

        if (!__all_sync(0xffffffffu, nochg)) {
            #pragma unroll
            for (int j = 0; j < 16; j++) {
                Oa[j][0] *= a0; Oa[j][1] *= a0;
                Oa[j][2] *= a1; Oa[j][3] *= a1;
            }
        }

        // ---- O += P V (3-term) ----
        {
            int vrow = ((ln >> 3) & 1) * 8 + (ln & 7);
            int vcb  = (ln >> 4) << 4;
            #pragma unroll
            for (int jp = 0; jp < 8; jp++) {
                #pragma unroll
                for (int kk = 0; kk < 4; kk++) {
                    int r_ = 16 * kk + vrow;
                    uint32_t off = fa_off(r_, 32 * jp + vcb);
                    uint32_t Bh[4], Bl[4];
                    ldsm_x4_t(Bh, sb + st + VHI_OFF + off);
                    mma16816(Oa[2*jp],   Phi[kk], Bh);
                    mma16816(Oa[2*jp+1], Phi[kk], Bh + 2);
                    mma16816(Oa[2*jp],   Plo[kk], Bh);
                    mma16816(Oa[2*jp+1], Plo[kk], Bh + 2);
                    ldsm_x4_t(Bl, sb + st + VLO_OFF + off);
                    mma16816(Oa[2*jp],   Phi[kk], Bl);
                    mma16816(Oa[2*jp+1], Phi[kk], Bl + 2);
                }
            }
        }
    }

    // ---- finalize: reduce l, normalize, split hi/lo, store ----
    l0r += __shfl_xor_sync(0xffffffffu, l0r, 1);
    l0r += __shfl_xor_sync(0xffffffffu, l0r, 2);
    l1r += __shfl_xor_sync(0xffffffffu, l1r, 1);
    l1r += __shfl_xor_sync(0xffffffffu, l1r, 2);
    float inv0 = 1.0f / l0r, inv1 = 1.0f / l1r;
    #pragma unroll
    for (int j = 0; j < 16; j++) {
        int col = 8 * j + 2 * tig;
        size_t i0 = base + (size_t)grow0 * DD + col;
        size_t i1 = base + (size_t)grow1 * DD + col;
        float v00 = Oa[j][0] * inv0, v01 = Oa[j][1] * inv0;
        float v10 = Oa[j][2] * inv1, v11 = Oa[j][3] * inv1;
        __nv_bfloat16 h00 = __float2bfloat16(v00), h01 = __float2bfloat16(v01);
        __nv_bfloat16 h10 = __float2bfloat16(v10), h11 = __float2bfloat16(v11);
        __nv_bfloat162 p0 = __halves2bfloat162(h00, h01);
        __nv_bfloat162 p1 = __halves2bfloat162(h10, h11);
        *(uint32_t*)(Ohi + i0) = *(uint32_t*)&p0;
        *(uint32_t*)(Ohi + i1) = *(uint32_t*)&p1;
        *(uint32_t*)(Olo + i0) = pack_bf2(v00 - __bfloat162float(h00), v01 - __bfloat162float(h01));
        *(uint32_t*)(Olo + i1) = pack_bf2(v10 - __bfloat162float(h10), v11 - __bfloat162float(h11));
    }
}

// ---------------- launch -----------------------------------------------------
extern "C" void kernel_launch(void* const* d_in, const int* in_sizes, int n_in,
                              void* d_out, int out_size) {
    const float* x        = (const float*)d_in[0];
    const float* W_q      = (const float*)d_in[1];
    const float* W_k      = (const float*)d_in[2];
    const float* W_v      = (const float*)d_in[3];
    const float* W_o      = (const float*)d_in[4];
    const float* ln_attn_g= (const float*)d_in[5];
    const float* ln_attn_b= (const float*)d_in[6];
    const float* fc1_w    = (const float*)d_in[7];
    const float* fc1_b    = (const float*)d_in[8];
    const float* fc2_w    = (const float*)d_in[9];
    const float* fc2_b    = (const float*)d_in[10];
    const float* ln_mlp_g = (const float*)d_in[11];
    const float* ln_mlp_b = (const float*)d_in[12];
    float* out = (float*)d_out;

    float *x2, *part;
    __nv_bfloat16 *h1h, *h1l, *h2h, *h2l, *th, *tl, *aoh, *aol;
    __nv_bfloat16 *qhi, *qlo, *khi, *klo, *vhi, *vlo;
    __nv_bfloat16 *wqh, *wql, *wkh, *wkl, *wvh, *wvl, *woh, *wol, *f1h, *f1l, *f2h, *f2l;
    cudaGetSymbolAddress((void**)&x2,  g_x2);
    cudaGetSymbolAddress((void**)&part, g_part);
    cudaGetSymbolAddress((void**)&h1h, g_h1h); cudaGetSymbolAddress((void**)&h1l, g_h1l);
    cudaGetSymbolAddress((void**)&h2h, g_h2h); cudaGetSymbolAddress((void**)&h2l, g_h2l);
    cudaGetSymbolAddress((void**)&th,  g_th);  cudaGetSymbolAddress((void**)&tl,  g_tl);
    cudaGetSymbolAddress((void**)&aoh, g_aoh); cudaGetSymbolAddress((void**)&aol, g_aol);
    cudaGetSymbolAddress((void**)&qhi, g_qhi); cudaGetSymbolAddress((void**)&qlo, g_qlo);
    cudaGetSymbolAddress((void**)&khi, g_khi); cudaGetSymbolAddress((void**)&klo, g_klo);
    cudaGetSymbolAddress((void**)&vhi, g_vhi); cudaGetSymbolAddress((void**)&vlo, g_vlo);
    cudaGetSymbolAddress((void**)&wqh, g_wqh); cudaGetSymbolAddress((void**)&wql, g_wql);
    cudaGetSymbolAddress((void**)&wkh, g_wkh); cudaGetSymbolAddress((void**)&wkl, g_wkl);
    cudaGetSymbolAddress((void**)&wvh, g_wvh); cudaGetSymbolAddress((void**)&wvl, g_wvl);
    cudaGetSymbolAddress((void**)&woh, g_woh); cudaGetSymbolAddress((void**)&wol, g_wol);
    cudaGetSymbolAddress((void**)&f1h, g_f1h); cudaGetSymbolAddress((void**)&f1l, g_f1l);
    cudaGetSymbolAddress((void**)&f2h, g_f2h); cudaGetSymbolAddress((void**)&f2l, g_f2l);

    // 0) split all six weights to bf16 hi/lo in one launch
    split6<<<1152, 256>>>(W_q, W_k, W_v, W_o, fc1_w, fc2_w,
                          wqh, wql, wkh, wkl, wvh, wvl,
                          woh, wol, f1h, f1l, f2h, f2l);

    // 1) LN -> bf16 hi/lo
    ln_kernel<<<MM/8, 256>>>(x, ln_attn_g, ln_attn_b, h1h, h1l);

    // 2) fused QKV projection (pipelined tensor core, fused RoPE/scale/split)
    const float qscale = 0.08838834764831845f;  // 1/sqrt(128)
    cudaFuncSetAttribute(qkv_mm, cudaFuncAttributeMaxDynamicSharedMemorySize, MM3_SMEM);
    qkv_mm<<<dim3(48, MM/128), 256, MM3_SMEM>>>(qscale);

    // 3) causal flash attention (1-D grid, globally-descending work order)
    cudaFuncSetAttribute(fa_mma, cudaFuncAttributeMaxDynamicSharedMemorySize, FA_SMEM);
    fa_mma<<<512, 256, FA_SMEM>>>(qhi, qlo, khi, klo, vhi, vlo, aoh, aol);

    // 4) O-projection via split-K (4 x 512, pipelined), then reduce + residual
    cudaFuncSetAttribute(mm3<6,true,true>,  cudaFuncAttributeMaxDynamicSharedMemorySize, MM3_SMEM);
    cudaFuncSetAttribute(mm3<6,false,true>, cudaFuncAttributeMaxDynamicSharedMemorySize, MM3_SMEM);
    cudaFuncSetAttribute(mm3<4,false,true>, cudaFuncAttributeMaxDynamicSharedMemorySize, MM3_SMEM);
    mm3<6,true,true><<<dim3(4, MM/64), 256, MM3_SMEM>>>(aoh, aol, woh, wol, nullptr, nullptr, part, nullptr, nullptr, MM, EE, HD, 512, 1.0f);
    reduce_k<4,false><<<(MM*EE)/1024, 256>>>(part, x, nullptr, x2);

    // 5) LN -> bf16 hi/lo
    ln_kernel<<<MM/8, 256>>>(x2, ln_mlp_g, ln_mlp_b, h2h, h2l);

    // 6) MLP: fc1 (pipelined, HALFM, fused bias+GELU+split), fc2 split-K 4x128
    mm3<4,false,true><<<dim3(DHH/128, MM/64), 256, MM3_SMEM>>>(h2h, h2l, f1h, f1l, fc1_b, nullptr, nullptr, th, tl, MM, DHH, EE, EE, 1.0f);
    mm3<6,false,true><<<dim3(4, MM/64), 256, MM3_SMEM>>>(th, tl, f2h, f2l, nullptr, nullptr, part, nullptr, nullptr, MM, EE, DHH, 128, 1.0f);
    reduce_k<4,true><<<(MM*EE)/1024, 256>>>(part, x2, fc2_b, out);
}

// round 13
// speedup vs baseline: 4.0265x; 1.0883x over previous
#include <cuda_runtime.h>
#include <cuda_bf16.h>
#include <math.h>
#include <stdint.h>

#define BB 2
#define SS 2048
#define EE 128
#define HH 16
#define DD 128
#define DHH 512
#define MM (BB*SS)     // 4096 rows
#define HD (HH*DD)     // 2048

// ---------------- scratch (static __device__, no allocation) ----------------
__device__ float g_x2[MM*EE];
__device__ float g_part[4*MM*EE];
__device__ __nv_bfloat16 g_h1h[MM*EE],  g_h1l[MM*EE];
__device__ __nv_bfloat16 g_h2h[MM*EE],  g_h2l[MM*EE];
__device__ __nv_bfloat16 g_th [MM*DHH], g_tl [MM*DHH];
__device__ __nv_bfloat16 g_aoh[MM*HD],  g_aol[MM*HD];
__device__ __nv_bfloat16 g_qhi[MM*HD],  g_qlo[MM*HD];
__device__ __nv_bfloat16 g_khi[MM*HD],  g_klo[MM*HD];
__device__ __nv_bfloat16 g_vhi[MM*HD],  g_vlo[MM*HD];
__device__ __nv_bfloat16 g_wqh[EE*HD],  g_wql[EE*HD];
__device__ __nv_bfloat16 g_wkh[EE*HD],  g_wkl[EE*HD];
__device__ __nv_bfloat16 g_wvh[EE*HD],  g_wvl[EE*HD];
__device__ __nv_bfloat16 g_woh[HD*EE],  g_wol[HD*EE];
__device__ __nv_bfloat16 g_f1h[EE*DHH], g_f1l[EE*DHH];
__device__ __nv_bfloat16 g_f2h[DHH*EE], g_f2l[DHH*EE];

// ======================= warp MMA helpers (baseline PTX) =====================
__device__ __forceinline__ uint32_t smem_u32(const void* p) {
    uint32_t a;
    asm("{ .reg .u64 t; cvta.to.shared.u64 t, %1; cvt.u32.u64 %0, t; }"
        : "=r"(a) : "l"(p));
    return a;
}
__device__ __forceinline__ void mma16816(float* c, const uint32_t* a, const uint32_t* b) {
    asm volatile(
        "mma.sync.aligned.m16n8k16.row.col.f32.bf16.bf16.f32 "
        "{%0,%1,%2,%3}, {%4,%5,%6,%7}, {%8,%9}, {%0,%1,%2,%3};"
        : "+f"(c[0]), "+f"(c[1]), "+f"(c[2]), "+f"(c[3])
        : "r"(a[0]), "r"(a[1]), "r"(a[2]), "r"(a[3]), "r"(b[0]), "r"(b[1]));
}
__device__ __forceinline__ void ldsm_x4(uint32_t* r, uint32_t addr) {
    asm volatile("ldmatrix.sync.aligned.m8n8.x4.shared.b16 {%0,%1,%2,%3}, [%4];"
        : "=r"(r[0]), "=r"(r[1]), "=r"(r[2]), "=r"(r[3]) : "r"(addr));
}
__device__ __forceinline__ void ldsm_x4_t(uint32_t* r, uint32_t addr) {
    asm volatile("ldmatrix.sync.aligned.m8n8.x4.trans.shared.b16 {%0,%1,%2,%3}, [%4];"
        : "=r"(r[0]), "=r"(r[1]), "=r"(r[2]), "=r"(r[3]) : "r"(addr));
}
__device__ __forceinline__ uint32_t pack_bf2(float a, float b) {
    __nv_bfloat162 h = __halves2bfloat162(__float2bfloat16(a), __float2bfloat16(b));
    return *(uint32_t*)&h;
}
__device__ __forceinline__ void cp16(uint32_t smem_addr, const void* gptr) {
    asm volatile("cp.async.cg.shared.global [%0], [%1], 16;"
        :: "r"(smem_addr), "l"(gptr) : "memory");
}
#define CP_COMMIT() asm volatile("cp.async.commit_group;" ::: "memory")
#define CP_WAIT(n)  asm volatile("cp.async.wait_group %0;" :: "n"(n) : "memory")

// 256B-row swizzle (B tiles, FA tiles); 128B-row swizzle (A tiles)
__device__ __forceinline__ uint32_t boff(int r, int cbyte) {
    return (uint32_t)(r * 256 + (cbyte ^ ((r & 7) << 4)));
}
__device__ __forceinline__ uint32_t aoff(int r, int cbyte) {
    return (uint32_t)(r * 128 + (cbyte ^ ((r & 7) << 4)));
}

// ---------------- fp32 -> bf16 hi/lo split: all six weights in ONE launch ----
__global__ void split6(const float* __restrict__ a0, const float* __restrict__ a1,
                       const float* __restrict__ a2, const float* __restrict__ a3,
                       const float* __restrict__ a4, const float* __restrict__ a5,
                       __nv_bfloat16* h0, __nv_bfloat16* l0,
                       __nv_bfloat16* h1, __nv_bfloat16* l1,
                       __nv_bfloat16* h2, __nv_bfloat16* l2,
                       __nv_bfloat16* h3, __nv_bfloat16* l3,
                       __nv_bfloat16* h4, __nv_bfloat16* l4,
                       __nv_bfloat16* h5, __nv_bfloat16* l5) {
    const float* ws[6] = {a0, a1, a2, a3, a4, a5};
    __nv_bfloat16* hs[6] = {h0, h1, h2, h3, h4, h5};
    __nv_bfloat16* ls[6] = {l0, l1, l2, l3, l4, l5};
    int b = blockIdx.x, wi, off;
    if (b < 1024) { wi = b >> 8;       off = (b & 255) * 1024; }
    else          { b -= 1024; wi = 4 + (b >> 6); off = (b & 63) * 1024; }
    int i = off + threadIdx.x * 4;
    float4 v = *(const float4*)(ws[wi] + i);
    __nv_bfloat16 b0 = __float2bfloat16(v.x), b1 = __float2bfloat16(v.y);
    __nv_bfloat16 b2 = __float2bfloat16(v.z), b3 = __float2bfloat16(v.w);
    __nv_bfloat162 hh01 = __halves2bfloat162(b0, b1), hh23 = __halves2bfloat162(b2, b3);
    *(uint2*)(hs[wi] + i) = make_uint2(*(uint32_t*)&hh01, *(uint32_t*)&hh23);
    uint32_t l01 = pack_bf2(v.x - __bfloat162float(b0), v.y - __bfloat162float(b1));
    uint32_t l23 = pack_bf2(v.z - __bfloat162float(b2), v.w - __bfloat162float(b3));
    *(uint2*)(ls[wi] + i) = make_uint2(l01, l23);
}

// ---------------- split-K reduce: out = resid (+bias) + sum partials --------
template<int NS, bool BIAS>
__global__ void reduce_k(const float* __restrict__ part, const float* __restrict__ resid,
                         const float* __restrict__ bias, float* __restrict__ out) {
    int i = (blockIdx.x * 256 + threadIdx.x) * 4;
    float4 acc = *(const float4*)(resid + i);
    if (BIAS) {
        float4 bv = *(const float4*)(bias + (i & (EE - 1)));
        acc.x += bv.x; acc.y += bv.y; acc.z += bv.z; acc.w += bv.w;
    }
    #pragma unroll
    for (int z = 0; z < NS; z++) {
        float4 p = *(const float4*)(part + (size_t)z * (MM * EE) + i);
        acc.x += p.x; acc.y += p.y; acc.z += p.z; acc.w += p.w;
    }
    *(float4*)(out + i) = acc;
}

// ---------------- LayerNorm: one warp per row, bf16 hi/lo out ---------------
__global__ void ln_kernel(const float* __restrict__ x, const float* __restrict__ g,
                          const float* __restrict__ b,
                          __nv_bfloat16* __restrict__ ohi, __nv_bfloat16* __restrict__ olo) {
    int warp = threadIdx.x >> 5, lane = threadIdx.x & 31;
    int row = blockIdx.x * 8 + warp;
    float4 v = ((const float4*)(x + (size_t)row * EE))[lane];
    float s = v.x + v.y + v.z + v.w;
    #pragma unroll
    for (int o = 16; o; o >>= 1) s += __shfl_xor_sync(0xffffffffu, s, o);
    float mu = s * (1.0f / EE);
    float d0 = v.x - mu, d1 = v.y - mu, d2 = v.z - mu, d3 = v.w - mu;
    float q = d0*d0 + d1*d1 + d2*d2 + d3*d3;
    #pragma unroll
    for (int o = 16; o; o >>= 1) q += __shfl_xor_sync(0xffffffffu, q, o);
    float inv = rsqrtf(q * (1.0f / EE) + 1e-5f);
    float4 gg = ((const float4*)g)[lane];
    float4 bb = ((const float4*)b)[lane];
    float r0 = d0 * inv * gg.x + bb.x;
    float r1 = d1 * inv * gg.y + bb.y;
    float r2 = d2 * inv * gg.z + bb.z;
    float r3 = d3 * inv * gg.w + bb.w;
    __nv_bfloat16 h0 = __float2bfloat16(r0), h1 = __float2bfloat16(r1);
    __nv_bfloat16 h2 = __float2bfloat16(r2), h3 = __float2bfloat16(r3);
    __nv_bfloat162 hh01 = __halves2bfloat162(h0, h1), hh23 = __halves2bfloat162(h2, h3);
    size_t base = (size_t)row * EE + lane * 4;
    *(uint2*)(ohi + base) = make_uint2(*(uint32_t*)&hh01, *(uint32_t*)&hh23);
    uint32_t l01 = pack_bf2(r0 - __bfloat162float(h0), r1 - __bfloat162float(h1));
    uint32_t l23 = pack_bf2(r2 - __bfloat162float(h2), r3 - __bfloat162float(h3));
    *(uint2*)(olo + base) = make_uint2(l01, l23);
}

// =============== shared smem layout for projection GEMMs (2 stages) =========
#define MM3_AHI 0u
#define MM3_ALO 16384u
#define MM3_BHI 32768u
#define MM3_BLO 49152u
#define MM3_STAGE 65536u
#define MM3_SMEM 131072

// =============== fused QKV projection (pipelined, bf16x3) ===================
__global__ __launch_bounds__(256, 1)
void qkv_mm(float qscale)
{
    extern __shared__ char sm[];
    uint32_t sb = smem_u32(sm);
    const int tid = threadIdx.x;
    const int w = tid >> 5, ln = tid & 31;
    const int tig = ln & 3, gid = ln >> 2;
    const int mi = blockIdx.x >> 4;
    const int n0 = (blockIdx.x & 15) * 128;
    const int m0 = blockIdx.y * 128;
    const __nv_bfloat16* Bh_ = (mi == 0) ? g_wqh : (mi == 1) ? g_wkh : g_wvh;
    const __nv_bfloat16* Bl_ = (mi == 0) ? g_wql : (mi == 1) ? g_wkl : g_wvl;
    __nv_bfloat16* Oh_ = (mi == 0) ? g_qhi : (mi == 1) ? g_khi : g_vhi;
    __nv_bfloat16* Ol_ = (mi == 0) ? g_qlo : (mi == 1) ? g_klo : g_vlo;
    const float scale = (mi == 0) ? qscale : 1.0f;

    float C[16][4];
    #pragma unroll
    for (int j = 0; j < 16; j++)
        #pragma unroll
        for (int e = 0; e < 4; e++) C[j][e] = 0.f;

    const int arow = 16 * w + ((ln >> 3) & 1) * 8 + (ln & 7);
    const int akb  = (ln >> 4) * 16;
    const int brow = ((ln >> 3) & 1) * 8 + (ln & 7);
    const int bcb  = (ln >> 4) << 4;

    // prologue: prefetch k-iter 0 into stage 0
    for (int f = tid; f < 1024; f += 256) {
        int r = f >> 3, seg = f & 7;
        size_t g = (size_t)(m0 + r) * EE + seg * 8;
        uint32_t so = aoff(r, seg * 16);
        cp16(sb + MM3_AHI + so, g_h1h + g);
        cp16(sb + MM3_ALO + so, g_h1l + g);
    }
    for (int f = tid; f < 1024; f += 256) {
        int r = f >> 4, seg = f & 15;
        size_t g = (size_t)r * HD + n0 + seg * 8;
        uint32_t so = boff(r, seg * 16);
        cp16(sb + MM3_BHI + so, Bh_ + g);
        cp16(sb + MM3_BLO + so, Bl_ + g);
    }
    CP_COMMIT();

    #pragma unroll
    for (int it = 0; it < 2; it++) {
        uint32_t st = (uint32_t)(it & 1) * MM3_STAGE;
        __syncthreads();
        if (it == 0) {
            for (int f = tid; f < 1024; f += 256) {
                int r = f >> 3, seg = f & 7;
                size_t g = (size_t)(m0 + r) * EE + 64 + seg * 8;
                uint32_t so = aoff(r, seg * 16);
                cp16(sb + MM3_STAGE + MM3_AHI + so, g_h1h + g);
                cp16(sb + MM3_STAGE + MM3_ALO + so, g_h1l + g);
            }
            for (int f = tid; f < 1024; f += 256) {
                int r = f >> 4, seg = f & 15;
                size_t g = (size_t)(64 + r) * HD + n0 + seg * 8;
                uint32_t so = boff(r, seg * 16);
                cp16(sb + MM3_STAGE + MM3_BHI + so, Bh_ + g);
                cp16(sb + MM3_STAGE + MM3_BLO + so, Bl_ + g);
            }
            CP_COMMIT();
            CP_WAIT(1);
        } else {
            CP_WAIT(0);
        }
        __syncthreads();

        uint32_t Ah[4][4], Al[4][4];
        #pragma unroll
        for (int kk = 0; kk < 4; kk++) {
            uint32_t off = aoff(arow, kk * 32 + akb);
            ldsm_x4(Ah[kk], sb + st + MM3_AHI + off);
            ldsm_x4(Al[kk], sb + st + MM3_ALO + off);
        }
        #pragma unroll
        for (int jp = 0; jp < 8; jp++) {
            int ncb = 32 * jp;
            #pragma unroll
            for (int kk = 0; kk < 4; kk++) {
                uint32_t off = boff(16 * kk + brow, ncb + bcb);
                uint32_t Bh[4], Bl[4];
                ldsm_x4_t(Bh, sb + st + MM3_BHI + off);
                mma16816(C[2*jp],   Ah[kk], Bh);
                mma16816(C[2*jp+1], Ah[kk], Bh + 2);
                mma16816(C[2*jp],   Al[kk], Bh);
                mma16816(C[2*jp+1], Al[kk], Bh + 2);
                ldsm_x4_t(Bl, sb + st + MM3_BLO + off);
                mma16816(C[2*jp],   Ah[kk], Bl);
                mma16816(C[2*jp+1], Ah[kk], Bl + 2);
            }
        }
    }

    // epilogue: scale, RoPE (Q/K), bf16 hi/lo split to (B,H,S,D)
    const int r0 = m0 + 16 * w + gid;
    const int r1 = r0 + 8;
    int b_ = r0 >> 11, s0 = r0 & 2047, s1 = r1 & 2047;
    #pragma unroll
    for (int j = 0; j < 16; j++) {
        int colg = n0 + 8 * j + 2 * tig;
        int h = colg >> 7, d = colg & 127;
        float o00 = C[j][0] * scale, o01 = C[j][1] * scale;
        float o10 = C[j][2] * scale, o11 = C[j][3] * scale;
        if (mi < 2) {
            int t2 = d >> 1;
            float f = expf((float)t2 * -0.14391157f);
            float si0, co0, si1, co1;
            sincosf((float)s0 * f, &si0, &co0);
            sincosf((float)s1 * f, &si1, &co1);
            float a = o00 * co0 - o01 * si0, b2 = o00 * si0 + o01 * co0;
            o00 = a; o01 = b2;
            a = o10 * co1 - o11 * si1; b2 = o10 * si1 + o11 * co1;
            o10 = a; o11 = b2;
        }
        size_t oi0 = (((size_t)(b_ * HH + h) * SS + s0) * DD + d);
        size_t oi1 = (((size_t)(b_ * HH + h) * SS + s1) * DD + d);
        __nv_bfloat16 h00 = __float2bfloat16(o00), h01 = __float2bfloat16(o01);
        __nv_bfloat16 h10 = __float2bfloat16(o10), h11 = __float2bfloat16(o11);
        __nv_bfloat162 p0 = __halves2bfloat162(h00, h01);
        __nv_bfloat162 p1 = __halves2bfloat162(h10, h11);
        *(uint32_t*)(Oh_ + oi0) = *(uint32_t*)&p0;
        *(uint32_t*)(Oh_ + oi1) = *(uint32_t*)&p1;
        *(uint32_t*)(Ol_ + oi0) = pack_bf2(o00 - __bfloat162float(h00), o01 - __bfloat162float(h01));
        *(uint32_t*)(Ol_ + oi1) = pack_bf2(o10 - __bfloat162float(h10), o11 - __bfloat162float(h11));
    }
}

// =============== bf16x3 tensor-core GEMM (pipelined) ========================
// MODE 4: gelu(acc + bias) -> bf16 hi/lo               (fc1)
// MODE 6: split-K partial: fp32 to out + blockIdx.x*M*N, k in [bx*kspl, +kspl)
template<int MODE, bool AG, bool HALFM>
__global__ __launch_bounds__(256)
void mm3(const __nv_bfloat16* __restrict__ Ahi, const __nv_bfloat16* __restrict__ Alo,
         const __nv_bfloat16* __restrict__ Bhi, const __nv_bfloat16* __restrict__ Blo,
         const float* __restrict__ bias, const float* __restrict__ resid,
         float* __restrict__ out,
         __nv_bfloat16* __restrict__ ohi, __nv_bfloat16* __restrict__ olo,
         int M, int N, int K, int kspl, float qscale)
{
    extern __shared__ char sm[];
    uint32_t sb = smem_u32(sm);
    constexpr int MT = HALFM ? 64 : 128;
    constexpr int NJ = HALFM ? 8 : 16;
    const int tid = threadIdx.x;
    const int w = tid >> 5, ln = tid & 31;
    const int tig = ln & 3, gid = ln >> 2;
    const int wr = HALFM ? (w & 3) : w;
    const int wc = HALFM ? (w >> 2) * 64 : 0;
    const int m0 = blockIdx.y * MT;
    const int n0 = (MODE == 6) ? 0 : blockIdx.x * 128;
    const int kb = (MODE == 6) ? blockIdx.x * kspl : 0;
    const int ke = (MODE == 6) ? kb + kspl : K;
    const int niter = (ke - kb) >> 6;

    float C[NJ][4];
    #pragma unroll
    for (int j = 0; j < NJ; j++)
        #pragma unroll
        for (int e = 0; e < 4; e++) C[j][e] = 0.f;

    const int arow = 16 * wr + ((ln >> 3) & 1) * 8 + (ln & 7);
    const int akb  = (ln >> 4) * 16;
    const int brow = ((ln >> 3) & 1) * 8 + (ln & 7);
    const int bcb  = (ln >> 4) << 4;

    // prologue: prefetch iter 0
    {
        int k0 = kb;
        for (int f = tid; f < MT * 8; f += 256) {
            int r = f >> 3, seg = f & 7;
            size_t g;
            if (!AG) {
                g = (size_t)(m0 + r) * K + k0 + seg * 8;
            } else {
                int rr = m0 + r;
                int b_ = rr >> 11, s_ = rr & 2047;
                int kk = k0 + seg * 8;
                g = ((size_t)(b_ * HH + (kk >> 7)) * SS + s_) * DD + (kk & 127);
            }
            uint32_t so = aoff(r, seg * 16);
            cp16(sb + MM3_AHI + so, Ahi + g);
            cp16(sb + MM3_ALO + so, Alo + g);
        }
        for (int f = tid; f < 1024; f += 256) {
            int r = f >> 4, seg = f & 15;
            size_t g = (size_t)(k0 + r) * N + n0 + seg * 8;
            uint32_t so = boff(r, seg * 16);
            cp16(sb + MM3_BHI + so, Bhi + g);
            cp16(sb + MM3_BLO + so, Blo + g);
        }
        CP_COMMIT();
    }

    for (int it = 0; it < niter; it++) {
        uint32_t st = (uint32_t)(it & 1) * MM3_STAGE;
        __syncthreads();
        if (it + 1 < niter) {
            int k0 = kb + (it + 1) * 64;
            uint32_t stn = (uint32_t)((it + 1) & 1) * MM3_STAGE;
            for (int f = tid; f < MT * 8; f += 256) {
                int r = f >> 3, seg = f & 7;
                size_t g;
                if (!AG) {
                    g = (size_t)(m0 + r) * K + k0 + seg * 8;
                } else {
                    int rr = m0 + r;
                    int b_ = rr >> 11, s_ = rr & 2047;
                    int kk = k0 + seg * 8;
                    g = ((size_t)(b_ * HH + (kk >> 7)) * SS + s_) * DD + (kk & 127);
                }
                uint32_t so = aoff(r, seg * 16);
                cp16(sb + stn + MM3_AHI + so, Ahi + g);
                cp16(sb + stn + MM3_ALO + so, Alo + g);
            }
            for (int f = tid; f < 1024; f += 256) {
                int r = f >> 4, seg = f & 15;
                size_t g = (size_t)(k0 + r) * N + n0 + seg * 8;
                uint32_t so = boff(r, seg * 16);
                cp16(sb + stn + MM3_BHI + so, Bhi + g);
                cp16(sb + stn + MM3_BLO + so, Blo + g);
            }
            CP_COMMIT();
            CP_WAIT(1);
        } else {
            CP_WAIT(0);
        }
        __syncthreads();

        uint32_t Ah[4][4], Al[4][4];
        #pragma unroll
        for (int kk = 0; kk < 4; kk++) {
            uint32_t off = aoff(arow, kk * 32 + akb);
            ldsm_x4(Ah[kk], sb + st + MM3_AHI + off);
            ldsm_x4(Al[kk], sb + st + MM3_ALO + off);
        }
        #pragma unroll
        for (int jp = 0; jp < NJ / 2; jp++) {
            int ncb = (wc + 16 * jp) * 2;
            #pragma unroll
            for (int kk = 0; kk < 4; kk++) {
                uint32_t off = boff(16 * kk + brow, ncb + bcb);
                uint32_t Bh[4], Bl[4];
                ldsm_x4_t(Bh, sb + st + MM3_BHI + off);
                mma16816(C[2*jp],   Ah[kk], Bh);
                mma16816(C[2*jp+1], Ah[kk], Bh + 2);
                mma16816(C[2*jp],   Al[kk], Bh);
                mma16816(C[2*jp+1], Al[kk], Bh + 2);
                ldsm_x4_t(Bl, sb + st + MM3_BLO + off);
                mma16816(C[2*jp],   Ah[kk], Bl);
                mma16816(C[2*jp+1], Ah[kk], Bl + 2);
            }
        }
    }

    const int r0 = m0 + 16 * wr + gid;
    const int r1 = r0 + 8;
    if (MODE == 6) {
        float* po = out + (size_t)blockIdx.x * M * N;
        #pragma unroll
        for (int j = 0; j < NJ; j++) {
            int colg = wc + 8 * j + 2 * tig;
            size_t i0 = (size_t)r0 * N + colg;
            size_t i1 = (size_t)r1 * N + colg;
            *(float2*)(po + i0) = make_float2(C[j][0], C[j][1]);
            *(float2*)(po + i1) = make_float2(C[j][2], C[j][3]);
        }
    } else if (MODE == 4) {
        #pragma unroll
        for (int j = 0; j < NJ; j++) {
            int colg = n0 + wc + 8 * j + 2 * tig;
            size_t i0 = (size_t)r0 * N + colg;
            size_t i1 = (size_t)r1 * N + colg;
            float v00 = C[j][0], v01 = C[j][1], v10 = C[j][2], v11 = C[j][3];
            float b0 = bias[colg], b1 = bias[colg + 1];
            v00 += b0; v01 += b1; v10 += b0; v11 += b1;
            v00 = 0.5f * v00 * (1.0f + erff(v00 * 0.70710678f));
            v01 = 0.5f * v01 * (1.0f + erff(v01 * 0.70710678f));
            v10 = 0.5f * v10 * (1.0f + erff(v10 * 0.70710678f));
            v11 = 0.5f * v11 * (1.0f + erff(v11 * 0.70710678f));
            __nv_bfloat16 h00 = __float2bfloat16(v00), h01 = __float2bfloat16(v01);
            __nv_bfloat16 h10 = __float2bfloat16(v10), h11 = __float2bfloat16(v11);
            __nv_bfloat162 p0 = __halves2bfloat162(h00, h01);
            __nv_bfloat162 p1 = __halves2bfloat162(h10, h11);
            *(uint32_t*)(ohi + i0) = *(uint32_t*)&p0;
            *(uint32_t*)(ohi + i1) = *(uint32_t*)&p1;
            *(uint32_t*)(olo + i0) = pack_bf2(v00 - __bfloat162float(h00), v01 - __bfloat162float(h01));
            *(uint32_t*)(olo + i1) = pack_bf2(v10 - __bfloat162float(h10), v11 - __bfloat162float(h11));
        }
    }
}

// ============== mma.sync flash attention (bf16x3, 2 CTAs/SM) ================
// CTA: 128 threads, 64 query rows. Grid 1024 (globally-descending work).
// Smem/CTA = 96KB: K single-buffer [0,32K), V double-buffer [32K,96K).
// K(t+1)/V(t+1) prefetched right after S(t); cross-CTA overlap hides the rest.
#define FA_KHI 0u
#define FA_KLO 16384u
#define FA_V0  32768u
#define FA_VST 32768u
#define FA_SMEM 98304

__device__ __forceinline__ uint32_t fa_off(int r, int cbyte) {
    return (uint32_t)(r * 256 + (cbyte ^ ((r & 7) << 4)));
}

__global__ __launch_bounds__(128, 2)
void fa_mma(const __nv_bfloat16* __restrict__ qhi, const __nv_bfloat16* __restrict__ qlo,
            const __nv_bfloat16* __restrict__ khi, const __nv_bfloat16* __restrict__ klo,
            const __nv_bfloat16* __restrict__ vhi, const __nv_bfloat16* __restrict__ vlo,
            __nv_bfloat16* __restrict__ Ohi, __nv_bfloat16* __restrict__ Olo)
{
    extern __shared__ char sm[];
    uint32_t sb = smem_u32(sm);
    const int tid = threadIdx.x;
    const int w = tid >> 5, ln = tid & 31;
    const int tig = ln & 3, gid = ln >> 2;
    const int bid = blockIdx.x;
    const int m0 = (31 - (bid >> 5)) * 64;    // globally descending work
    const int bh = bid & 31;
    const size_t base = (size_t)bh * SS * DD;

    // ---- stage Q tile (64x128 hi/lo) through smem (overwritten by K/V) ----
    for (int f = tid; f < 1024; f += 128) {
        int r = f >> 4, c16 = f & 15;
        size_t g = base + (size_t)(m0 + r) * DD + c16 * 8;
        uint32_t so = fa_off(r, c16 * 16);
        *(uint4*)(sm + FA_KHI + so) = *(const uint4*)(qhi + g);
        *(uint4*)(sm + FA_V0  + so) = *(const uint4*)(qlo + g);
    }
    __syncthreads();
    uint32_t Qh[8][4], Ql[8][4];
    {
        int row = 16 * w + ((ln >> 3) & 1) * 8 + (ln & 7);
        int kb0 = (ln >> 4) * 16;
        #pragma unroll
        for (int kk = 0; kk < 8; kk++) {
            uint32_t off = fa_off(row, kk * 32 + kb0);
            ldsm_x4(Qh[kk], sb + FA_KHI + off);
            ldsm_x4(Ql[kk], sb + FA_V0  + off);
        }
    }
    __syncthreads();

    float Oa[16][4];
    #pragma unroll
    for (int j = 0; j < 16; j++)
        #pragma unroll
        for (int e = 0; e < 4; e++) Oa[j][e] = 0.f;
    float m0r = -1e30f, m1r = -1e30f, l0r = 0.f, l1r = 0.f;

    const int grow0 = m0 + 16 * w + gid;
    const int grow1 = grow0 + 8;
    const int nk = m0 / 64 + 1;

    // ---- prologue: K(0), V(0) ----
    for (int f = tid; f < 1024; f += 128) {
        int r = f >> 4, c16 = f & 15;
        size_t g = base + (size_t)r * DD + c16 * 8;
        uint32_t so = fa_off(r, c16 * 16);
        cp16(sb + FA_KHI + so, khi + g);
        cp16(sb + FA_KLO + so, klo + g);
        cp16(sb + FA_V0 + so, vhi + g);
        cp16(sb + FA_V0 + 16384 + so, vlo + g);
    }
    CP_COMMIT();

    for (int t = 0; t < nk; t++) {
        int n0 = t * 64;
        uint32_t vb = FA_V0 + (uint32_t)(t & 1) * FA_VST;
        CP_WAIT(0);        // K(t), V(t) resident
        __syncthreads();

        // ---- S = Q K^T (3-term) ----
        float S[8][4];
        #pragma unroll
        for (int j = 0; j < 8; j++)
            #pragma unroll
            for (int e = 0; e < 4; e++) S[j][e] = 0.f;
        {
            int brow = ((ln >> 4) << 3) + (ln & 7);
            int bkb  = ((ln >> 3) & 1) << 4;
            #pragma unroll
            for (int jp = 0; jp < 4; jp++) {
                #pragma unroll
                for (int kk = 0; kk < 8; kk++) {
                    int r_ = 16 * jp + brow;
                    uint32_t off = fa_off(r_, kk * 32 + bkb);
                    uint32_t Bh[4], Bl[4];
                    ldsm_x4(Bh, sb + FA_KHI + off);
                    mma16816(S[2*jp],   Qh[kk], Bh);
                    mma16816(S[2*jp+1], Qh[kk], Bh + 2);
                    mma16816(S[2*jp],   Ql[kk], Bh);
                    mma16816(S[2*jp+1], Ql[kk], Bh + 2);
                    ldsm_x4(Bl, sb + FA_KLO + off);
                    mma16816(S[2*jp],   Qh[kk], Bl);
                    mma16816(S[2*jp+1], Qh[kk], Bl + 2);
                }
            }
        }
        __syncthreads();   // all warps done reading K(t)

        // ---- prefetch K(t+1) and V(t+1) (overlaps softmax + PV below) ----
        if (t + 1 < nk) {
            int n1 = n0 + 64;
            uint32_t vbn = FA_V0 + (uint32_t)((t + 1) & 1) * FA_VST;
            for (int f = tid; f < 1024; f += 128) {
                int r = f >> 4, c16 = f & 15;
                size_t g = base + (size_t)(n1 + r) * DD + c16 * 8;
                uint32_t so = fa_off(r, c16 * 16);
                cp16(sb + FA_KHI + so, khi + g);
                cp16(sb + FA_KLO + so, klo + g);
                cp16(sb + vbn + so, vhi + g);
                cp16(sb + vbn + 16384 + so, vlo + g);
            }
            CP_COMMIT();
        }

        // ---- causal mask (diagonal tile only) ----
        if (n0 + 63 > m0 + 16 * w) {
            #pragma unroll
            for (int j = 0; j < 8; j++) {
                int c = n0 + 8 * j + 2 * tig;
                if (c     > grow0) S[j][0] = -1e30f;
                if (c + 1 > grow0) S[j][1] = -1e30f;
                if (c     > grow1) S[j][2] = -1e30f;
                if (c + 1 > grow1) S[j][3] = -1e30f;
            }
        }

        // ---- online softmax ----
        float mx0 = -1e30f, mx1 = -1e30f;
        #pragma unroll
        for (int j = 0; j < 8; j++) {
            mx0 = fmaxf(mx0, fmaxf(S[j][0], S[j][1]));
            mx1 = fmaxf(mx1, fmaxf(S[j][2], S[j][3]));
        }
        mx0 = fmaxf(mx0, __shfl_xor_sync(0xffffffffu, mx0, 1));
        mx0 = fmaxf(mx0, __shfl_xor_sync(0xffffffffu, mx0, 2));
        mx1 = fmaxf(mx1, __shfl_xor_sync(0xffffffffu, mx1, 1));
        mx1 = fmaxf(mx1, __shfl_xor_sync(0xffffffffu, mx1, 2));
        float mn0 = fmaxf(m0r, mx0), mn1 = fmaxf(m1r, mx1);
        bool nochg = (mn0 == m0r) && (mn1 == m1r);
        float a0 = nochg ? 1.f : __expf(m0r - mn0);
        float a1 = nochg ? 1.f : __expf(m1r - mn1);
        m0r = mn0; m1r = mn1;
        l0r *= a0; l1r *= a1;

        uint32_t Phi[4][4], Plo[4][4];
        float ls0 = 0.f, ls1 = 0.f;
        #pragma unroll
        for (int j = 0; j < 8; j++) {
            float p0 = __expf(S[j][0] - mn0);
            float p1 = __expf(S[j][1] - mn0);
            float p2 = __expf(S[j][2] - mn1);
            float p3 = __expf(S[j][3] - mn1);
            ls0 += p0 + p1; ls1 += p2 + p3;
            __nv_bfloat16 h0 = __float2bfloat16(p0);
            __nv_bfloat16 h1 = __float2bfloat16(p1);
            __nv_bfloat16 h2 = __float2bfloat16(p2);
            __nv_bfloat16 h3 = __float2bfloat16(p3);
            int kk = j >> 1, q = (j & 1) * 2;
            __nv_bfloat162 hh01 = __halves2bfloat162(h0, h1);
            __nv_bfloat162 hh23 = __halves2bfloat162(h2, h3);
            Phi[kk][q]     = *(uint32_t*)&hh01;
            Phi[kk][q + 1] = *(uint32_t*)&hh23;
            Plo[kk][q]     = pack_bf2(p0 - __bfloat162float(h0), p1 - __bfloat162float(h1));
            Plo[kk][q + 1] = pack_bf2(p2 - __bfloat162float(h2), p3 - __bfloat162float(h3));
        }
        l0r += ls0; l1r += ls1;

        if (!__all_sync(0xffffffffu, nochg)) {
            #pragma unroll
            for (int j = 0; j < 16; j++) {
                Oa[j][0] *= a0; Oa[j][1] *= a0;
                Oa[j][2] *= a1; Oa[j][3] *= a1;
            }
        }

        // ---- O += P V (3-term) ----
        {
            int vrow = ((ln >> 3) & 1) * 8 + (ln & 7);
            int vcb  = (ln >> 4) << 4;
            #pragma unroll
            for (int jp = 0; jp < 8; jp++) {
                #pragma unroll
                for (int kk = 0; kk < 4; kk++) {
                    int r_ = 16 * kk + vrow;
                    uint32_t off = fa_off(r_, 32 * jp + vcb);
                    uint32_t Bh[4], Bl[4];
                    ldsm_x4_t(Bh, sb + vb + off);
                    mma16816(Oa[2*jp],   Phi[kk], Bh);
                    mma16816(Oa[2*jp+1], Phi[kk], Bh + 2);
                    mma16816(Oa[2*jp],   Plo[kk], Bh);
                    mma16816(Oa[2*jp+1], Plo[kk], Bh + 2);
                    ldsm_x4_t(Bl, sb + vb + 16384 + off);
                    mma16816(Oa[2*jp],   Phi[kk], Bl);
                    mma16816(Oa[2*jp+1], Phi[kk], Bl + 2);
                }
            }
        }
    }

    // ---- finalize: reduce l, normalize, split hi/lo, store ----
    l0r += __shfl_xor_sync(0xffffffffu, l0r, 1);
    l0r += __shfl_xor_sync(0xffffffffu, l0r, 2);
    l1r += __shfl_xor_sync(0xffffffffu, l1r, 1);
    l1r += __shfl_xor_sync(0xffffffffu, l1r, 2);
    float inv0 = 1.0f / l0r, inv1 = 1.0f / l1r;
    #pragma unroll
    for (int j = 0; j < 16; j++) {
        int col = 8 * j + 2 * tig;
        size_t i0 = base + (size_t)grow0 * DD + col;
        size_t i1 = base + (size_t)grow1 * DD + col;
        float v00 = Oa[j][0] * inv0, v01 = Oa[j][1] * inv0;
        float v10 = Oa[j][2] * inv1, v11 = Oa[j][3] * inv1;
        __nv_bfloat16 h00 = __float2bfloat16(v00), h01 = __float2bfloat16(v01);
        __nv_bfloat16 h10 = __float2bfloat16(v10), h11 = __float2bfloat16(v11);
        __nv_bfloat162 p0 = __halves2bfloat162(h00, h01);
        __nv_bfloat162 p1 = __halves2bfloat162(h10, h11);
        *(uint32_t*)(Ohi + i0) = *(uint32_t*)&p0;
        *(uint32_t*)(Ohi + i1) = *(uint32_t*)&p1;
        *(uint32_t*)(Olo + i0) = pack_bf2(v00 - __bfloat162float(h00), v01 - __bfloat162float(h01));
        *(uint32_t*)(Olo + i1) = pack_bf2(v10 - __bfloat162float(h10), v11 - __bfloat162float(h11));
    }
}

// ---------------- launch -----------------------------------------------------
extern "C" void kernel_launch(void* const* d_in, const int* in_sizes, int n_in,
                              void* d_out, int out_size) {
    const float* x        = (const float*)d_in[0];
    const float* W_q      = (const float*)d_in[1];
    const float* W_k      = (const float*)d_in[2];
    const float* W_v      = (const float*)d_in[3];
    const float* W_o      = (const float*)d_in[4];
    const float* ln_attn_g= (const float*)d_in[5];
    const float* ln_attn_b= (const float*)d_in[6];
    const float* fc1_w    = (const float*)d_in[7];
    const float* fc1_b    = (const float*)d_in[8];
    const float* fc2_w    = (const float*)d_in[9];
    const float* fc2_b    = (const float*)d_in[10];
    const float* ln_mlp_g = (const float*)d_in[11];
    const float* ln_mlp_b = (const float*)d_in[12];
    float* out = (float*)d_out;

    float *x2, *part;
    __nv_bfloat16 *h1h, *h1l, *h2h, *h2l, *th, *tl, *aoh, *aol;
    __nv_bfloat16 *qhi, *qlo, *khi, *klo, *vhi, *vlo;
    __nv_bfloat16 *wqh, *wql, *wkh, *wkl, *wvh, *wvl, *woh, *wol, *f1h, *f1l, *f2h, *f2l;
    cudaGetSymbolAddress((void**)&x2,  g_x2);
    cudaGetSymbolAddress((void**)&part, g_part);
    cudaGetSymbolAddress((void**)&h1h, g_h1h); cudaGetSymbolAddress((void**)&h1l, g_h1l);
    cudaGetSymbolAddress((void**)&h2h, g_h2h); cudaGetSymbolAddress((void**)&h2l, g_h2l);
    cudaGetSymbolAddress((void**)&th,  g_th);  cudaGetSymbolAddress((void**)&tl,  g_tl);
    cudaGetSymbolAddress((void**)&aoh, g_aoh); cudaGetSymbolAddress((void**)&aol, g_aol);
    cudaGetSymbolAddress((void**)&qhi, g_qhi); cudaGetSymbolAddress((void**)&qlo, g_qlo);
    cudaGetSymbolAddress((void**)&khi, g_khi); cudaGetSymbolAddress((void**)&klo, g_klo);
    cudaGetSymbolAddress((void**)&vhi, g_vhi); cudaGetSymbolAddress((void**)&vlo, g_vlo);
    cudaGetSymbolAddress((void**)&wqh, g_wqh); cudaGetSymbolAddress((void**)&wql, g_wql);
    cudaGetSymbolAddress((void**)&wkh, g_wkh); cudaGetSymbolAddress((void**)&wkl, g_wkl);
    cudaGetSymbolAddress((void**)&wvh, g_wvh); cudaGetSymbolAddress((void**)&wvl, g_wvl);
    cudaGetSymbolAddress((void**)&woh, g_woh); cudaGetSymbolAddress((void**)&wol, g_wol);
    cudaGetSymbolAddress((void**)&f1h, g_f1h); cudaGetSymbolAddress((void**)&f1l, g_f1l);
    cudaGetSymbolAddress((void**)&f2h, g_f2h); cudaGetSymbolAddress((void**)&f2l, g_f2l);

    // 0) split all six weights to bf16 hi/lo in one launch
    split6<<<1152, 256>>>(W_q, W_k, W_v, W_o, fc1_w, fc2_w,
                          wqh, wql, wkh, wkl, wvh, wvl,
                          woh, wol, f1h, f1l, f2h, f2l);

    // 1) LN -> bf16 hi/lo
    ln_kernel<<<MM/8, 256>>>(x, ln_attn_g, ln_attn_b, h1h, h1l);

    // 2) fused QKV projection (pipelined tensor core, fused RoPE/scale/split)
    const float qscale = 0.08838834764831845f;  // 1/sqrt(128)
    cudaFuncSetAttribute(qkv_mm, cudaFuncAttributeMaxDynamicSharedMemorySize, MM3_SMEM);
    qkv_mm<<<dim3(48, MM/128), 256, MM3_SMEM>>>(qscale);

    // 3) causal flash attention (2 CTAs/SM, globally-descending work order)
    cudaFuncSetAttribute(fa_mma, cudaFuncAttributeMaxDynamicSharedMemorySize, FA_SMEM);
    fa_mma<<<1024, 128, FA_SMEM>>>(qhi, qlo, khi, klo, vhi, vlo, aoh, aol);

    // 4) O-projection via split-K (4 x 512, pipelined), then reduce + residual
    cudaFuncSetAttribute(mm3<6,true,true>,  cudaFuncAttributeMaxDynamicSharedMemorySize, MM3_SMEM);
    cudaFuncSetAttribute(mm3<6,false,true>, cudaFuncAttributeMaxDynamicSharedMemorySize, MM3_SMEM);
    cudaFuncSetAttribute(mm3<4,false,true>, cudaFuncAttributeMaxDynamicSharedMemorySize, MM3_SMEM);
    mm3<6,true,true><<<dim3(4, MM/64), 256, MM3_SMEM>>>(aoh, aol, woh, wol, nullptr, nullptr, part, nullptr, nullptr, MM, EE, HD, 512, 1.0f);
    reduce_k<4,false><<<(MM*EE)/1024, 256>>>(part, x, nullptr, x2);

    // 5) LN -> bf16 hi/lo
    ln_kernel<<<MM/8, 256>>>(x2, ln_mlp_g, ln_mlp_b, h2h, h2l);

    // 6) MLP: fc1 (pipelined, HALFM, fused bias+GELU+split), fc2 split-K 4x128
    mm3<4,false,true><<<dim3(DHH/128, MM/64), 256, MM3_SMEM>>>(h2h, h2l, f1h, f1l, fc1_b, nullptr, nullptr, th, tl, MM, DHH, EE, EE, 1.0f);
    mm3<6,false,true><<<dim3(4, MM/64), 256, MM3_SMEM>>>(th, tl, f2h, f2l, nullptr, nullptr, part, nullptr, nullptr, MM, EE, DHH, 128, 1.0f);
    reduce_k<4,true><<<(MM*EE)/1024, 256>>>(part, x2, fc2_b, out);
}